// round 3
// baseline (speedup 1.0000x reference)
#include <cuda_runtime.h>
#include <cuda_bf16.h>
#include <math.h>
#include <stdint.h>

// ---------------------------------------------------------------------------
// OptimizedMambaBlock: B=8, DIM=256, H=W=32 -> L=1024, tokens N=8192
// GEMMs on tensor pipe: mma.sync.m16n8k8.tf32 with 3xTF32 hi/lo split.
// ---------------------------------------------------------------------------

#define NTOK   8192
#define LSEQ   1024
#define BSZ    8
#define DIMC   256
#define DINNER 512
#define DSTATE 16
#define DTRANK 16

__device__ float g_xf [NTOK * DIMC];
__device__ float g_xn [NTOK * DIMC];
__device__ float g_xz [NTOK * 1024];
__device__ float g_xc [NTOK * DINNER];
__device__ float g_dbl[NTOK * 48];
__device__ float g_dt [NTOK * DINNER];
__device__ float g_y  [NTOK * DINNER];
__device__ float g_xf2[NTOK * DIMC];
__device__ float g_hln[NTOK * DIMC];
__device__ float g_h1 [NTOK * 1024];

// ---------------------------------------------------------------------------
// LN1 + transpose
// ---------------------------------------------------------------------------
__global__ void ln1_kernel(const float* __restrict__ x,
                           const float* __restrict__ g,
                           const float* __restrict__ bta) {
    __shared__ float red[16];
    int token = blockIdx.x;
    int c = threadIdx.x;
    int b = token >> 10, t = token & 1023;
    float v = x[((size_t)b * DIMC + c) * LSEQ + t];
    float s = v, q = v * v;
    #pragma unroll
    for (int o = 16; o; o >>= 1) {
        s += __shfl_xor_sync(~0u, s, o);
        q += __shfl_xor_sync(~0u, q, o);
    }
    int w = c >> 5, l = c & 31;
    if (l == 0) { red[w] = s; red[8 + w] = q; }
    __syncthreads();
    s = 0.f; q = 0.f;
    #pragma unroll
    for (int i = 0; i < 8; i++) { s += red[i]; q += red[8 + i]; }
    float mean = s * (1.f / 256.f);
    float var  = q * (1.f / 256.f) - mean * mean;
    float rs = rsqrtf(var + 1e-5f);
    size_t o = (size_t)token * DIMC + c;
    g_xf[o] = v;
    g_xn[o] = (v - mean) * rs * g[c] + bta[c];
}

// ---------------------------------------------------------------------------
// LN2
// ---------------------------------------------------------------------------
__global__ void ln2_kernel(const float* __restrict__ g,
                           const float* __restrict__ bta) {
    int token = (blockIdx.x * blockDim.x + threadIdx.x) >> 5;
    int lane = threadIdx.x & 31;
    const float* row = g_xf2 + (size_t)token * DIMC;
    float4 a = *(const float4*)(row + lane * 4);
    float4 c4 = *(const float4*)(row + 128 + lane * 4);
    float s = a.x + a.y + a.z + a.w + c4.x + c4.y + c4.z + c4.w;
    float q = a.x*a.x + a.y*a.y + a.z*a.z + a.w*a.w
            + c4.x*c4.x + c4.y*c4.y + c4.z*c4.z + c4.w*c4.w;
    #pragma unroll
    for (int o = 16; o; o >>= 1) {
        s += __shfl_xor_sync(~0u, s, o);
        q += __shfl_xor_sync(~0u, q, o);
    }
    float mean = s * (1.f / 256.f);
    float var  = q * (1.f / 256.f) - mean * mean;
    float rs = rsqrtf(var + 1e-5f);
    float* out = g_hln + (size_t)token * DIMC;
    float va[8] = { a.x, a.y, a.z, a.w, c4.x, c4.y, c4.z, c4.w };
    #pragma unroll
    for (int h = 0; h < 2; h++) {
        #pragma unroll
        for (int i = 0; i < 4; i++) {
            int c = h * 128 + lane * 4 + i;
            out[c] = (va[h * 4 + i] - mean) * rs * g[c] + bta[c];
        }
    }
}

// ---------------------------------------------------------------------------
// conv + silu
// ---------------------------------------------------------------------------
__global__ void conv_silu_kernel(const float* __restrict__ cw,
                                 const float* __restrict__ cb) {
    int idx = blockIdx.x * blockDim.x + threadIdx.x;
    int token = idx >> 9;
    int d = idx & 511;
    int t = token & 1023;
    int tokbase = token - t;
    float acc = cb[d];
    #pragma unroll
    for (int j = 0; j < 4; j++) {
        int tt = t - 3 + j;
        if (tt >= 0)
            acc += g_xz[(size_t)(tokbase + tt) * 1024 + d] * cw[d * 4 + j];
    }
    float sv = acc / (1.f + __expf(-acc));
    g_xc[(size_t)token * DINNER + d] = sv;
}

// ---------------------------------------------------------------------------
// dt projection + softplus
// ---------------------------------------------------------------------------
__global__ void dt_kernel(const float* __restrict__ dtw,
                          const float* __restrict__ dtb) {
    __shared__ float swT[16][512];
    int tid = threadIdx.x;
    for (int idx = tid; idx < 512 * 16; idx += 256) {
        int d = idx >> 4, r = idx & 15;
        swT[r][d] = dtw[idx];
    }
    __syncthreads();
    int t0 = blockIdx.x * 8;
    for (int o = tid; o < 8 * 512; o += 256) {
        int tl = o >> 9, d = o & 511;
        int token = t0 + tl;
        const float* row = g_dbl + (size_t)token * 48;
        float acc = dtb[d];
        #pragma unroll
        for (int r = 0; r < 16; r++)
            acc += row[r] * swT[r][d];
        float sp = (acc > 20.f) ? acc : log1pf(__expf(acc));
        g_dt[(size_t)token * DINNER + d] = sp;
    }
}

// ---------------------------------------------------------------------------
// selective scan + gating
// ---------------------------------------------------------------------------
__global__ void scan_kernel(const float* __restrict__ A_log,
                            const float* __restrict__ Dp) {
    int tid = threadIdx.x;
    int b  = blockIdx.x >> 4;
    int d  = ((blockIdx.x & 15) << 5) + (tid >> 2);
    int sq = tid & 3;

    float Al[4], h[4];
    #pragma unroll
    for (int j = 0; j < 4; j++) {
        Al[j] = -__expf(A_log[d * 16 + sq * 4 + j]) * 1.44269504f;
        h[j] = 0.f;
    }
    float dpv = Dp[d];

    const float* dtp  = g_dt  + (size_t)b * LSEQ * DINNER + d;
    const float* up   = g_xc  + (size_t)b * LSEQ * DINNER + d;
    const float* dblp = g_dbl + (size_t)b * LSEQ * 48;
    const float* zp   = g_xz  + (size_t)b * LSEQ * 1024 + 512 + d;
    float*       yp   = g_y   + (size_t)b * LSEQ * DINNER + d;

    for (int t = 0; t < LSEQ; t++) {
        float dt = dtp[(size_t)t * DINNER];
        float u  = up [(size_t)t * DINNER];
        float4 Bv = *(const float4*)(dblp + (size_t)t * 48 + 16 + sq * 4);
        float4 Cv = *(const float4*)(dblp + (size_t)t * 48 + 32 + sq * 4);
        float dtu = dt * u;
        float y = 0.f;
        h[0] = exp2f(dt * Al[0]) * h[0] + dtu * Bv.x; y += h[0] * Cv.x;
        h[1] = exp2f(dt * Al[1]) * h[1] + dtu * Bv.y; y += h[1] * Cv.y;
        h[2] = exp2f(dt * Al[2]) * h[2] + dtu * Bv.z; y += h[2] * Cv.z;
        h[3] = exp2f(dt * Al[3]) * h[3] + dtu * Bv.w; y += h[3] * Cv.w;
        y += __shfl_xor_sync(~0u, y, 1);
        y += __shfl_xor_sync(~0u, y, 2);
        if (sq == 0) {
            float z = zp[(size_t)t * 1024];
            float gate = z / (1.f + __expf(-z));
            yp[(size_t)t * DINNER] = (y + u * dpv) * gate;
        }
    }
}

// ---------------------------------------------------------------------------
// Tensor-core GEMM (NT): C[M,N] = A[M,K] @ B[N,K]^T with 3xTF32.
// BM=128 BN=64 BK=16, 256 threads = 8 warps (4m x 2n), 32x32 warp tile.
// SMEM layout per row, per k8 sub-chunk: 16 floats
//   [hi(c) lo(c) hi(c+4) lo(c+4)] for c = 0..3 at offset c*4.
// Row stride 48 floats -> conflict-free LDS.128 fragment fetches.
// ---------------------------------------------------------------------------
__device__ __forceinline__ void mma_tf32(float* c, const uint32_t* a, const uint32_t* b) {
    asm volatile(
        "mma.sync.aligned.m16n8k8.row.col.f32.tf32.tf32.f32 "
        "{%0,%1,%2,%3}, {%4,%5,%6,%7}, {%8,%9}, {%0,%1,%2,%3};\n"
        : "+f"(c[0]), "+f"(c[1]), "+f"(c[2]), "+f"(c[3])
        : "r"(a[0]), "r"(a[1]), "r"(a[2]), "r"(a[3]), "r"(b[0]), "r"(b[1]));
}

__device__ __forceinline__ void stage_row(float* row, int aq, float4 v) {
    float f4[4] = { v.x, v.y, v.z, v.w };
    #pragma unroll
    for (int j = 0; j < 4; j++) {
        int kk = aq * 4 + j;
        float f = f4[j];
        uint32_t hb;
        asm("cvt.rna.tf32.f32 %0, %1;" : "=r"(hb) : "f"(f));
        float hf = __uint_as_float(hb);
        float lf = f - hf;
        uint32_t lb;
        asm("cvt.rna.tf32.f32 %0, %1;" : "=r"(lb) : "f"(lf));
        int sub = kk >> 3, c8 = kk & 7;
        int base = sub * 16 + (c8 & 3) * 4 + ((c8 >> 2) << 1);
        // adjacent hi/lo -> 64-bit store
        float2* p = (float2*)(row + base);
        *p = make_float2(hf, __uint_as_float(lb));
    }
}

template <int EPI>
__global__ void __launch_bounds__(256)
gemm_tc(const float* __restrict__ A, const float* __restrict__ B,
        float* __restrict__ C, int M, int N, int K,
        const float* __restrict__ bias, const float* __restrict__ res) {
    const int BM = 128, BN = 64, BK = 16;
    __shared__ __align__(16) float As[BM][48];
    __shared__ __align__(16) float Bs[BN][48];

    int tid = threadIdx.x;
    int wid = tid >> 5, lane = tid & 31;
    int wm = wid & 3, wn = wid >> 2;          // 4 x 2 warp grid
    int m0 = blockIdx.y * BM, n0 = blockIdx.x * BN;

    int arow = tid >> 2;                       // 0..63
    int aq = tid & 3;                          // quad (k float4)

    float acc[2][4][4];
    #pragma unroll
    for (int i = 0; i < 2; i++)
        #pragma unroll
        for (int j = 0; j < 4; j++)
            #pragma unroll
            for (int k = 0; k < 4; k++) acc[i][j][k] = 0.f;

    for (int kt = 0; kt < K; kt += BK) {
        // stage A: 128 rows (two passes of 64)
        #pragma unroll
        for (int p = 0; p < 2; p++) {
            int r = arow + p * 64;
            float4 v = *(const float4*)(A + (size_t)(m0 + r) * K + kt + aq * 4);
            stage_row(&As[r][0], aq, v);
        }
        // stage B: 64 rows (guard N)
        {
            float4 v = make_float4(0.f, 0.f, 0.f, 0.f);
            if (n0 + arow < N)
                v = *(const float4*)(B + (size_t)(n0 + arow) * K + kt + aq * 4);
            stage_row(&Bs[arow][0], aq, v);
        }
        __syncthreads();

        #pragma unroll
        for (int sub = 0; sub < 2; sub++) {
            uint32_t ah[2][4], al[2][4], bh[4][2], bl[4][2];
            #pragma unroll
            for (int mt = 0; mt < 2; mt++) {
                int r = wm * 32 + mt * 16 + (lane >> 2);
                float4 f0 = *(const float4*)&As[r][sub * 16 + (lane & 3) * 4];
                float4 f1 = *(const float4*)&As[r + 8][sub * 16 + (lane & 3) * 4];
                ah[mt][0] = __float_as_uint(f0.x); al[mt][0] = __float_as_uint(f0.y);
                ah[mt][2] = __float_as_uint(f0.z); al[mt][2] = __float_as_uint(f0.w);
                ah[mt][1] = __float_as_uint(f1.x); al[mt][1] = __float_as_uint(f1.y);
                ah[mt][3] = __float_as_uint(f1.z); al[mt][3] = __float_as_uint(f1.w);
            }
            #pragma unroll
            for (int nt = 0; nt < 4; nt++) {
                int cc = wn * 32 + nt * 8 + (lane >> 2);
                float4 g0 = *(const float4*)&Bs[cc][sub * 16 + (lane & 3) * 4];
                bh[nt][0] = __float_as_uint(g0.x); bl[nt][0] = __float_as_uint(g0.y);
                bh[nt][1] = __float_as_uint(g0.z); bl[nt][1] = __float_as_uint(g0.w);
            }
            #pragma unroll
            for (int mt = 0; mt < 2; mt++)
                #pragma unroll
                for (int nt = 0; nt < 4; nt++) {
                    mma_tf32(acc[mt][nt], ah[mt], bh[nt]);
                    mma_tf32(acc[mt][nt], ah[mt], bl[nt]);
                    mma_tf32(acc[mt][nt], al[mt], bh[nt]);
                }
        }
        __syncthreads();
    }

    // epilogue
    #pragma unroll
    for (int mt = 0; mt < 2; mt++) {
        #pragma unroll
        for (int nt = 0; nt < 4; nt++) {
            int rbase = m0 + wm * 32 + mt * 16 + (lane >> 2);
            int cbase = n0 + wn * 32 + nt * 8 + (lane & 3) * 2;
            #pragma unroll
            for (int e = 0; e < 4; e++) {
                int m = rbase + (e >> 1) * 8;
                int n = cbase + (e & 1);
                if (n >= N) continue;
                float v = acc[mt][nt][e];
                if (EPI == 0) {
                    C[(size_t)m * N + n] = v;
                } else if (EPI == 1) {
                    C[(size_t)m * N + n] = res[(size_t)m * N + n] + v;
                } else if (EPI == 2) {
                    float u = v + bias[n];
                    C[(size_t)m * N + n] = 0.5f * u * (1.f + erff(u * 0.70710678118f));
                } else { // EPI 3: residual + bias + transposed store
                    float u = res[(size_t)m * N + n] + v + bias[n];
                    int b = m >> 10, t = m & 1023;
                    C[((size_t)b * DIMC + n) * LSEQ + t] = u;
                }
            }
        }
    }
}

// ---------------------------------------------------------------------------
extern "C" void kernel_launch(void* const* d_in, const int* in_sizes, int n_in,
                              void* d_out, int out_size) {
    const float* x        = (const float*)d_in[0];
    const float* ln_g     = (const float*)d_in[1];
    const float* ln_b     = (const float*)d_in[2];
    const float* in_proj  = (const float*)d_in[3];
    const float* conv_w   = (const float*)d_in[4];
    const float* conv_b   = (const float*)d_in[5];
    const float* x_proj   = (const float*)d_in[6];
    const float* dt_w     = (const float*)d_in[7];
    const float* dt_b     = (const float*)d_in[8];
    const float* A_log    = (const float*)d_in[9];
    const float* Dp       = (const float*)d_in[10];
    const float* out_proj = (const float*)d_in[11];
    const float* mlp_ln_g = (const float*)d_in[12];
    const float* mlp_ln_b = (const float*)d_in[13];
    const float* mlp_w1   = (const float*)d_in[14];
    const float* mlp_b1   = (const float*)d_in[15];
    const float* mlp_w2   = (const float*)d_in[16];
    const float* mlp_b2   = (const float*)d_in[17];
    float* out = (float*)d_out;

    float *p_xn, *p_xz, *p_xc, *p_dbl, *p_y, *p_xf, *p_xf2, *p_hln, *p_h1;
    cudaGetSymbolAddress((void**)&p_xn,  g_xn);
    cudaGetSymbolAddress((void**)&p_xz,  g_xz);
    cudaGetSymbolAddress((void**)&p_xc,  g_xc);
    cudaGetSymbolAddress((void**)&p_dbl, g_dbl);
    cudaGetSymbolAddress((void**)&p_y,   g_y);
    cudaGetSymbolAddress((void**)&p_xf,  g_xf);
    cudaGetSymbolAddress((void**)&p_xf2, g_xf2);
    cudaGetSymbolAddress((void**)&p_hln, g_hln);
    cudaGetSymbolAddress((void**)&p_h1,  g_h1);

    // 1. ln1 + transpose
    ln1_kernel<<<NTOK, 256>>>(x, ln_g, ln_b);
    // 2. in_proj (8192 x 1024, K=256)
    gemm_tc<0><<<dim3(1024 / 64, NTOK / 128), 256>>>(p_xn, in_proj, p_xz,
                                                     NTOK, 1024, 256, nullptr, nullptr);
    // 3. conv + silu
    conv_silu_kernel<<<(NTOK * DINNER) / 256, 256>>>(conv_w, conv_b);
    // 4. x_proj (8192 x 48, K=512)
    gemm_tc<0><<<dim3(1, NTOK / 128), 256>>>(p_xc, x_proj, p_dbl,
                                             NTOK, 48, 512, nullptr, nullptr);
    // 5. dt projection
    dt_kernel<<<NTOK / 8, 256>>>(dt_w, dt_b);
    // 6. selective scan
    scan_kernel<<<128, 128>>>(A_log, Dp);
    // 7. out_proj + residual (8192 x 256, K=512)
    gemm_tc<1><<<dim3(256 / 64, NTOK / 128), 256>>>(p_y, out_proj, p_xf2,
                                                    NTOK, 256, 512, nullptr, p_xf);
    // 8. ln2
    ln2_kernel<<<NTOK / 8, 256>>>(mlp_ln_g, mlp_ln_b);
    // 9. mlp1 + gelu (8192 x 1024, K=256)
    gemm_tc<2><<<dim3(1024 / 64, NTOK / 128), 256>>>(p_hln, mlp_w1, p_h1,
                                                     NTOK, 1024, 256, mlp_b1, nullptr);
    // 10. mlp2 + residual + transposed store (8192 x 256, K=1024)
    gemm_tc<3><<<dim3(256 / 64, NTOK / 128), 256>>>(p_h1, mlp_w2, out,
                                                    NTOK, 256, 1024, mlp_b2, p_xf2);
}

// round 5
// speedup vs baseline: 1.1686x; 1.1686x over previous
#include <cuda_runtime.h>
#include <cuda_bf16.h>
#include <math.h>
#include <stdint.h>

// ---------------------------------------------------------------------------
// OptimizedMambaBlock: B=8, DIM=256, H=W=32 -> L=1024, tokens N=8192
// GEMMs: mma.sync.m16n8k16.bf16, hi/lo 2-term split (3 MMA passes),
// ldmatrix fragments from SW128-swizzled smem.
// R5 fixes: lo-plane staging offset is XOR (in-row), smem 1024-aligned.
// ---------------------------------------------------------------------------

#define NTOK   8192
#define LSEQ   1024
#define BSZ    8
#define DIMC   256
#define DINNER 512
#define DSTATE 16
#define DTRANK 16

__device__ float g_xf [NTOK * DIMC];
__device__ float g_xn [NTOK * DIMC];
__device__ float g_xz [NTOK * 1024];
__device__ float g_xc [NTOK * DINNER];
__device__ float g_dbl[NTOK * 48];
__device__ float g_dt [NTOK * DINNER];
__device__ float g_y  [NTOK * DINNER];
__device__ float g_xf2[NTOK * DIMC];
__device__ float g_hln[NTOK * DIMC];
__device__ float g_h1 [NTOK * 1024];

// ---------------------------------------------------------------------------
// LN1 + transpose
// ---------------------------------------------------------------------------
__global__ void ln1_kernel(const float* __restrict__ x,
                           const float* __restrict__ g,
                           const float* __restrict__ bta) {
    __shared__ float red[16];
    int token = blockIdx.x;
    int c = threadIdx.x;
    int b = token >> 10, t = token & 1023;
    float v = x[((size_t)b * DIMC + c) * LSEQ + t];
    float s = v, q = v * v;
    #pragma unroll
    for (int o = 16; o; o >>= 1) {
        s += __shfl_xor_sync(~0u, s, o);
        q += __shfl_xor_sync(~0u, q, o);
    }
    int w = c >> 5, l = c & 31;
    if (l == 0) { red[w] = s; red[8 + w] = q; }
    __syncthreads();
    s = 0.f; q = 0.f;
    #pragma unroll
    for (int i = 0; i < 8; i++) { s += red[i]; q += red[8 + i]; }
    float mean = s * (1.f / 256.f);
    float var  = q * (1.f / 256.f) - mean * mean;
    float rs = rsqrtf(var + 1e-5f);
    size_t o = (size_t)token * DIMC + c;
    g_xf[o] = v;
    g_xn[o] = (v - mean) * rs * g[c] + bta[c];
}

// ---------------------------------------------------------------------------
// LN2
// ---------------------------------------------------------------------------
__global__ void ln2_kernel(const float* __restrict__ g,
                           const float* __restrict__ bta) {
    int token = (blockIdx.x * blockDim.x + threadIdx.x) >> 5;
    int lane = threadIdx.x & 31;
    const float* row = g_xf2 + (size_t)token * DIMC;
    float4 a = *(const float4*)(row + lane * 4);
    float4 c4 = *(const float4*)(row + 128 + lane * 4);
    float s = a.x + a.y + a.z + a.w + c4.x + c4.y + c4.z + c4.w;
    float q = a.x*a.x + a.y*a.y + a.z*a.z + a.w*a.w
            + c4.x*c4.x + c4.y*c4.y + c4.z*c4.z + c4.w*c4.w;
    #pragma unroll
    for (int o = 16; o; o >>= 1) {
        s += __shfl_xor_sync(~0u, s, o);
        q += __shfl_xor_sync(~0u, q, o);
    }
    float mean = s * (1.f / 256.f);
    float var  = q * (1.f / 256.f) - mean * mean;
    float rs = rsqrtf(var + 1e-5f);
    float* out = g_hln + (size_t)token * DIMC;
    float va[8] = { a.x, a.y, a.z, a.w, c4.x, c4.y, c4.z, c4.w };
    #pragma unroll
    for (int h = 0; h < 2; h++) {
        #pragma unroll
        for (int i = 0; i < 4; i++) {
            int c = h * 128 + lane * 4 + i;
            out[c] = (va[h * 4 + i] - mean) * rs * g[c] + bta[c];
        }
    }
}

// ---------------------------------------------------------------------------
// conv + silu
// ---------------------------------------------------------------------------
__global__ void conv_silu_kernel(const float* __restrict__ cw,
                                 const float* __restrict__ cb) {
    int idx = blockIdx.x * blockDim.x + threadIdx.x;
    int token = idx >> 9;
    int d = idx & 511;
    int t = token & 1023;
    int tokbase = token - t;
    float acc = cb[d];
    #pragma unroll
    for (int j = 0; j < 4; j++) {
        int tt = t - 3 + j;
        if (tt >= 0)
            acc += g_xz[(size_t)(tokbase + tt) * 1024 + d] * cw[d * 4 + j];
    }
    float sv = acc / (1.f + __expf(-acc));
    g_xc[(size_t)token * DINNER + d] = sv;
}

// ---------------------------------------------------------------------------
// dt projection + softplus
// ---------------------------------------------------------------------------
__global__ void dt_kernel(const float* __restrict__ dtw,
                          const float* __restrict__ dtb) {
    __shared__ float swT[16][512];
    int tid = threadIdx.x;
    for (int idx = tid; idx < 512 * 16; idx += 256) {
        int d = idx >> 4, r = idx & 15;
        swT[r][d] = dtw[idx];
    }
    __syncthreads();
    int t0 = blockIdx.x * 8;
    for (int o = tid; o < 8 * 512; o += 256) {
        int tl = o >> 9, d = o & 511;
        int token = t0 + tl;
        const float* row = g_dbl + (size_t)token * 48;
        float acc = dtb[d];
        #pragma unroll
        for (int r = 0; r < 16; r++)
            acc += row[r] * swT[r][d];
        float sp = (acc > 20.f) ? acc : log1pf(__expf(acc));
        g_dt[(size_t)token * DINNER + d] = sp;
    }
}

// ---------------------------------------------------------------------------
// selective scan + gating
// ---------------------------------------------------------------------------
__global__ void scan_kernel(const float* __restrict__ A_log,
                            const float* __restrict__ Dp) {
    int tid = threadIdx.x;
    int b  = blockIdx.x >> 4;
    int d  = ((blockIdx.x & 15) << 5) + (tid >> 2);
    int sq = tid & 3;

    float Al[4], h[4];
    #pragma unroll
    for (int j = 0; j < 4; j++) {
        Al[j] = -__expf(A_log[d * 16 + sq * 4 + j]) * 1.44269504f;
        h[j] = 0.f;
    }
    float dpv = Dp[d];

    const float* dtp  = g_dt  + (size_t)b * LSEQ * DINNER + d;
    const float* up   = g_xc  + (size_t)b * LSEQ * DINNER + d;
    const float* dblp = g_dbl + (size_t)b * LSEQ * 48;
    const float* zp   = g_xz  + (size_t)b * LSEQ * 1024 + 512 + d;
    float*       yp   = g_y   + (size_t)b * LSEQ * DINNER + d;

    for (int t = 0; t < LSEQ; t++) {
        float dt = dtp[(size_t)t * DINNER];
        float u  = up [(size_t)t * DINNER];
        float4 Bv = *(const float4*)(dblp + (size_t)t * 48 + 16 + sq * 4);
        float4 Cv = *(const float4*)(dblp + (size_t)t * 48 + 32 + sq * 4);
        float dtu = dt * u;
        float y = 0.f;
        h[0] = exp2f(dt * Al[0]) * h[0] + dtu * Bv.x; y += h[0] * Cv.x;
        h[1] = exp2f(dt * Al[1]) * h[1] + dtu * Bv.y; y += h[1] * Cv.y;
        h[2] = exp2f(dt * Al[2]) * h[2] + dtu * Bv.z; y += h[2] * Cv.z;
        h[3] = exp2f(dt * Al[3]) * h[3] + dtu * Bv.w; y += h[3] * Cv.w;
        y += __shfl_xor_sync(~0u, y, 1);
        y += __shfl_xor_sync(~0u, y, 2);
        if (sq == 0) {
            float z = zp[(size_t)t * 1024];
            float gate = z / (1.f + __expf(-z));
            yp[(size_t)t * DINNER] = (y + u * dpv) * gate;
        }
    }
}

// ---------------------------------------------------------------------------
// bf16 split helpers
// ---------------------------------------------------------------------------
__device__ __forceinline__ uint32_t pack_bf16x2(float e, float o) {
    uint32_t d;
    asm("cvt.rn.bf16x2.f32 %0, %1, %2;" : "=r"(d) : "f"(o), "f"(e));
    return d;
}

__device__ __forceinline__ void cvt8(float4 x, float4 y, uint4& hi, uint4& lo) {
    hi.x = pack_bf16x2(x.x, x.y);
    hi.y = pack_bf16x2(x.z, x.w);
    hi.z = pack_bf16x2(y.x, y.y);
    hi.w = pack_bf16x2(y.z, y.w);
    float hxe = __uint_as_float(hi.x << 16), hxo = __uint_as_float(hi.x & 0xFFFF0000u);
    float hye = __uint_as_float(hi.y << 16), hyo = __uint_as_float(hi.y & 0xFFFF0000u);
    float hze = __uint_as_float(hi.z << 16), hzo = __uint_as_float(hi.z & 0xFFFF0000u);
    float hwe = __uint_as_float(hi.w << 16), hwo = __uint_as_float(hi.w & 0xFFFF0000u);
    lo.x = pack_bf16x2(x.x - hxe, x.y - hxo);
    lo.y = pack_bf16x2(x.z - hye, x.w - hyo);
    lo.z = pack_bf16x2(y.x - hze, y.y - hzo);
    lo.w = pack_bf16x2(y.z - hwe, y.w - hwo);
}

__device__ __forceinline__ void ldsm4(uint32_t r[4], uint32_t addr) {
    asm volatile("ldmatrix.sync.aligned.m8n8.x4.shared.b16 {%0,%1,%2,%3}, [%4];"
                 : "=r"(r[0]), "=r"(r[1]), "=r"(r[2]), "=r"(r[3]) : "r"(addr));
}

__device__ __forceinline__ void mma_bf16(float* c, const uint32_t* a, const uint32_t* b) {
    asm volatile(
        "mma.sync.aligned.m16n8k16.row.col.f32.bf16.bf16.f32 "
        "{%0,%1,%2,%3}, {%4,%5,%6,%7}, {%8,%9}, {%0,%1,%2,%3};\n"
        : "+f"(c[0]), "+f"(c[1]), "+f"(c[2]), "+f"(c[3])
        : "r"(a[0]), "r"(a[1]), "r"(a[2]), "r"(a[3]), "r"(b[0]), "r"(b[1]));
}

// ---------------------------------------------------------------------------
// Tensor-core GEMM (NT): C[M,N] = A[M,K] @ B[N,K]^T, bf16 hi/lo 3-pass.
// BM=128 BN=64 BK=32, 256 threads = 8 warps (4m x 2n), 32x32 warp tiles.
// SMEM row (128B): 8 16B chunks, chunk id = plane*4 + sub*2 + k8half,
// stored at chunk ^ (row & 7).
// ---------------------------------------------------------------------------
template <int EPI>
__global__ void __launch_bounds__(256)
gemm_bf16(const float* __restrict__ A, const float* __restrict__ B,
          float* __restrict__ C, int M, int N, int K,
          const float* __restrict__ bias, const float* __restrict__ res) {
    const int BM = 128, BN = 64, BK = 32;
    __shared__ __align__(1024) unsigned char As[BM * 128];
    __shared__ __align__(1024) unsigned char Bs[BN * 128];

    int tid = threadIdx.x;
    int lane = tid & 31, wid = tid >> 5;
    int wm = wid & 3, wn = wid >> 2;
    int m0 = blockIdx.y * BM, n0 = blockIdx.x * BN;

    uint32_t As_u, Bs_u;
    asm("{ .reg .u64 t; cvta.to.shared.u64 t, %1; cvt.u32.u64 %0, t; }" : "=r"(As_u) : "l"(As));
    asm("{ .reg .u64 t; cvta.to.shared.u64 t, %1; cvt.u32.u64 %0, t; }" : "=r"(Bs_u) : "l"(Bs));

    // ldmatrix base addresses (hi plane, sub 0); sub1 = ^0x20, lo plane = ^0x40
    int lh = lane >> 4;
    uint32_t aAddr[2], bAddr[2];
    #pragma unroll
    for (int mt = 0; mt < 2; mt++) {
        int r = wm * 32 + mt * 16 + (lane & 15);
        aAddr[mt] = As_u + r * 128 + ((lh ^ (r & 7)) << 4);
    }
    #pragma unroll
    for (int np = 0; np < 2; np++) {
        int r = wn * 32 + np * 16 + (lane & 15);
        bAddr[np] = Bs_u + r * 128 + ((lh ^ (r & 7)) << 4);
    }

    // staging assignment
    int ar = tid >> 1, ahf = tid & 1;          // A: row, k-half (16 floats)
    const float* Ag = A + (size_t)(m0 + ar) * K + ahf * 16;
    unsigned char* aRow = As + ar * 128;
    int aOff0 = ((ahf * 2 + 0) ^ (ar & 7)) << 4;
    int aOff1 = ((ahf * 2 + 1) ^ (ar & 7)) << 4;
    int br = tid & 63, bq = tid >> 6;          // B: row, k-quarter (8 floats)
    const float* Bg = B + (size_t)(n0 + br) * K + bq * 8;
    bool bok = (n0 + br) < N;
    unsigned char* bRow = Bs + br * 128;
    int bOff = (bq ^ (br & 7)) << 4;

    float acc[2][4][4];
    #pragma unroll
    for (int i = 0; i < 2; i++)
        #pragma unroll
        for (int j = 0; j < 4; j++)
            #pragma unroll
            for (int k = 0; k < 4; k++) acc[i][j][k] = 0.f;

    for (int kt = 0; kt < K; kt += BK) {
        // stage A (16 floats/thread)
        {
            float4 v0 = *(const float4*)(Ag + kt);
            float4 v1 = *(const float4*)(Ag + kt + 4);
            float4 v2 = *(const float4*)(Ag + kt + 8);
            float4 v3 = *(const float4*)(Ag + kt + 12);
            uint4 h0, l0, h1, l1;
            cvt8(v0, v1, h0, l0);
            cvt8(v2, v3, h1, l1);
            *(uint4*)(aRow + aOff0)          = h0;
            *(uint4*)(aRow + aOff1)          = h1;
            *(uint4*)(aRow + (aOff0 ^ 0x40)) = l0;
            *(uint4*)(aRow + (aOff1 ^ 0x40)) = l1;
        }
        // stage B (8 floats/thread)
        {
            uint4 h0 = make_uint4(0, 0, 0, 0), l0 = make_uint4(0, 0, 0, 0);
            if (bok) {
                float4 w0 = *(const float4*)(Bg + kt);
                float4 w1 = *(const float4*)(Bg + kt + 4);
                cvt8(w0, w1, h0, l0);
            }
            *(uint4*)(bRow + bOff)          = h0;
            *(uint4*)(bRow + (bOff ^ 0x40)) = l0;
        }
        __syncthreads();

        #pragma unroll
        for (int s = 0; s < 2; s++) {
            uint32_t sx = s << 5;
            uint32_t ah[2][4], al[2][4];
            ldsm4(ah[0], aAddr[0] ^ sx);
            ldsm4(ah[1], aAddr[1] ^ sx);
            ldsm4(al[0], aAddr[0] ^ sx ^ 0x40);
            ldsm4(al[1], aAddr[1] ^ sx ^ 0x40);
            uint32_t t0[4], t1[4], u0[4], u1[4];
            ldsm4(t0, bAddr[0] ^ sx);
            ldsm4(t1, bAddr[1] ^ sx);
            ldsm4(u0, bAddr[0] ^ sx ^ 0x40);
            ldsm4(u1, bAddr[1] ^ sx ^ 0x40);
            uint32_t bh[4][2] = {{t0[0], t0[2]}, {t0[1], t0[3]}, {t1[0], t1[2]}, {t1[1], t1[3]}};
            uint32_t bl[4][2] = {{u0[0], u0[2]}, {u0[1], u0[3]}, {u1[0], u1[2]}, {u1[1], u1[3]}};
            #pragma unroll
            for (int mt = 0; mt < 2; mt++)
                #pragma unroll
                for (int nt = 0; nt < 4; nt++) {
                    mma_bf16(acc[mt][nt], ah[mt], bh[nt]);
                    mma_bf16(acc[mt][nt], ah[mt], bl[nt]);
                    mma_bf16(acc[mt][nt], al[mt], bh[nt]);
                }
        }
        __syncthreads();
    }

    // epilogue
    #pragma unroll
    for (int mt = 0; mt < 2; mt++) {
        #pragma unroll
        for (int nt = 0; nt < 4; nt++) {
            int rbase = m0 + wm * 32 + mt * 16 + (lane >> 2);
            int cbase = n0 + wn * 32 + nt * 8 + (lane & 3) * 2;
            #pragma unroll
            for (int e = 0; e < 4; e++) {
                int m = rbase + (e >> 1) * 8;
                int n = cbase + (e & 1);
                if (n >= N) continue;
                float v = acc[mt][nt][e];
                if (EPI == 0) {
                    C[(size_t)m * N + n] = v;
                } else if (EPI == 1) {
                    C[(size_t)m * N + n] = res[(size_t)m * N + n] + v;
                } else if (EPI == 2) {
                    float u = v + bias[n];
                    C[(size_t)m * N + n] = 0.5f * u * (1.f + erff(u * 0.70710678118f));
                } else {
                    float u = res[(size_t)m * N + n] + v + bias[n];
                    int b = m >> 10, t = m & 1023;
                    C[((size_t)b * DIMC + n) * LSEQ + t] = u;
                }
            }
        }
    }
}

// ---------------------------------------------------------------------------
extern "C" void kernel_launch(void* const* d_in, const int* in_sizes, int n_in,
                              void* d_out, int out_size) {
    const float* x        = (const float*)d_in[0];
    const float* ln_g     = (const float*)d_in[1];
    const float* ln_b     = (const float*)d_in[2];
    const float* in_proj  = (const float*)d_in[3];
    const float* conv_w   = (const float*)d_in[4];
    const float* conv_b   = (const float*)d_in[5];
    const float* x_proj   = (const float*)d_in[6];
    const float* dt_w     = (const float*)d_in[7];
    const float* dt_b     = (const float*)d_in[8];
    const float* A_log    = (const float*)d_in[9];
    const float* Dp       = (const float*)d_in[10];
    const float* out_proj = (const float*)d_in[11];
    const float* mlp_ln_g = (const float*)d_in[12];
    const float* mlp_ln_b = (const float*)d_in[13];
    const float* mlp_w1   = (const float*)d_in[14];
    const float* mlp_b1   = (const float*)d_in[15];
    const float* mlp_w2   = (const float*)d_in[16];
    const float* mlp_b2   = (const float*)d_in[17];
    float* out = (float*)d_out;

    float *p_xn, *p_xz, *p_xc, *p_dbl, *p_y, *p_xf, *p_xf2, *p_hln, *p_h1;
    cudaGetSymbolAddress((void**)&p_xn,  g_xn);
    cudaGetSymbolAddress((void**)&p_xz,  g_xz);
    cudaGetSymbolAddress((void**)&p_xc,  g_xc);
    cudaGetSymbolAddress((void**)&p_dbl, g_dbl);
    cudaGetSymbolAddress((void**)&p_y,   g_y);
    cudaGetSymbolAddress((void**)&p_xf,  g_xf);
    cudaGetSymbolAddress((void**)&p_xf2, g_xf2);
    cudaGetSymbolAddress((void**)&p_hln, g_hln);
    cudaGetSymbolAddress((void**)&p_h1,  g_h1);

    ln1_kernel<<<NTOK, 256>>>(x, ln_g, ln_b);
    gemm_bf16<0><<<dim3(1024 / 64, NTOK / 128), 256>>>(p_xn, in_proj, p_xz,
                                                       NTOK, 1024, 256, nullptr, nullptr);
    conv_silu_kernel<<<(NTOK * DINNER) / 256, 256>>>(conv_w, conv_b);
    gemm_bf16<0><<<dim3(1, NTOK / 128), 256>>>(p_xc, x_proj, p_dbl,
                                               NTOK, 48, 512, nullptr, nullptr);
    dt_kernel<<<NTOK / 8, 256>>>(dt_w, dt_b);
    scan_kernel<<<128, 128>>>(A_log, Dp);
    gemm_bf16<1><<<dim3(256 / 64, NTOK / 128), 256>>>(p_y, out_proj, p_xf2,
                                                      NTOK, 256, 512, nullptr, p_xf);
    ln2_kernel<<<NTOK / 8, 256>>>(mlp_ln_g, mlp_ln_b);
    gemm_bf16<2><<<dim3(1024 / 64, NTOK / 128), 256>>>(p_hln, mlp_w1, p_h1,
                                                       NTOK, 1024, 256, mlp_b1, nullptr);
    gemm_bf16<3><<<dim3(256 / 64, NTOK / 128), 256>>>(p_h1, mlp_w2, out,
                                                      NTOK, 256, 1024, mlp_b2, p_xf2);
}

// round 6
// speedup vs baseline: 1.8316x; 1.5673x over previous
#include <cuda_runtime.h>
#include <cuda_bf16.h>
#include <math.h>
#include <stdint.h>

// ---------------------------------------------------------------------------
// OptimizedMambaBlock: B=8, DIM=256, H=W=32 -> L=1024, tokens N=8192
// GEMMs: mma.sync.m16n8k16.bf16 hi/lo split (3 passes), ldmatrix + SW128,
// R6: 2-stage smem double buffering with register prefetch; scan prefetch.
// ---------------------------------------------------------------------------

#define NTOK   8192
#define LSEQ   1024
#define BSZ    8
#define DIMC   256
#define DINNER 512
#define DSTATE 16
#define DTRANK 16

__device__ float g_xf [NTOK * DIMC];
__device__ float g_xn [NTOK * DIMC];
__device__ float g_xz [NTOK * 1024];
__device__ float g_xc [NTOK * DINNER];
__device__ float g_dbl[NTOK * 48];
__device__ float g_dt [NTOK * DINNER];
__device__ float g_y  [NTOK * DINNER];
__device__ float g_xf2[NTOK * DIMC];
__device__ float g_hln[NTOK * DIMC];
__device__ float g_h1 [NTOK * 1024];

// ---------------------------------------------------------------------------
// LN1 + transpose
// ---------------------------------------------------------------------------
__global__ void ln1_kernel(const float* __restrict__ x,
                           const float* __restrict__ g,
                           const float* __restrict__ bta) {
    __shared__ float red[16];
    int token = blockIdx.x;
    int c = threadIdx.x;
    int b = token >> 10, t = token & 1023;
    float v = x[((size_t)b * DIMC + c) * LSEQ + t];
    float s = v, q = v * v;
    #pragma unroll
    for (int o = 16; o; o >>= 1) {
        s += __shfl_xor_sync(~0u, s, o);
        q += __shfl_xor_sync(~0u, q, o);
    }
    int w = c >> 5, l = c & 31;
    if (l == 0) { red[w] = s; red[8 + w] = q; }
    __syncthreads();
    s = 0.f; q = 0.f;
    #pragma unroll
    for (int i = 0; i < 8; i++) { s += red[i]; q += red[8 + i]; }
    float mean = s * (1.f / 256.f);
    float var  = q * (1.f / 256.f) - mean * mean;
    float rs = rsqrtf(var + 1e-5f);
    size_t o = (size_t)token * DIMC + c;
    g_xf[o] = v;
    g_xn[o] = (v - mean) * rs * g[c] + bta[c];
}

// ---------------------------------------------------------------------------
// LN2
// ---------------------------------------------------------------------------
__global__ void ln2_kernel(const float* __restrict__ g,
                           const float* __restrict__ bta) {
    int token = (blockIdx.x * blockDim.x + threadIdx.x) >> 5;
    int lane = threadIdx.x & 31;
    const float* row = g_xf2 + (size_t)token * DIMC;
    float4 a = *(const float4*)(row + lane * 4);
    float4 c4 = *(const float4*)(row + 128 + lane * 4);
    float s = a.x + a.y + a.z + a.w + c4.x + c4.y + c4.z + c4.w;
    float q = a.x*a.x + a.y*a.y + a.z*a.z + a.w*a.w
            + c4.x*c4.x + c4.y*c4.y + c4.z*c4.z + c4.w*c4.w;
    #pragma unroll
    for (int o = 16; o; o >>= 1) {
        s += __shfl_xor_sync(~0u, s, o);
        q += __shfl_xor_sync(~0u, q, o);
    }
    float mean = s * (1.f / 256.f);
    float var  = q * (1.f / 256.f) - mean * mean;
    float rs = rsqrtf(var + 1e-5f);
    float* out = g_hln + (size_t)token * DIMC;
    float va[8] = { a.x, a.y, a.z, a.w, c4.x, c4.y, c4.z, c4.w };
    #pragma unroll
    for (int h = 0; h < 2; h++) {
        #pragma unroll
        for (int i = 0; i < 4; i++) {
            int c = h * 128 + lane * 4 + i;
            out[c] = (va[h * 4 + i] - mean) * rs * g[c] + bta[c];
        }
    }
}

// ---------------------------------------------------------------------------
// conv + silu
// ---------------------------------------------------------------------------
__global__ void conv_silu_kernel(const float* __restrict__ cw,
                                 const float* __restrict__ cb) {
    int idx = blockIdx.x * blockDim.x + threadIdx.x;
    int token = idx >> 9;
    int d = idx & 511;
    int t = token & 1023;
    int tokbase = token - t;
    float acc = cb[d];
    #pragma unroll
    for (int j = 0; j < 4; j++) {
        int tt = t - 3 + j;
        if (tt >= 0)
            acc += g_xz[(size_t)(tokbase + tt) * 1024 + d] * cw[d * 4 + j];
    }
    float sv = acc / (1.f + __expf(-acc));
    g_xc[(size_t)token * DINNER + d] = sv;
}

// ---------------------------------------------------------------------------
// dt projection + softplus
// ---------------------------------------------------------------------------
__global__ void dt_kernel(const float* __restrict__ dtw,
                          const float* __restrict__ dtb) {
    __shared__ float swT[16][512];
    int tid = threadIdx.x;
    for (int idx = tid; idx < 512 * 16; idx += 256) {
        int d = idx >> 4, r = idx & 15;
        swT[r][d] = dtw[idx];
    }
    __syncthreads();
    int t0 = blockIdx.x * 8;
    for (int o = tid; o < 8 * 512; o += 256) {
        int tl = o >> 9, d = o & 511;
        int token = t0 + tl;
        const float* row = g_dbl + (size_t)token * 48;
        float acc = dtb[d];
        #pragma unroll
        for (int r = 0; r < 16; r++)
            acc += row[r] * swT[r][d];
        float sp = (acc > 20.f) ? acc : log1pf(__expf(acc));
        g_dt[(size_t)token * DINNER + d] = sp;
    }
}

// ---------------------------------------------------------------------------
// selective scan + gating, with next-step operand prefetch
// ---------------------------------------------------------------------------
__global__ void scan_kernel(const float* __restrict__ A_log,
                            const float* __restrict__ Dp) {
    int tid = threadIdx.x;
    int b  = blockIdx.x >> 4;
    int d  = ((blockIdx.x & 15) << 5) + (tid >> 2);
    int sq = tid & 3;

    float Al[4], h[4];
    #pragma unroll
    for (int j = 0; j < 4; j++) {
        Al[j] = -__expf(A_log[d * 16 + sq * 4 + j]) * 1.44269504f;
        h[j] = 0.f;
    }
    float dpv = Dp[d];

    const float* dtp  = g_dt  + (size_t)b * LSEQ * DINNER + d;
    const float* up   = g_xc  + (size_t)b * LSEQ * DINNER + d;
    const float* dblp = g_dbl + (size_t)b * LSEQ * 48;
    const float* zp   = g_xz  + (size_t)b * LSEQ * 1024 + 512 + d;
    float*       yp   = g_y   + (size_t)b * LSEQ * DINNER + d;

    // prefetch t=0
    float  dt_n = dtp[0];
    float  u_n  = up[0];
    float4 Bv_n = *(const float4*)(dblp + 16 + sq * 4);
    float4 Cv_n = *(const float4*)(dblp + 32 + sq * 4);
    float  z_n  = (sq == 0) ? zp[0] : 0.f;

    for (int t = 0; t < LSEQ; t++) {
        float  dt = dt_n;
        float  u  = u_n;
        float4 Bv = Bv_n;
        float4 Cv = Cv_n;
        float  z  = z_n;
        if (t + 1 < LSEQ) {
            dt_n = dtp[(size_t)(t + 1) * DINNER];
            u_n  = up [(size_t)(t + 1) * DINNER];
            Bv_n = *(const float4*)(dblp + (size_t)(t + 1) * 48 + 16 + sq * 4);
            Cv_n = *(const float4*)(dblp + (size_t)(t + 1) * 48 + 32 + sq * 4);
            if (sq == 0) z_n = zp[(size_t)(t + 1) * 1024];
        }
        float dtu = dt * u;
        float y = 0.f;
        h[0] = exp2f(dt * Al[0]) * h[0] + dtu * Bv.x; y += h[0] * Cv.x;
        h[1] = exp2f(dt * Al[1]) * h[1] + dtu * Bv.y; y += h[1] * Cv.y;
        h[2] = exp2f(dt * Al[2]) * h[2] + dtu * Bv.z; y += h[2] * Cv.z;
        h[3] = exp2f(dt * Al[3]) * h[3] + dtu * Bv.w; y += h[3] * Cv.w;
        y += __shfl_xor_sync(~0u, y, 1);
        y += __shfl_xor_sync(~0u, y, 2);
        if (sq == 0) {
            float gate = z / (1.f + __expf(-z));
            yp[(size_t)t * DINNER] = (y + u * dpv) * gate;
        }
    }
}

// ---------------------------------------------------------------------------
// bf16 split helpers
// ---------------------------------------------------------------------------
__device__ __forceinline__ uint32_t pack_bf16x2(float e, float o) {
    uint32_t d;
    asm("cvt.rn.bf16x2.f32 %0, %1, %2;" : "=r"(d) : "f"(o), "f"(e));
    return d;
}

__device__ __forceinline__ void cvt8(float4 x, float4 y, uint4& hi, uint4& lo) {
    hi.x = pack_bf16x2(x.x, x.y);
    hi.y = pack_bf16x2(x.z, x.w);
    hi.z = pack_bf16x2(y.x, y.y);
    hi.w = pack_bf16x2(y.z, y.w);
    float hxe = __uint_as_float(hi.x << 16), hxo = __uint_as_float(hi.x & 0xFFFF0000u);
    float hye = __uint_as_float(hi.y << 16), hyo = __uint_as_float(hi.y & 0xFFFF0000u);
    float hze = __uint_as_float(hi.z << 16), hzo = __uint_as_float(hi.z & 0xFFFF0000u);
    float hwe = __uint_as_float(hi.w << 16), hwo = __uint_as_float(hi.w & 0xFFFF0000u);
    lo.x = pack_bf16x2(x.x - hxe, x.y - hxo);
    lo.y = pack_bf16x2(x.z - hye, x.w - hyo);
    lo.z = pack_bf16x2(y.x - hze, y.y - hzo);
    lo.w = pack_bf16x2(y.z - hwe, y.w - hwo);
}

__device__ __forceinline__ void ldsm4(uint32_t r[4], uint32_t addr) {
    asm volatile("ldmatrix.sync.aligned.m8n8.x4.shared.b16 {%0,%1,%2,%3}, [%4];"
                 : "=r"(r[0]), "=r"(r[1]), "=r"(r[2]), "=r"(r[3]) : "r"(addr));
}

__device__ __forceinline__ void mma_bf16(float* c, const uint32_t* a, const uint32_t* b) {
    asm volatile(
        "mma.sync.aligned.m16n8k16.row.col.f32.bf16.bf16.f32 "
        "{%0,%1,%2,%3}, {%4,%5,%6,%7}, {%8,%9}, {%0,%1,%2,%3};\n"
        : "+f"(c[0]), "+f"(c[1]), "+f"(c[2]), "+f"(c[3])
        : "r"(a[0]), "r"(a[1]), "r"(a[2]), "r"(a[3]), "r"(b[0]), "r"(b[1]));
}

// ---------------------------------------------------------------------------
// Tensor-core GEMM (NT), 2-stage pipelined.
// BM=128 BN=64 BK=32, 256 threads, 8 warps (4m x 2n), 32x32 warp tiles.
// SMEM row (128B): 8 16B chunks, chunk id = plane*4 + sub*2 + k8half,
// stored at (chunk ^ (row & 7)) * 16.  Double buffered.
// ---------------------------------------------------------------------------
template <int EPI>
__global__ void __launch_bounds__(256, 2)
gemm_bf16(const float* __restrict__ A, const float* __restrict__ B,
          float* __restrict__ C, int M, int N, int K,
          const float* __restrict__ bias, const float* __restrict__ res) {
    const int BM = 128, BN = 64, BK = 32;
    const int ABUF = BM * 128;                 // 16384 bytes
    const int BBUF = BN * 128;                 // 8192 bytes
    __shared__ __align__(1024) unsigned char As[2 * ABUF];
    __shared__ __align__(1024) unsigned char Bs[2 * BBUF];

    int tid = threadIdx.x;
    int lane = tid & 31, wid = tid >> 5;
    int wm = wid & 3, wn = wid >> 2;
    int m0 = blockIdx.y * BM, n0 = blockIdx.x * BN;

    uint32_t As_u, Bs_u;
    asm("{ .reg .u64 t; cvta.to.shared.u64 t, %1; cvt.u32.u64 %0, t; }" : "=r"(As_u) : "l"(As));
    asm("{ .reg .u64 t; cvta.to.shared.u64 t, %1; cvt.u32.u64 %0, t; }" : "=r"(Bs_u) : "l"(Bs));

    // ldmatrix base addresses (hi plane, sub 0); sub1 = ^0x20, lo plane = ^0x40
    int lh = lane >> 4;
    uint32_t aAddr[2], bAddr[2];
    #pragma unroll
    for (int mt = 0; mt < 2; mt++) {
        int r = wm * 32 + mt * 16 + (lane & 15);
        aAddr[mt] = As_u + r * 128 + ((lh ^ (r & 7)) << 4);
    }
    #pragma unroll
    for (int np = 0; np < 2; np++) {
        int r = wn * 32 + np * 16 + (lane & 15);
        bAddr[np] = Bs_u + r * 128 + ((lh ^ (r & 7)) << 4);
    }

    // staging assignment
    int ar = tid >> 1, ahf = tid & 1;          // A: row, k-half (16 floats)
    const float* Ag = A + (size_t)(m0 + ar) * K + ahf * 16;
    unsigned char* aRow = As + ar * 128;
    int aOff0 = ((ahf * 2 + 0) ^ (ar & 7)) << 4;
    int aOff1 = ((ahf * 2 + 1) ^ (ar & 7)) << 4;
    int br = tid & 63, bq = tid >> 6;          // B: row, k-quarter (8 floats)
    const float* Bg = B + (size_t)(n0 + br) * K + bq * 8;
    bool bok = (n0 + br) < N;
    unsigned char* bRow = Bs + br * 128;
    int bOff = (bq ^ (br & 7)) << 4;

    float acc[2][4][4];
    #pragma unroll
    for (int i = 0; i < 2; i++)
        #pragma unroll
        for (int j = 0; j < 4; j++)
            #pragma unroll
            for (int k = 0; k < 4; k++) acc[i][j][k] = 0.f;

    int nk = K / BK;

    // ---- prologue: stage tile 0 into buffer 0
    {
        float4 v0 = *(const float4*)(Ag + 0);
        float4 v1 = *(const float4*)(Ag + 4);
        float4 v2 = *(const float4*)(Ag + 8);
        float4 v3 = *(const float4*)(Ag + 12);
        uint4 h0, l0, h1, l1;
        cvt8(v0, v1, h0, l0);
        cvt8(v2, v3, h1, l1);
        *(uint4*)(aRow + aOff0)          = h0;
        *(uint4*)(aRow + aOff1)          = h1;
        *(uint4*)(aRow + (aOff0 ^ 0x40)) = l0;
        *(uint4*)(aRow + (aOff1 ^ 0x40)) = l1;
        uint4 bh = make_uint4(0, 0, 0, 0), bl = make_uint4(0, 0, 0, 0);
        if (bok) {
            float4 w0 = *(const float4*)(Bg + 0);
            float4 w1 = *(const float4*)(Bg + 4);
            cvt8(w0, w1, bh, bl);
        }
        *(uint4*)(bRow + bOff)          = bh;
        *(uint4*)(bRow + (bOff ^ 0x40)) = bl;
    }
    __syncthreads();

    for (int it = 0; it < nk; it++) {
        int cur = it & 1;
        int kt1 = (it + 1) * BK;
        bool more = (it + 1) < nk;

        // issue global loads for next tile first (latency overlap)
        float4 v0, v1, v2, v3, w0, w1;
        if (more) {
            v0 = *(const float4*)(Ag + kt1);
            v1 = *(const float4*)(Ag + kt1 + 4);
            v2 = *(const float4*)(Ag + kt1 + 8);
            v3 = *(const float4*)(Ag + kt1 + 12);
            if (bok) {
                w0 = *(const float4*)(Bg + kt1);
                w1 = *(const float4*)(Bg + kt1 + 4);
            }
        }

        // MMAs on current buffer
        uint32_t aBufOff = cur * (uint32_t)ABUF;
        uint32_t bBufOff = cur * (uint32_t)BBUF;
        #pragma unroll
        for (int s = 0; s < 2; s++) {
            uint32_t sx = s << 5;
            uint32_t ah[2][4], al[2][4];
            ldsm4(ah[0], (aAddr[0] + aBufOff) ^ sx);
            ldsm4(ah[1], (aAddr[1] + aBufOff) ^ sx);
            ldsm4(al[0], (aAddr[0] + aBufOff) ^ sx ^ 0x40);
            ldsm4(al[1], (aAddr[1] + aBufOff) ^ sx ^ 0x40);
            uint32_t t0[4], t1[4], u0[4], u1[4];
            ldsm4(t0, (bAddr[0] + bBufOff) ^ sx);
            ldsm4(t1, (bAddr[1] + bBufOff) ^ sx);
            ldsm4(u0, (bAddr[0] + bBufOff) ^ sx ^ 0x40);
            ldsm4(u1, (bAddr[1] + bBufOff) ^ sx ^ 0x40);
            uint32_t bh2[4][2] = {{t0[0], t0[2]}, {t0[1], t0[3]}, {t1[0], t1[2]}, {t1[1], t1[3]}};
            uint32_t bl2[4][2] = {{u0[0], u0[2]}, {u0[1], u0[3]}, {u1[0], u1[2]}, {u1[1], u1[3]}};
            #pragma unroll
            for (int mt = 0; mt < 2; mt++)
                #pragma unroll
                for (int nt = 0; nt < 4; nt++) {
                    mma_bf16(acc[mt][nt], ah[mt], bh2[nt]);
                    mma_bf16(acc[mt][nt], ah[mt], bl2[nt]);
                    mma_bf16(acc[mt][nt], al[mt], bh2[nt]);
                }
        }

        // convert + store next tile into the other buffer
        if (more) {
            int nxt = cur ^ 1;
            unsigned char* aR = aRow + nxt * ABUF;
            unsigned char* bR = bRow + nxt * BBUF;
            uint4 h0, l0, h1, l1;
            cvt8(v0, v1, h0, l0);
            cvt8(v2, v3, h1, l1);
            *(uint4*)(aR + aOff0)          = h0;
            *(uint4*)(aR + aOff1)          = h1;
            *(uint4*)(aR + (aOff0 ^ 0x40)) = l0;
            *(uint4*)(aR + (aOff1 ^ 0x40)) = l1;
            uint4 bh = make_uint4(0, 0, 0, 0), bl = make_uint4(0, 0, 0, 0);
            if (bok) cvt8(w0, w1, bh, bl);
            *(uint4*)(bR + bOff)          = bh;
            *(uint4*)(bR + (bOff ^ 0x40)) = bl;
        }
        __syncthreads();
    }

    // epilogue
    #pragma unroll
    for (int mt = 0; mt < 2; mt++) {
        #pragma unroll
        for (int nt = 0; nt < 4; nt++) {
            int rbase = m0 + wm * 32 + mt * 16 + (lane >> 2);
            int cbase = n0 + wn * 32 + nt * 8 + (lane & 3) * 2;
            #pragma unroll
            for (int e = 0; e < 4; e++) {
                int m = rbase + (e >> 1) * 8;
                int n = cbase + (e & 1);
                if (n >= N) continue;
                float v = acc[mt][nt][e];
                if (EPI == 0) {
                    C[(size_t)m * N + n] = v;
                } else if (EPI == 1) {
                    C[(size_t)m * N + n] = res[(size_t)m * N + n] + v;
                } else if (EPI == 2) {
                    float u = v + bias[n];
                    C[(size_t)m * N + n] = 0.5f * u * (1.f + erff(u * 0.70710678118f));
                } else {
                    float u = res[(size_t)m * N + n] + v + bias[n];
                    int b = m >> 10, t = m & 1023;
                    C[((size_t)b * DIMC + n) * LSEQ + t] = u;
                }
            }
        }
    }
}

// ---------------------------------------------------------------------------
extern "C" void kernel_launch(void* const* d_in, const int* in_sizes, int n_in,
                              void* d_out, int out_size) {
    const float* x        = (const float*)d_in[0];
    const float* ln_g     = (const float*)d_in[1];
    const float* ln_b     = (const float*)d_in[2];
    const float* in_proj  = (const float*)d_in[3];
    const float* conv_w   = (const float*)d_in[4];
    const float* conv_b   = (const float*)d_in[5];
    const float* x_proj   = (const float*)d_in[6];
    const float* dt_w     = (const float*)d_in[7];
    const float* dt_b     = (const float*)d_in[8];
    const float* A_log    = (const float*)d_in[9];
    const float* Dp       = (const float*)d_in[10];
    const float* out_proj = (const float*)d_in[11];
    const float* mlp_ln_g = (const float*)d_in[12];
    const float* mlp_ln_b = (const float*)d_in[13];
    const float* mlp_w1   = (const float*)d_in[14];
    const float* mlp_b1   = (const float*)d_in[15];
    const float* mlp_w2   = (const float*)d_in[16];
    const float* mlp_b2   = (const float*)d_in[17];
    float* out = (float*)d_out;

    float *p_xn, *p_xz, *p_xc, *p_dbl, *p_y, *p_xf, *p_xf2, *p_hln, *p_h1;
    cudaGetSymbolAddress((void**)&p_xn,  g_xn);
    cudaGetSymbolAddress((void**)&p_xz,  g_xz);
    cudaGetSymbolAddress((void**)&p_xc,  g_xc);
    cudaGetSymbolAddress((void**)&p_dbl, g_dbl);
    cudaGetSymbolAddress((void**)&p_y,   g_y);
    cudaGetSymbolAddress((void**)&p_xf,  g_xf);
    cudaGetSymbolAddress((void**)&p_xf2, g_xf2);
    cudaGetSymbolAddress((void**)&p_hln, g_hln);
    cudaGetSymbolAddress((void**)&p_h1,  g_h1);

    ln1_kernel<<<NTOK, 256>>>(x, ln_g, ln_b);
    gemm_bf16<0><<<dim3(1024 / 64, NTOK / 128), 256>>>(p_xn, in_proj, p_xz,
                                                       NTOK, 1024, 256, nullptr, nullptr);
    conv_silu_kernel<<<(NTOK * DINNER) / 256, 256>>>(conv_w, conv_b);
    gemm_bf16<0><<<dim3(1, NTOK / 128), 256>>>(p_xc, x_proj, p_dbl,
                                               NTOK, 48, 512, nullptr, nullptr);
    dt_kernel<<<NTOK / 8, 256>>>(dt_w, dt_b);
    scan_kernel<<<128, 128>>>(A_log, Dp);
    gemm_bf16<1><<<dim3(256 / 64, NTOK / 128), 256>>>(p_y, out_proj, p_xf2,
                                                      NTOK, 256, 512, nullptr, p_xf);
    ln2_kernel<<<NTOK / 8, 256>>>(mlp_ln_g, mlp_ln_b);
    gemm_bf16<2><<<dim3(1024 / 64, NTOK / 128), 256>>>(p_hln, mlp_w1, p_h1,
                                                       NTOK, 1024, 256, mlp_b1, nullptr);
    gemm_bf16<3><<<dim3(256 / 64, NTOK / 128), 256>>>(p_h1, mlp_w2, out,
                                                      NTOK, 256, 1024, mlp_b2, p_xf2);
}

// round 8
// speedup vs baseline: 1.8603x; 1.0157x over previous
#include <cuda_runtime.h>
#include <cuda_bf16.h>
#include <math.h>
#include <stdint.h>

// ---------------------------------------------------------------------------
// OptimizedMambaBlock: B=8, DIM=256, H=W=32 -> L=1024, tokens N=8192
// R8 (= R7 + macro-collision fix): planar bf16 hi/lo operands precomputed
// outside the GEMM; GEMM is a cp.async 2-stage pipeline of pure
// ldmatrix + mma.m16n8k16.bf16 (3-pass hi/lo).
// ---------------------------------------------------------------------------

#define NTOK   8192
#define LSEQ   1024
#define DIMC   256
#define DINNER 512

// fp32 scratch
__device__ float g_xf [NTOK * DIMC];
__device__ float g_xz [NTOK * 1024];
__device__ float g_xc [NTOK * DINNER];
__device__ float g_dbl[NTOK * 48];
__device__ float g_dt [NTOK * DINNER];
__device__ float g_xf2[NTOK * DIMC];

// planar bf16 activations (hi/lo)
__device__ __nv_bfloat16 g_xnh [NTOK * DIMC],   g_xnl [NTOK * DIMC];
__device__ __nv_bfloat16 g_xch [NTOK * DINNER], g_xcl [NTOK * DINNER];
__device__ __nv_bfloat16 g_yh  [NTOK * DINNER], g_yl  [NTOK * DINNER];
__device__ __nv_bfloat16 g_hlnh[NTOK * DIMC],   g_hlnl[NTOK * DIMC];
__device__ __nv_bfloat16 g_h1h [NTOK * 1024],   g_h1l [NTOK * 1024];

// planar bf16 weights (hi/lo)
__device__ __nv_bfloat16 w_inh[1024 * 256], w_inl[1024 * 256];
__device__ __nv_bfloat16 w_xph[48 * 512],   w_xpl[48 * 512];
__device__ __nv_bfloat16 w_oph[256 * 512],  w_opl[256 * 512];
__device__ __nv_bfloat16 w_m1h[1024 * 256], w_m1l[1024 * 256];
__device__ __nv_bfloat16 w_m2h[256 * 1024], w_m2l[256 * 1024];

// ---------------------------------------------------------------------------
// weight split: fp32 -> bf16 hi + bf16 lo
// ---------------------------------------------------------------------------
__global__ void wconv_kernel(const float* __restrict__ w,
                             __nv_bfloat16* __restrict__ hi,
                             __nv_bfloat16* __restrict__ lo, int n) {
    int i = blockIdx.x * 256 + threadIdx.x;
    if (i < n) {
        float f = w[i];
        __nv_bfloat16 h = __float2bfloat16(f);
        hi[i] = h;
        lo[i] = __float2bfloat16(f - __bfloat162float(h));
    }
}

// ---------------------------------------------------------------------------
// LN1 + transpose: writes residual fp32 + planar bf16 normed
// ---------------------------------------------------------------------------
__global__ void ln1_kernel(const float* __restrict__ x,
                           const float* __restrict__ g,
                           const float* __restrict__ bta) {
    __shared__ float red[16];
    int token = blockIdx.x;
    int c = threadIdx.x;
    int b = token >> 10, t = token & 1023;
    float v = x[((size_t)b * DIMC + c) * LSEQ + t];
    float s = v, q = v * v;
    #pragma unroll
    for (int o = 16; o; o >>= 1) {
        s += __shfl_xor_sync(~0u, s, o);
        q += __shfl_xor_sync(~0u, q, o);
    }
    int w = c >> 5, l = c & 31;
    if (l == 0) { red[w] = s; red[8 + w] = q; }
    __syncthreads();
    s = 0.f; q = 0.f;
    #pragma unroll
    for (int i = 0; i < 8; i++) { s += red[i]; q += red[8 + i]; }
    float mean = s * (1.f / 256.f);
    float var  = q * (1.f / 256.f) - mean * mean;
    float rs = rsqrtf(var + 1e-5f);
    size_t o = (size_t)token * DIMC + c;
    g_xf[o] = v;
    float xn = (v - mean) * rs * g[c] + bta[c];
    __nv_bfloat16 h = __float2bfloat16(xn);
    g_xnh[o] = h;
    g_xnl[o] = __float2bfloat16(xn - __bfloat162float(h));
}

// ---------------------------------------------------------------------------
// LN2: fp32 in (xf2), planar bf16 out
// ---------------------------------------------------------------------------
__global__ void ln2_kernel(const float* __restrict__ g,
                           const float* __restrict__ bta) {
    int token = (blockIdx.x * blockDim.x + threadIdx.x) >> 5;
    int lane = threadIdx.x & 31;
    const float* row = g_xf2 + (size_t)token * DIMC;
    float4 a = *(const float4*)(row + lane * 4);
    float4 c4 = *(const float4*)(row + 128 + lane * 4);
    float s = a.x + a.y + a.z + a.w + c4.x + c4.y + c4.z + c4.w;
    float q = a.x*a.x + a.y*a.y + a.z*a.z + a.w*a.w
            + c4.x*c4.x + c4.y*c4.y + c4.z*c4.z + c4.w*c4.w;
    #pragma unroll
    for (int o = 16; o; o >>= 1) {
        s += __shfl_xor_sync(~0u, s, o);
        q += __shfl_xor_sync(~0u, q, o);
    }
    float mean = s * (1.f / 256.f);
    float var  = q * (1.f / 256.f) - mean * mean;
    float rs = rsqrtf(var + 1e-5f);
    float va[8] = { a.x, a.y, a.z, a.w, c4.x, c4.y, c4.z, c4.w };
    size_t base = (size_t)token * DIMC;
    #pragma unroll
    for (int h = 0; h < 2; h++) {
        #pragma unroll
        for (int i = 0; i < 4; i++) {
            int c = h * 128 + lane * 4 + i;
            float u = (va[h * 4 + i] - mean) * rs * g[c] + bta[c];
            __nv_bfloat16 hb = __float2bfloat16(u);
            g_hlnh[base + c] = hb;
            g_hlnl[base + c] = __float2bfloat16(u - __bfloat162float(hb));
        }
    }
}

// ---------------------------------------------------------------------------
// conv + silu: fp32 out (scan) + planar bf16 out (x_proj GEMM)
// ---------------------------------------------------------------------------
__global__ void conv_silu_kernel(const float* __restrict__ cw,
                                 const float* __restrict__ cb) {
    int idx = blockIdx.x * blockDim.x + threadIdx.x;
    int token = idx >> 9;
    int d = idx & 511;
    int t = token & 1023;
    int tokbase = token - t;
    float acc = cb[d];
    #pragma unroll
    for (int j = 0; j < 4; j++) {
        int tt = t - 3 + j;
        if (tt >= 0)
            acc += g_xz[(size_t)(tokbase + tt) * 1024 + d] * cw[d * 4 + j];
    }
    float sv = acc / (1.f + __expf(-acc));
    size_t o = (size_t)token * DINNER + d;
    g_xc[o] = sv;
    __nv_bfloat16 h = __float2bfloat16(sv);
    g_xch[o] = h;
    g_xcl[o] = __float2bfloat16(sv - __bfloat162float(h));
}

// ---------------------------------------------------------------------------
// dt projection + softplus
// ---------------------------------------------------------------------------
__global__ void dt_kernel(const float* __restrict__ dtw,
                          const float* __restrict__ dtb) {
    __shared__ float swT[16][512];
    int tid = threadIdx.x;
    for (int idx = tid; idx < 512 * 16; idx += 256) {
        int d = idx >> 4, r = idx & 15;
        swT[r][d] = dtw[idx];
    }
    __syncthreads();
    int t0 = blockIdx.x * 8;
    for (int o = tid; o < 8 * 512; o += 256) {
        int tl = o >> 9, d = o & 511;
        int token = t0 + tl;
        const float* row = g_dbl + (size_t)token * 48;
        float acc = dtb[d];
        #pragma unroll
        for (int r = 0; r < 16; r++)
            acc += row[r] * swT[r][d];
        float sp = (acc > 20.f) ? acc : log1pf(__expf(acc));
        g_dt[(size_t)token * DINNER + d] = sp;
    }
}

// ---------------------------------------------------------------------------
// selective scan + gating -> planar bf16 y
// ---------------------------------------------------------------------------
__global__ void scan_kernel(const float* __restrict__ A_log,
                            const float* __restrict__ Dp) {
    int tid = threadIdx.x;
    int b  = blockIdx.x >> 4;
    int d  = ((blockIdx.x & 15) << 5) + (tid >> 2);
    int sq = tid & 3;

    float Al[4], h[4];
    #pragma unroll
    for (int j = 0; j < 4; j++) {
        Al[j] = -__expf(A_log[d * 16 + sq * 4 + j]) * 1.44269504f;
        h[j] = 0.f;
    }
    float dpv = Dp[d];

    const float* dtp  = g_dt + (size_t)b * LSEQ * DINNER + d;
    const float* up   = g_xc + (size_t)b * LSEQ * DINNER + d;
    const float* dblp = g_dbl + (size_t)b * LSEQ * 48;
    const float* zp   = g_xz + (size_t)b * LSEQ * 1024 + 512 + d;
    size_t ybase = (size_t)b * LSEQ * DINNER + d;

    float  dt_n = dtp[0];
    float  u_n  = up[0];
    float4 Bv_n = *(const float4*)(dblp + 16 + sq * 4);
    float4 Cv_n = *(const float4*)(dblp + 32 + sq * 4);
    float  z_n  = (sq == 0) ? zp[0] : 0.f;

    for (int t = 0; t < LSEQ; t++) {
        float  dt = dt_n;
        float  u  = u_n;
        float4 Bv = Bv_n;
        float4 Cv = Cv_n;
        float  z  = z_n;
        if (t + 1 < LSEQ) {
            dt_n = dtp[(size_t)(t + 1) * DINNER];
            u_n  = up [(size_t)(t + 1) * DINNER];
            Bv_n = *(const float4*)(dblp + (size_t)(t + 1) * 48 + 16 + sq * 4);
            Cv_n = *(const float4*)(dblp + (size_t)(t + 1) * 48 + 32 + sq * 4);
            if (sq == 0) z_n = zp[(size_t)(t + 1) * 1024];
        }
        float dtu = dt * u;
        float y = 0.f;
        h[0] = exp2f(dt * Al[0]) * h[0] + dtu * Bv.x; y += h[0] * Cv.x;
        h[1] = exp2f(dt * Al[1]) * h[1] + dtu * Bv.y; y += h[1] * Cv.y;
        h[2] = exp2f(dt * Al[2]) * h[2] + dtu * Bv.z; y += h[2] * Cv.z;
        h[3] = exp2f(dt * Al[3]) * h[3] + dtu * Bv.w; y += h[3] * Cv.w;
        y += __shfl_xor_sync(~0u, y, 1);
        y += __shfl_xor_sync(~0u, y, 2);
        if (sq == 0) {
            float gate = z / (1.f + __expf(-z));
            float v = (y + u * dpv) * gate;
            __nv_bfloat16 hb = __float2bfloat16(v);
            g_yh[ybase + (size_t)t * DINNER] = hb;
            g_yl[ybase + (size_t)t * DINNER] = __float2bfloat16(v - __bfloat162float(hb));
        }
    }
}

// ---------------------------------------------------------------------------
// GEMM helpers
// ---------------------------------------------------------------------------
__device__ __forceinline__ uint32_t pack_bf16x2(float e, float o) {
    uint32_t d;
    asm("cvt.rn.bf16x2.f32 %0, %1, %2;" : "=r"(d) : "f"(o), "f"(e));
    return d;
}

__device__ __forceinline__ void ldsm4(uint32_t r[4], uint32_t addr) {
    asm volatile("ldmatrix.sync.aligned.m8n8.x4.shared.b16 {%0,%1,%2,%3}, [%4];"
                 : "=r"(r[0]), "=r"(r[1]), "=r"(r[2]), "=r"(r[3]) : "r"(addr));
}

__device__ __forceinline__ void mma_bf16(float* c, const uint32_t* a, const uint32_t* b) {
    asm volatile(
        "mma.sync.aligned.m16n8k16.row.col.f32.bf16.bf16.f32 "
        "{%0,%1,%2,%3}, {%4,%5,%6,%7}, {%8,%9}, {%0,%1,%2,%3};\n"
        : "+f"(c[0]), "+f"(c[1]), "+f"(c[2]), "+f"(c[3])
        : "r"(a[0]), "r"(a[1]), "r"(a[2]), "r"(a[3]), "r"(b[0]), "r"(b[1]));
}

__device__ __forceinline__ void cp16(uint32_t dst, const void* src, bool ok) {
    int sz = ok ? 16 : 0;
    asm volatile("cp.async.cg.shared.global [%0], [%1], 16, %2;\n"
                 :: "r"(dst), "l"(src), "r"(sz));
}
#define CP_COMMIT() asm volatile("cp.async.commit_group;\n" ::: "memory")

// ---------------------------------------------------------------------------
// Planar bf16 GEMM (NT): C[M,N] = (Ah+Al)[M,K] @ (Bh+Bl)[N,K]^T, 3-pass.
// BM=128 BN=64 BK=64, 256 threads, 8 warps (4m x 2n), 32x32 warp tiles.
// SMEM per stage: Ah[128][128B] Al Bh[64][128B] Bl = 48KB; 2 stages (96KB dyn)
// Row layout: 8 16B chunks (k8 each), chunk stored at (chunk ^ (row&7))*16.
// EPI: 0 fp32 C | 1 +res | 2 gelu+bias -> planar bf16 out | 3 res+bias, transp
// ---------------------------------------------------------------------------
template <int EPI>
__global__ void __launch_bounds__(256, 2)
gemm_pl(const __nv_bfloat16* __restrict__ Ah, const __nv_bfloat16* __restrict__ Al,
        const __nv_bfloat16* __restrict__ Bh, const __nv_bfloat16* __restrict__ Bl,
        float* __restrict__ C, int M, int N, int K,
        const float* __restrict__ bias, const float* __restrict__ res,
        __nv_bfloat16* __restrict__ outH, __nv_bfloat16* __restrict__ outL) {
    const int APL = 128 * 128;           // bytes per A plane per stage (16KB)
    const int BPL = 64 * 128;            // bytes per B plane per stage (8KB)
    const int STG = 2 * APL + 2 * BPL;   // 49152 bytes per stage
    extern __shared__ __align__(1024) unsigned char smem[];

    int tid = threadIdx.x;
    int lane = tid & 31, wid = tid >> 5;
    int wm = wid & 3, wn = wid >> 2;
    int m0 = blockIdx.y * 128, n0 = blockIdx.x * 64;

    uint32_t smem_u;
    asm("{ .reg .u64 t; cvta.to.shared.u64 t, %1; cvt.u32.u64 %0, t; }"
        : "=r"(smem_u) : "l"(smem));

    // ldmatrix within-stage offsets (k-sub 0); sub s => XOR (s<<5)
    int lh = lane >> 4;
    uint32_t aOff[2], bOff[2];
    #pragma unroll
    for (int mt = 0; mt < 2; mt++) {
        int r = wm * 32 + mt * 16 + (lane & 15);
        aOff[mt] = r * 128 + ((lh ^ (r & 7)) << 4);
    }
    #pragma unroll
    for (int np = 0; np < 2; np++) {
        int r = wn * 32 + np * 16 + (lane & 15);
        bOff[np] = 2 * APL + r * 128 + ((lh ^ (r & 7)) << 4);
    }

    float acc[2][4][4];
    #pragma unroll
    for (int i = 0; i < 2; i++)
        #pragma unroll
        for (int j = 0; j < 4; j++)
            #pragma unroll
            for (int k = 0; k < 4; k++) acc[i][j][k] = 0.f;

    int nk = K / 64;

    // stage copy: A 1024 chunks/plane (4/thread), B 512 (2/thread)
    auto stage_copy = [&](int st, int kt) {
        uint32_t sb = smem_u + st * STG;
        #pragma unroll
        for (int i = 0; i < 4; i++) {
            int chunk = tid + i * 256;
            int row = chunk >> 3, c = chunk & 7;
            size_t goff = (size_t)(m0 + row) * K + kt + c * 8;
            uint32_t d = sb + row * 128 + ((c ^ (row & 7)) << 4);
            cp16(d, Ah + goff, true);
            cp16(d + APL, Al + goff, true);
        }
        #pragma unroll
        for (int i = 0; i < 2; i++) {
            int chunk = tid + i * 256;
            int row = chunk >> 3, c = chunk & 7;
            bool ok = (n0 + row) < N;
            size_t goff = (size_t)(ok ? (n0 + row) : 0) * K + kt + c * 8;
            uint32_t d = sb + 2 * APL + row * 128 + ((c ^ (row & 7)) << 4);
            cp16(d, Bh + goff, ok);
            cp16(d + BPL, Bl + goff, ok);
        }
    };

    stage_copy(0, 0);
    CP_COMMIT();

    for (int it = 0; it < nk; it++) {
        bool more = (it + 1) < nk;
        if (more) {
            stage_copy((it + 1) & 1, (it + 1) * 64);
            CP_COMMIT();
            asm volatile("cp.async.wait_group 1;\n" ::: "memory");
        } else {
            asm volatile("cp.async.wait_group 0;\n" ::: "memory");
        }
        __syncthreads();

        uint32_t sb = smem_u + (it & 1) * STG;
        #pragma unroll
        for (int s = 0; s < 4; s++) {
            uint32_t sx = s << 5;
            uint32_t ah[2][4], al[2][4];
            ldsm4(ah[0], (sb + aOff[0]) ^ sx);
            ldsm4(ah[1], (sb + aOff[1]) ^ sx);
            ldsm4(al[0], (sb + aOff[0] + APL) ^ sx);
            ldsm4(al[1], (sb + aOff[1] + APL) ^ sx);
            uint32_t t0[4], t1[4], u0[4], u1[4];
            ldsm4(t0, (sb + bOff[0]) ^ sx);
            ldsm4(t1, (sb + bOff[1]) ^ sx);
            ldsm4(u0, (sb + bOff[0] + BPL) ^ sx);
            ldsm4(u1, (sb + bOff[1] + BPL) ^ sx);
            uint32_t bh2[4][2] = {{t0[0], t0[2]}, {t0[1], t0[3]}, {t1[0], t1[2]}, {t1[1], t1[3]}};
            uint32_t bl2[4][2] = {{u0[0], u0[2]}, {u0[1], u0[3]}, {u1[0], u1[2]}, {u1[1], u1[3]}};
            #pragma unroll
            for (int mt = 0; mt < 2; mt++)
                #pragma unroll
                for (int nt = 0; nt < 4; nt++) {
                    mma_bf16(acc[mt][nt], ah[mt], bh2[nt]);
                    mma_bf16(acc[mt][nt], ah[mt], bl2[nt]);
                    mma_bf16(acc[mt][nt], al[mt], bh2[nt]);
                }
        }
        __syncthreads();
    }

    // epilogue
    #pragma unroll
    for (int mt = 0; mt < 2; mt++) {
        #pragma unroll
        for (int nt = 0; nt < 4; nt++) {
            int rbase = m0 + wm * 32 + mt * 16 + (lane >> 2);
            int cbase = n0 + wn * 32 + nt * 8 + (lane & 3) * 2;
            if (EPI == 2) {
                #pragma unroll
                for (int ep = 0; ep < 2; ep++) {
                    int m = rbase + ep * 8;
                    int n = cbase;
                    float u0 = acc[mt][nt][ep * 2 + 0] + bias[n];
                    float u1 = acc[mt][nt][ep * 2 + 1] + bias[n + 1];
                    float g0 = 0.5f * u0 * (1.f + erff(u0 * 0.70710678118f));
                    float g1 = 0.5f * u1 * (1.f + erff(u1 * 0.70710678118f));
                    uint32_t hp = pack_bf16x2(g0, g1);
                    float h0 = __uint_as_float(hp << 16);
                    float h1 = __uint_as_float(hp & 0xFFFF0000u);
                    uint32_t lp = pack_bf16x2(g0 - h0, g1 - h1);
                    size_t off = ((size_t)m * N + n) >> 1;
                    ((uint32_t*)outH)[off] = hp;
                    ((uint32_t*)outL)[off] = lp;
                }
            } else {
                #pragma unroll
                for (int e = 0; e < 4; e++) {
                    int m = rbase + (e >> 1) * 8;
                    int n = cbase + (e & 1);
                    if (n >= N) continue;
                    float v = acc[mt][nt][e];
                    if (EPI == 0) {
                        C[(size_t)m * N + n] = v;
                    } else if (EPI == 1) {
                        C[(size_t)m * N + n] = res[(size_t)m * N + n] + v;
                    } else { // EPI 3: residual + bias + transposed store
                        float u = res[(size_t)m * N + n] + v + bias[n];
                        int b = m >> 10, t = m & 1023;
                        C[((size_t)b * DIMC + n) * LSEQ + t] = u;
                    }
                }
            }
        }
    }
}

// ---------------------------------------------------------------------------
extern "C" void kernel_launch(void* const* d_in, const int* in_sizes, int n_in,
                              void* d_out, int out_size) {
    const float* x        = (const float*)d_in[0];
    const float* ln_g     = (const float*)d_in[1];
    const float* ln_b     = (const float*)d_in[2];
    const float* in_proj  = (const float*)d_in[3];
    const float* conv_w   = (const float*)d_in[4];
    const float* conv_b   = (const float*)d_in[5];
    const float* x_proj   = (const float*)d_in[6];
    const float* dt_w     = (const float*)d_in[7];
    const float* dt_b     = (const float*)d_in[8];
    const float* A_log    = (const float*)d_in[9];
    const float* Dp       = (const float*)d_in[10];
    const float* out_proj = (const float*)d_in[11];
    const float* mlp_ln_g = (const float*)d_in[12];
    const float* mlp_ln_b = (const float*)d_in[13];
    const float* mlp_w1   = (const float*)d_in[14];
    const float* mlp_b1   = (const float*)d_in[15];
    const float* mlp_w2   = (const float*)d_in[16];
    const float* mlp_b2   = (const float*)d_in[17];
    float* out = (float*)d_out;

    float *p_dbl, *p_xf, *p_xf2;
    cudaGetSymbolAddress((void**)&p_dbl, g_dbl);
    cudaGetSymbolAddress((void**)&p_xf,  g_xf);
    cudaGetSymbolAddress((void**)&p_xf2, g_xf2);
    __nv_bfloat16 *p_xnh, *p_xnl, *p_xch, *p_xcl, *p_yh, *p_yl, *p_hlnh, *p_hlnl, *p_h1h, *p_h1l;
    cudaGetSymbolAddress((void**)&p_xnh,  g_xnh);
    cudaGetSymbolAddress((void**)&p_xnl,  g_xnl);
    cudaGetSymbolAddress((void**)&p_xch,  g_xch);
    cudaGetSymbolAddress((void**)&p_xcl,  g_xcl);
    cudaGetSymbolAddress((void**)&p_yh,   g_yh);
    cudaGetSymbolAddress((void**)&p_yl,   g_yl);
    cudaGetSymbolAddress((void**)&p_hlnh, g_hlnh);
    cudaGetSymbolAddress((void**)&p_hlnl, g_hlnl);
    cudaGetSymbolAddress((void**)&p_h1h,  g_h1h);
    cudaGetSymbolAddress((void**)&p_h1l,  g_h1l);
    __nv_bfloat16 *p_inh, *p_inl, *p_xph, *p_xpl, *p_oph, *p_opl, *p_m1h, *p_m1l, *p_m2h, *p_m2l;
    cudaGetSymbolAddress((void**)&p_inh, w_inh);
    cudaGetSymbolAddress((void**)&p_inl, w_inl);
    cudaGetSymbolAddress((void**)&p_xph, w_xph);
    cudaGetSymbolAddress((void**)&p_xpl, w_xpl);
    cudaGetSymbolAddress((void**)&p_oph, w_oph);
    cudaGetSymbolAddress((void**)&p_opl, w_opl);
    cudaGetSymbolAddress((void**)&p_m1h, w_m1h);
    cudaGetSymbolAddress((void**)&p_m1l, w_m1l);
    cudaGetSymbolAddress((void**)&p_m2h, w_m2h);
    cudaGetSymbolAddress((void**)&p_m2l, w_m2l);

    const int SMEM = 2 * (2 * 128 * 128 + 2 * 64 * 128);  // 98304
    cudaFuncSetAttribute(gemm_pl<0>, cudaFuncAttributeMaxDynamicSharedMemorySize, SMEM);
    cudaFuncSetAttribute(gemm_pl<1>, cudaFuncAttributeMaxDynamicSharedMemorySize, SMEM);
    cudaFuncSetAttribute(gemm_pl<2>, cudaFuncAttributeMaxDynamicSharedMemorySize, SMEM);
    cudaFuncSetAttribute(gemm_pl<3>, cudaFuncAttributeMaxDynamicSharedMemorySize, SMEM);

    // weight splits
    wconv_kernel<<<(1024 * 256 + 255) / 256, 256>>>(in_proj,  p_inh, p_inl, 1024 * 256);
    wconv_kernel<<<(48 * 512 + 255) / 256,   256>>>(x_proj,   p_xph, p_xpl, 48 * 512);
    wconv_kernel<<<(256 * 512 + 255) / 256,  256>>>(out_proj, p_oph, p_opl, 256 * 512);
    wconv_kernel<<<(1024 * 256 + 255) / 256, 256>>>(mlp_w1,   p_m1h, p_m1l, 1024 * 256);
    wconv_kernel<<<(256 * 1024 + 255) / 256, 256>>>(mlp_w2,   p_m2h, p_m2l, 256 * 1024);

    float *p_xz;
    cudaGetSymbolAddress((void**)&p_xz, g_xz);

    // 1. ln1
    ln1_kernel<<<NTOK, 256>>>(x, ln_g, ln_b);
    // 2. in_proj (8192 x 1024, K=256)
    gemm_pl<0><<<dim3(1024 / 64, NTOK / 128), 256, SMEM>>>(
        p_xnh, p_xnl, p_inh, p_inl, p_xz, NTOK, 1024, 256, nullptr, nullptr, nullptr, nullptr);
    // 3. conv + silu
    conv_silu_kernel<<<(NTOK * DINNER) / 256, 256>>>(conv_w, conv_b);
    // 4. x_proj (8192 x 48, K=512)
    gemm_pl<0><<<dim3(1, NTOK / 128), 256, SMEM>>>(
        p_xch, p_xcl, p_xph, p_xpl, p_dbl, NTOK, 48, 512, nullptr, nullptr, nullptr, nullptr);
    // 5. dt projection
    dt_kernel<<<NTOK / 8, 256>>>(dt_w, dt_b);
    // 6. selective scan
    scan_kernel<<<128, 128>>>(A_log, Dp);
    // 7. out_proj + residual (8192 x 256, K=512)
    gemm_pl<1><<<dim3(256 / 64, NTOK / 128), 256, SMEM>>>(
        p_yh, p_yl, p_oph, p_opl, p_xf2, NTOK, 256, 512, nullptr, p_xf, nullptr, nullptr);
    // 8. ln2
    ln2_kernel<<<NTOK / 8, 256>>>(mlp_ln_g, mlp_ln_b);
    // 9. mlp1 + gelu -> planar h1 (8192 x 1024, K=256)
    gemm_pl<2><<<dim3(1024 / 64, NTOK / 128), 256, SMEM>>>(
        p_hlnh, p_hlnl, p_m1h, p_m1l, nullptr, NTOK, 1024, 256, mlp_b1, nullptr, p_h1h, p_h1l);
    // 10. mlp2 + residual + transposed store (8192 x 256, K=1024)
    gemm_pl<3><<<dim3(256 / 64, NTOK / 128), 256, SMEM>>>(
        p_h1h, p_h1l, p_m2h, p_m2l, out, NTOK, 256, 1024, mlp_b2, p_xf2, nullptr, nullptr);
}

// round 9
// speedup vs baseline: 2.6207x; 1.4088x over previous
#include <cuda_runtime.h>
#include <cuda_bf16.h>
#include <math.h>
#include <stdint.h>

// ---------------------------------------------------------------------------
// OptimizedMambaBlock: B=8, DIM=256, H=W=32 -> L=1024, tokens N=8192
// R9: scan operands in [b][d][t] (t-contiguous) layout; coalesced ln1;
// smem-transposed final store; fused weight split. GEMM pipeline as R8.
// ---------------------------------------------------------------------------

#define NTOK   8192
#define LSEQ   1024
#define DIMC   256
#define DINNER 512

// fp32 scratch
__device__ float g_xf [NTOK * DIMC];       // residual (token-major)
__device__ float g_xz [NTOK * 1024];       // in_proj out (token-major)
__device__ float g_dbl[NTOK * 48];         // x_proj out
__device__ float g_xf2[NTOK * DIMC];       // after out_proj
// scan-layout operands [b][d][t]
__device__ float g_uT [8 * DINNER * LSEQ];
__device__ float g_gT [8 * DINNER * LSEQ];
__device__ float g_dtT[8 * DINNER * LSEQ];

// planar bf16 activations (hi/lo, token-major)
__device__ __nv_bfloat16 g_xnh [NTOK * DIMC],   g_xnl [NTOK * DIMC];
__device__ __nv_bfloat16 g_xch [NTOK * DINNER], g_xcl [NTOK * DINNER];
__device__ __nv_bfloat16 g_yh  [NTOK * DINNER], g_yl  [NTOK * DINNER];
__device__ __nv_bfloat16 g_hlnh[NTOK * DIMC],   g_hlnl[NTOK * DIMC];
__device__ __nv_bfloat16 g_h1h [NTOK * 1024],   g_h1l [NTOK * 1024];

// planar bf16 weights (hi/lo)
__device__ __nv_bfloat16 w_inh[1024 * 256], w_inl[1024 * 256];
__device__ __nv_bfloat16 w_xph[48 * 512],   w_xpl[48 * 512];
__device__ __nv_bfloat16 w_oph[256 * 512],  w_opl[256 * 512];
__device__ __nv_bfloat16 w_m1h[1024 * 256], w_m1l[1024 * 256];
__device__ __nv_bfloat16 w_m2h[256 * 1024], w_m2l[256 * 1024];

// ---------------------------------------------------------------------------
// fused weight split: all 5 weight matrices, fp32 -> bf16 hi + lo
// ---------------------------------------------------------------------------
#define WS0 262144            // in_proj 1024x256
#define WS1 (WS0 + 24576)     // x_proj 48x512
#define WS2 (WS1 + 131072)    // out_proj 256x512
#define WS3 (WS2 + 262144)    // mlp_w1 1024x256
#define WS4 (WS3 + 262144)    // mlp_w2 256x1024
__global__ void wconv_all(const float* __restrict__ w_in, const float* __restrict__ w_xp,
                          const float* __restrict__ w_op, const float* __restrict__ w_m1,
                          const float* __restrict__ w_m2) {
    int i = blockIdx.x * 256 + threadIdx.x;
    const float* src;
    __nv_bfloat16 *dh, *dl;
    int off;
    if      (i < WS0) { src = w_in; dh = w_inh; dl = w_inl; off = i; }
    else if (i < WS1) { src = w_xp; dh = w_xph; dl = w_xpl; off = i - WS0; }
    else if (i < WS2) { src = w_op; dh = w_oph; dl = w_opl; off = i - WS1; }
    else if (i < WS3) { src = w_m1; dh = w_m1h; dl = w_m1l; off = i - WS2; }
    else if (i < WS4) { src = w_m2; dh = w_m2h; dl = w_m2l; off = i - WS3; }
    else return;
    float f = src[off];
    __nv_bfloat16 h = __float2bfloat16(f);
    dh[off] = h;
    dl[off] = __float2bfloat16(f - __bfloat162float(h));
}

// ---------------------------------------------------------------------------
// LN1: coalesced smem-transpose. Block = 32 tokens x 256 channels.
// grid 256 (= 8 b x 32 t-blocks), block 256 (8 warps).
// ---------------------------------------------------------------------------
__global__ void ln1_kernel(const float* __restrict__ x,
                           const float* __restrict__ g,
                           const float* __restrict__ bta) {
    __shared__ float xs[32][257];
    int tid = threadIdx.x, lane = tid & 31, w = tid >> 5;
    int b = blockIdx.x >> 5, tb = blockIdx.x & 31;
    // load: warp w loads channels w*32..w*32+31, lanes span t (coalesced)
    #pragma unroll 8
    for (int j = 0; j < 32; j++) {
        int c = w * 32 + j;
        xs[lane][c] = x[(((size_t)b * DIMC + c) << 10) + tb * 32 + lane];
    }
    __syncthreads();
    // reduce: warp w handles 4 tokens
    for (int q = 0; q < 4; q++) {
        int tt = w * 4 + q;
        float v[8], s = 0.f, sq = 0.f;
        #pragma unroll
        for (int k = 0; k < 8; k++) {
            v[k] = xs[tt][lane + k * 32];
            s += v[k]; sq += v[k] * v[k];
        }
        #pragma unroll
        for (int o = 16; o; o >>= 1) {
            s  += __shfl_xor_sync(~0u, s, o);
            sq += __shfl_xor_sync(~0u, sq, o);
        }
        float mean = s * (1.f / 256.f);
        float var  = sq * (1.f / 256.f) - mean * mean;
        float rs = rsqrtf(var + 1e-5f);
        size_t base = (size_t)(b * 1024 + tb * 32 + tt) * DIMC;
        #pragma unroll
        for (int k = 0; k < 8; k++) {
            int c = lane + k * 32;
            g_xf[base + c] = v[k];
            float xn = (v[k] - mean) * rs * g[c] + bta[c];
            __nv_bfloat16 h = __float2bfloat16(xn);
            g_xnh[base + c] = h;
            g_xnl[base + c] = __float2bfloat16(xn - __bfloat162float(h));
        }
    }
}

// ---------------------------------------------------------------------------
// LN2: fp32 in (xf2 token-major), planar bf16 out (token-major)
// ---------------------------------------------------------------------------
__global__ void ln2_kernel(const float* __restrict__ g,
                           const float* __restrict__ bta) {
    int token = (blockIdx.x * blockDim.x + threadIdx.x) >> 5;
    int lane = threadIdx.x & 31;
    const float* row = g_xf2 + (size_t)token * DIMC;
    float4 a = *(const float4*)(row + lane * 4);
    float4 c4 = *(const float4*)(row + 128 + lane * 4);
    float s = a.x + a.y + a.z + a.w + c4.x + c4.y + c4.z + c4.w;
    float q = a.x*a.x + a.y*a.y + a.z*a.z + a.w*a.w
            + c4.x*c4.x + c4.y*c4.y + c4.z*c4.z + c4.w*c4.w;
    #pragma unroll
    for (int o = 16; o; o >>= 1) {
        s += __shfl_xor_sync(~0u, s, o);
        q += __shfl_xor_sync(~0u, q, o);
    }
    float mean = s * (1.f / 256.f);
    float var  = q * (1.f / 256.f) - mean * mean;
    float rs = rsqrtf(var + 1e-5f);
    float va[8] = { a.x, a.y, a.z, a.w, c4.x, c4.y, c4.z, c4.w };
    size_t base = (size_t)token * DIMC;
    #pragma unroll
    for (int h = 0; h < 2; h++) {
        #pragma unroll
        for (int i = 0; i < 4; i++) {
            int c = h * 128 + lane * 4 + i;
            float u = (va[h * 4 + i] - mean) * rs * g[c] + bta[c];
            __nv_bfloat16 hb = __float2bfloat16(u);
            g_hlnh[base + c] = hb;
            g_hlnl[base + c] = __float2bfloat16(u - __bfloat162float(hb));
        }
    }
}

// ---------------------------------------------------------------------------
// conv + silu + gate: smem-tiled. Block covers 64 d x 32 t of one batch.
// Emits: g_uT, g_gT in [b][d][t]; g_xch/xcl planar token-major.
// grid (32 tblk, 8 dblk, 8 b), block 256.
// ---------------------------------------------------------------------------
__global__ void conv_silu_kernel(const float* __restrict__ cw,
                                 const float* __restrict__ cb) {
    __shared__ float xs[35][64];
    __shared__ float zs[32][64];
    __shared__ float us[32][65];
    __shared__ float gs[32][65];
    int b = blockIdx.z, d0 = blockIdx.y * 64, t0 = blockIdx.x * 32;
    int tid = threadIdx.x;

    for (int i = tid; i < 35 * 64; i += 256) {
        int tt = i >> 6, dd = i & 63;
        int t = t0 - 3 + tt;
        xs[tt][dd] = (t >= 0) ? g_xz[((size_t)(b * 1024 + t) << 10) + d0 + dd] : 0.f;
    }
    for (int i = tid; i < 32 * 64; i += 256) {
        int tt = i >> 6, dd = i & 63;
        zs[tt][dd] = g_xz[((size_t)(b * 1024 + t0 + tt) << 10) + 512 + d0 + dd];
    }
    __syncthreads();

    for (int i = tid; i < 32 * 64; i += 256) {
        int tt = i >> 6, dd = i & 63;
        int d = d0 + dd;
        float acc = cb[d];
        #pragma unroll
        for (int j = 0; j < 4; j++)
            acc += xs[tt + j][dd] * cw[d * 4 + j];
        us[tt][dd] = acc / (1.f + __expf(-acc));
        float z = zs[tt][dd];
        gs[tt][dd] = z / (1.f + __expf(-z));
    }
    __syncthreads();

    // scan-layout outputs: lanes span t (coalesced)
    {
        int tt = tid & 31, dgrp = tid >> 5;
        #pragma unroll
        for (int k = 0; k < 8; k++) {
            int dd = dgrp * 8 + k;
            size_t o = ((size_t)(b * DINNER + d0 + dd) << 10) + t0 + tt;
            g_uT[o] = us[tt][dd];
            g_gT[o] = gs[tt][dd];
        }
    }
    // planar GEMM outputs: lanes span d (coalesced)
    {
        int dd = tid & 63, tq = tid >> 6;
        #pragma unroll
        for (int k = 0; k < 8; k++) {
            int tt = k * 4 + tq;
            float u = us[tt][dd];
            __nv_bfloat16 h = __float2bfloat16(u);
            size_t o = (size_t)(b * 1024 + t0 + tt) * DINNER + d0 + dd;
            g_xch[o] = h;
            g_xcl[o] = __float2bfloat16(u - __bfloat162float(h));
        }
    }
}

// ---------------------------------------------------------------------------
// dt projection + softplus -> g_dtT [b][d][t].
// grid 256 (= 8 b x 32 t-blocks of 32 tokens), block 256 (8 warps).
// warp w covers d = w*64..w*64+63, lane = t (writes coalesced).
// ---------------------------------------------------------------------------
__global__ void dt_kernel(const float* __restrict__ dtw,
                          const float* __restrict__ dtb) {
    __shared__ float swT[16][512];
    __shared__ float db[32][17];
    int tid = threadIdx.x, lane = tid & 31, w = tid >> 5;
    int b = blockIdx.x >> 5, t0 = (blockIdx.x & 31) * 32;
    for (int i = tid; i < 16 * 512; i += 256) {
        int dd = i >> 4, r = i & 15;
        swT[r][dd] = dtw[i];
    }
    for (int i = tid; i < 512; i += 256) {
        int tt = i >> 4, r = i & 15;
        db[tt][r] = g_dbl[(size_t)(b * 1024 + t0 + tt) * 48 + r];
    }
    __syncthreads();
    float drow[16];
    #pragma unroll
    for (int r = 0; r < 16; r++) drow[r] = db[lane][r];
    for (int dd = 0; dd < 64; dd++) {
        int d = w * 64 + dd;
        float acc = dtb[d];
        #pragma unroll
        for (int r = 0; r < 16; r++)
            acc += drow[r] * swT[r][d];
        float sp = (acc > 20.f) ? acc : log1pf(__expf(acc));
        g_dtT[((size_t)(b * DINNER + d) << 10) + t0 + lane] = sp;
    }
}

// ---------------------------------------------------------------------------
// selective scan + gating (operands t-contiguous) -> planar bf16 y
// ---------------------------------------------------------------------------
__global__ void scan_kernel(const float* __restrict__ A_log,
                            const float* __restrict__ Dp) {
    int tid = threadIdx.x;
    int b  = blockIdx.x >> 4;
    int d  = ((blockIdx.x & 15) << 5) + (tid >> 2);
    int sq = tid & 3;

    float Al[4], h[4];
    #pragma unroll
    for (int j = 0; j < 4; j++) {
        Al[j] = -__expf(A_log[d * 16 + sq * 4 + j]) * 1.44269504f;
        h[j] = 0.f;
    }
    float dpv = Dp[d];

    const float* dtp  = g_dtT + ((size_t)(b * DINNER + d) << 10);
    const float* up   = g_uT  + ((size_t)(b * DINNER + d) << 10);
    const float* gp   = g_gT  + ((size_t)(b * DINNER + d) << 10);
    const float* dblp = g_dbl + (size_t)b * LSEQ * 48;
    size_t ybase = (size_t)b * LSEQ * DINNER + d;

    float  dt_n = dtp[0];
    float  u_n  = up[0];
    float4 Bv_n = *(const float4*)(dblp + 16 + sq * 4);
    float4 Cv_n = *(const float4*)(dblp + 32 + sq * 4);
    float  g_n  = (sq == 0) ? gp[0] : 0.f;

    for (int t = 0; t < LSEQ; t++) {
        float  dt = dt_n;
        float  u  = u_n;
        float4 Bv = Bv_n;
        float4 Cv = Cv_n;
        float  gate = g_n;
        if (t + 1 < LSEQ) {
            dt_n = dtp[t + 1];
            u_n  = up[t + 1];
            Bv_n = *(const float4*)(dblp + (size_t)(t + 1) * 48 + 16 + sq * 4);
            Cv_n = *(const float4*)(dblp + (size_t)(t + 1) * 48 + 32 + sq * 4);
            if (sq == 0) g_n = gp[t + 1];
        }
        float dtu = dt * u;
        float y = 0.f;
        h[0] = exp2f(dt * Al[0]) * h[0] + dtu * Bv.x; y += h[0] * Cv.x;
        h[1] = exp2f(dt * Al[1]) * h[1] + dtu * Bv.y; y += h[1] * Cv.y;
        h[2] = exp2f(dt * Al[2]) * h[2] + dtu * Bv.z; y += h[2] * Cv.z;
        h[3] = exp2f(dt * Al[3]) * h[3] + dtu * Bv.w; y += h[3] * Cv.w;
        y += __shfl_xor_sync(~0u, y, 1);
        y += __shfl_xor_sync(~0u, y, 2);
        if (sq == 0) {
            float v = (y + u * dpv) * gate;
            __nv_bfloat16 hb = __float2bfloat16(v);
            g_yh[ybase + (size_t)t * DINNER] = hb;
            g_yl[ybase + (size_t)t * DINNER] = __float2bfloat16(v - __bfloat162float(hb));
        }
    }
}

// ---------------------------------------------------------------------------
// GEMM helpers
// ---------------------------------------------------------------------------
__device__ __forceinline__ uint32_t pack_bf16x2(float e, float o) {
    uint32_t d;
    asm("cvt.rn.bf16x2.f32 %0, %1, %2;" : "=r"(d) : "f"(o), "f"(e));
    return d;
}

__device__ __forceinline__ void ldsm4(uint32_t r[4], uint32_t addr) {
    asm volatile("ldmatrix.sync.aligned.m8n8.x4.shared.b16 {%0,%1,%2,%3}, [%4];"
                 : "=r"(r[0]), "=r"(r[1]), "=r"(r[2]), "=r"(r[3]) : "r"(addr));
}

__device__ __forceinline__ void mma_bf16(float* c, const uint32_t* a, const uint32_t* b) {
    asm volatile(
        "mma.sync.aligned.m16n8k16.row.col.f32.bf16.bf16.f32 "
        "{%0,%1,%2,%3}, {%4,%5,%6,%7}, {%8,%9}, {%0,%1,%2,%3};\n"
        : "+f"(c[0]), "+f"(c[1]), "+f"(c[2]), "+f"(c[3])
        : "r"(a[0]), "r"(a[1]), "r"(a[2]), "r"(a[3]), "r"(b[0]), "r"(b[1]));
}

__device__ __forceinline__ void cp16(uint32_t dst, const void* src, bool ok) {
    int sz = ok ? 16 : 0;
    asm volatile("cp.async.cg.shared.global [%0], [%1], 16, %2;\n"
                 :: "r"(dst), "l"(src), "r"(sz));
}
#define CP_COMMIT() asm volatile("cp.async.commit_group;\n" ::: "memory")

// ---------------------------------------------------------------------------
// Planar bf16 GEMM (NT), cp.async 2-stage. BM=128 BN=64 BK=64, 256 thr.
// EPI: 0 fp32 | 1 +res | 2 gelu+bias -> planar bf16 | 3 res+bias, smem-transp
// ---------------------------------------------------------------------------
template <int EPI>
__global__ void __launch_bounds__(256, 2)
gemm_pl(const __nv_bfloat16* __restrict__ Ah, const __nv_bfloat16* __restrict__ Al,
        const __nv_bfloat16* __restrict__ Bh, const __nv_bfloat16* __restrict__ Bl,
        float* __restrict__ C, int M, int N, int K,
        const float* __restrict__ bias, const float* __restrict__ res,
        __nv_bfloat16* __restrict__ outH, __nv_bfloat16* __restrict__ outL) {
    const int APL = 128 * 128;           // bytes per A plane per stage
    const int BPL = 64 * 128;            // bytes per B plane per stage
    const int STG = 2 * APL + 2 * BPL;   // bytes per stage
    extern __shared__ __align__(1024) unsigned char smem[];

    int tid = threadIdx.x;
    int lane = tid & 31, wid = tid >> 5;
    int wm = wid & 3, wn = wid >> 2;
    int m0 = blockIdx.y * 128, n0 = blockIdx.x * 64;

    uint32_t smem_u;
    asm("{ .reg .u64 t; cvta.to.shared.u64 t, %1; cvt.u32.u64 %0, t; }"
        : "=r"(smem_u) : "l"(smem));

    int lh = lane >> 4;
    uint32_t aOff[2], bOff[2];
    #pragma unroll
    for (int mt = 0; mt < 2; mt++) {
        int r = wm * 32 + mt * 16 + (lane & 15);
        aOff[mt] = r * 128 + ((lh ^ (r & 7)) << 4);
    }
    #pragma unroll
    for (int np = 0; np < 2; np++) {
        int r = wn * 32 + np * 16 + (lane & 15);
        bOff[np] = 2 * APL + r * 128 + ((lh ^ (r & 7)) << 4);
    }

    float acc[2][4][4];
    #pragma unroll
    for (int i = 0; i < 2; i++)
        #pragma unroll
        for (int j = 0; j < 4; j++)
            #pragma unroll
            for (int k = 0; k < 4; k++) acc[i][j][k] = 0.f;

    int nk = K / 64;

    auto stage_copy = [&](int st, int kt) {
        uint32_t sb = smem_u + st * STG;
        #pragma unroll
        for (int i = 0; i < 4; i++) {
            int chunk = tid + i * 256;
            int row = chunk >> 3, c = chunk & 7;
            size_t goff = (size_t)(m0 + row) * K + kt + c * 8;
            uint32_t d = sb + row * 128 + ((c ^ (row & 7)) << 4);
            cp16(d, Ah + goff, true);
            cp16(d + APL, Al + goff, true);
        }
        #pragma unroll
        for (int i = 0; i < 2; i++) {
            int chunk = tid + i * 256;
            int row = chunk >> 3, c = chunk & 7;
            bool ok = (n0 + row) < N;
            size_t goff = (size_t)(ok ? (n0 + row) : 0) * K + kt + c * 8;
            uint32_t d = sb + 2 * APL + row * 128 + ((c ^ (row & 7)) << 4);
            cp16(d, Bh + goff, ok);
            cp16(d + BPL, Bl + goff, ok);
        }
    };

    stage_copy(0, 0);
    CP_COMMIT();

    for (int it = 0; it < nk; it++) {
        bool more = (it + 1) < nk;
        if (more) {
            stage_copy((it + 1) & 1, (it + 1) * 64);
            CP_COMMIT();
            asm volatile("cp.async.wait_group 1;\n" ::: "memory");
        } else {
            asm volatile("cp.async.wait_group 0;\n" ::: "memory");
        }
        __syncthreads();

        uint32_t sb = smem_u + (it & 1) * STG;
        #pragma unroll
        for (int s = 0; s < 4; s++) {
            uint32_t sx = s << 5;
            uint32_t ah[2][4], al[2][4];
            ldsm4(ah[0], (sb + aOff[0]) ^ sx);
            ldsm4(ah[1], (sb + aOff[1]) ^ sx);
            ldsm4(al[0], (sb + aOff[0] + APL) ^ sx);
            ldsm4(al[1], (sb + aOff[1] + APL) ^ sx);
            uint32_t t0[4], t1[4], u0[4], u1[4];
            ldsm4(t0, (sb + bOff[0]) ^ sx);
            ldsm4(t1, (sb + bOff[1]) ^ sx);
            ldsm4(u0, (sb + bOff[0] + BPL) ^ sx);
            ldsm4(u1, (sb + bOff[1] + BPL) ^ sx);
            uint32_t bh2[4][2] = {{t0[0], t0[2]}, {t0[1], t0[3]}, {t1[0], t1[2]}, {t1[1], t1[3]}};
            uint32_t bl2[4][2] = {{u0[0], u0[2]}, {u0[1], u0[3]}, {u1[0], u1[2]}, {u1[1], u1[3]}};
            #pragma unroll
            for (int mt = 0; mt < 2; mt++)
                #pragma unroll
                for (int nt = 0; nt < 4; nt++) {
                    mma_bf16(acc[mt][nt], ah[mt], bh2[nt]);
                    mma_bf16(acc[mt][nt], ah[mt], bl2[nt]);
                    mma_bf16(acc[mt][nt], al[mt], bh2[nt]);
                }
        }
        __syncthreads();
    }

    if (EPI == 3) {
        // residual + bias, stage into smem, then coalesced transposed store.
        float* sf = (float*)smem;
        #pragma unroll
        for (int mt = 0; mt < 2; mt++) {
            #pragma unroll
            for (int nt = 0; nt < 4; nt++) {
                int mlb = wm * 32 + mt * 16 + (lane >> 2);
                int nlb = wn * 32 + nt * 8 + (lane & 3) * 2;
                #pragma unroll
                for (int e = 0; e < 4; e++) {
                    int ml = mlb + (e >> 1) * 8;
                    int nl = nlb + (e & 1);
                    float v = res[(size_t)(m0 + ml) * N + (n0 + nl)]
                            + acc[mt][nt][e] + bias[n0 + nl];
                    sf[nl * 132 + ml] = v;
                }
            }
        }
        __syncthreads();
        int b = m0 >> 10, tb = m0 & 1023;
        for (int i = tid; i < 64 * 128; i += 256) {
            int nl = i >> 7, ml = i & 127;
            C[(((size_t)b * DIMC + n0 + nl) << 10) + tb + ml] = sf[nl * 132 + ml];
        }
        return;
    }

    #pragma unroll
    for (int mt = 0; mt < 2; mt++) {
        #pragma unroll
        for (int nt = 0; nt < 4; nt++) {
            int rbase = m0 + wm * 32 + mt * 16 + (lane >> 2);
            int cbase = n0 + wn * 32 + nt * 8 + (lane & 3) * 2;
            if (EPI == 2) {
                #pragma unroll
                for (int ep = 0; ep < 2; ep++) {
                    int m = rbase + ep * 8;
                    int n = cbase;
                    float u0 = acc[mt][nt][ep * 2 + 0] + bias[n];
                    float u1 = acc[mt][nt][ep * 2 + 1] + bias[n + 1];
                    float g0 = 0.5f * u0 * (1.f + erff(u0 * 0.70710678118f));
                    float g1 = 0.5f * u1 * (1.f + erff(u1 * 0.70710678118f));
                    uint32_t hp = pack_bf16x2(g0, g1);
                    float h0 = __uint_as_float(hp << 16);
                    float h1 = __uint_as_float(hp & 0xFFFF0000u);
                    uint32_t lp = pack_bf16x2(g0 - h0, g1 - h1);
                    size_t off = ((size_t)m * N + n) >> 1;
                    ((uint32_t*)outH)[off] = hp;
                    ((uint32_t*)outL)[off] = lp;
                }
            } else {
                #pragma unroll
                for (int e = 0; e < 4; e++) {
                    int m = rbase + (e >> 1) * 8;
                    int n = cbase + (e & 1);
                    if (n >= N) continue;
                    float v = acc[mt][nt][e];
                    if (EPI == 0) {
                        C[(size_t)m * N + n] = v;
                    } else { // EPI 1
                        C[(size_t)m * N + n] = res[(size_t)m * N + n] + v;
                    }
                }
            }
        }
    }
}

// ---------------------------------------------------------------------------
extern "C" void kernel_launch(void* const* d_in, const int* in_sizes, int n_in,
                              void* d_out, int out_size) {
    const float* x        = (const float*)d_in[0];
    const float* ln_g     = (const float*)d_in[1];
    const float* ln_b     = (const float*)d_in[2];
    const float* in_proj  = (const float*)d_in[3];
    const float* conv_w   = (const float*)d_in[4];
    const float* conv_b   = (const float*)d_in[5];
    const float* x_proj   = (const float*)d_in[6];
    const float* dt_w     = (const float*)d_in[7];
    const float* dt_b     = (const float*)d_in[8];
    const float* A_log    = (const float*)d_in[9];
    const float* Dp       = (const float*)d_in[10];
    const float* out_proj = (const float*)d_in[11];
    const float* mlp_ln_g = (const float*)d_in[12];
    const float* mlp_ln_b = (const float*)d_in[13];
    const float* mlp_w1   = (const float*)d_in[14];
    const float* mlp_b1   = (const float*)d_in[15];
    const float* mlp_w2   = (const float*)d_in[16];
    const float* mlp_b2   = (const float*)d_in[17];
    float* out = (float*)d_out;

    float *p_dbl, *p_xf, *p_xf2, *p_xz;
    cudaGetSymbolAddress((void**)&p_dbl, g_dbl);
    cudaGetSymbolAddress((void**)&p_xf,  g_xf);
    cudaGetSymbolAddress((void**)&p_xf2, g_xf2);
    cudaGetSymbolAddress((void**)&p_xz,  g_xz);
    __nv_bfloat16 *p_xnh, *p_xnl, *p_xch, *p_xcl, *p_yh, *p_yl, *p_hlnh, *p_hlnl, *p_h1h, *p_h1l;
    cudaGetSymbolAddress((void**)&p_xnh,  g_xnh);
    cudaGetSymbolAddress((void**)&p_xnl,  g_xnl);
    cudaGetSymbolAddress((void**)&p_xch,  g_xch);
    cudaGetSymbolAddress((void**)&p_xcl,  g_xcl);
    cudaGetSymbolAddress((void**)&p_yh,   g_yh);
    cudaGetSymbolAddress((void**)&p_yl,   g_yl);
    cudaGetSymbolAddress((void**)&p_hlnh, g_hlnh);
    cudaGetSymbolAddress((void**)&p_hlnl, g_hlnl);
    cudaGetSymbolAddress((void**)&p_h1h,  g_h1h);
    cudaGetSymbolAddress((void**)&p_h1l,  g_h1l);
    __nv_bfloat16 *p_inh, *p_inl, *p_xph, *p_xpl, *p_oph, *p_opl, *p_m1h, *p_m1l, *p_m2h, *p_m2l;
    cudaGetSymbolAddress((void**)&p_inh, w_inh);
    cudaGetSymbolAddress((void**)&p_inl, w_inl);
    cudaGetSymbolAddress((void**)&p_xph, w_xph);
    cudaGetSymbolAddress((void**)&p_xpl, w_xpl);
    cudaGetSymbolAddress((void**)&p_oph, w_oph);
    cudaGetSymbolAddress((void**)&p_opl, w_opl);
    cudaGetSymbolAddress((void**)&p_m1h, w_m1h);
    cudaGetSymbolAddress((void**)&p_m1l, w_m1l);
    cudaGetSymbolAddress((void**)&p_m2h, w_m2h);
    cudaGetSymbolAddress((void**)&p_m2l, w_m2l);

    const int SMEM = 2 * (2 * 128 * 128 + 2 * 64 * 128);  // 98304
    cudaFuncSetAttribute(gemm_pl<0>, cudaFuncAttributeMaxDynamicSharedMemorySize, SMEM);
    cudaFuncSetAttribute(gemm_pl<1>, cudaFuncAttributeMaxDynamicSharedMemorySize, SMEM);
    cudaFuncSetAttribute(gemm_pl<2>, cudaFuncAttributeMaxDynamicSharedMemorySize, SMEM);
    cudaFuncSetAttribute(gemm_pl<3>, cudaFuncAttributeMaxDynamicSharedMemorySize, SMEM);

    // fused weight split
    wconv_all<<<(WS4 + 255) / 256, 256>>>(in_proj, x_proj, out_proj, mlp_w1, mlp_w2);

    // 1. ln1 (coalesced transpose)
    ln1_kernel<<<256, 256>>>(x, ln_g, ln_b);
    // 2. in_proj (8192 x 1024, K=256)
    gemm_pl<0><<<dim3(1024 / 64, NTOK / 128), 256, SMEM>>>(
        p_xnh, p_xnl, p_inh, p_inl, p_xz, NTOK, 1024, 256, nullptr, nullptr, nullptr, nullptr);
    // 3. conv + silu + gate (tiled)
    conv_silu_kernel<<<dim3(32, 8, 8), 256>>>(conv_w, conv_b);
    // 4. x_proj (8192 x 48, K=512)
    gemm_pl<0><<<dim3(1, NTOK / 128), 256, SMEM>>>(
        p_xch, p_xcl, p_xph, p_xpl, p_dbl, NTOK, 48, 512, nullptr, nullptr, nullptr, nullptr);
    // 5. dt projection -> [b][d][t]
    dt_kernel<<<256, 256>>>(dt_w, dt_b);
    // 6. selective scan (t-contiguous operands)
    scan_kernel<<<128, 128>>>(A_log, Dp);
    // 7. out_proj + residual (8192 x 256, K=512)
    gemm_pl<1><<<dim3(256 / 64, NTOK / 128), 256, SMEM>>>(
        p_yh, p_yl, p_oph, p_opl, p_xf2, NTOK, 256, 512, nullptr, p_xf, nullptr, nullptr);
    // 8. ln2
    ln2_kernel<<<NTOK / 8, 256>>>(mlp_ln_g, mlp_ln_b);
    // 9. mlp1 + gelu -> planar h1 (8192 x 1024, K=256)
    gemm_pl<2><<<dim3(1024 / 64, NTOK / 128), 256, SMEM>>>(
        p_hlnh, p_hlnl, p_m1h, p_m1l, nullptr, NTOK, 1024, 256, mlp_b1, nullptr, p_h1h, p_h1l);
    // 10. mlp2 + residual + transposed store (8192 x 256, K=1024)
    gemm_pl<3><<<dim3(256 / 64, NTOK / 128), 256, SMEM>>>(
        p_h1h, p_h1l, p_m2h, p_m2l, out, NTOK, 256, 1024, mlp_b2, p_xf2, nullptr, nullptr);
}

// round 11
// speedup vs baseline: 3.4100x; 1.3012x over previous
#include <cuda_runtime.h>
#include <cuda_bf16.h>
#include <cuda_fp16.h>
#include <math.h>
#include <stdint.h>

// ---------------------------------------------------------------------------
// OptimizedMambaBlock: B=8, DIM=256, H=W=32 -> L=1024, tokens N=8192
// R11: legacy mma.sync pipeline (tcgen05 unavailable: build emits compute_103
// PTX). KIND=0: bf16 hi/lo 3-pass (scan-feeding GEMMs). KIND=1: fp16
// single-pass (residual-diluted GEMMs: out_proj, mlp1, mlp2).
// ---------------------------------------------------------------------------

#define NTOK   8192
#define LSEQ   1024
#define DIMC   256
#define DINNER 512

// fp32 scratch
__device__ float g_xf [NTOK * DIMC];
__device__ float g_xz [NTOK * 1024];
__device__ float g_dbl[NTOK * 48];
__device__ float g_xf2[NTOK * DIMC];
// scan-layout operands [b][d][t]
__device__ float g_uT [8 * DINNER * LSEQ];
__device__ float g_gT [8 * DINNER * LSEQ];
__device__ float g_dtT[8 * DINNER * LSEQ];

// bf16 hi/lo activations (scan-feeding path)
__device__ __nv_bfloat16 g_xnh[NTOK * DIMC],   g_xnl[NTOK * DIMC];
__device__ __nv_bfloat16 g_xch[NTOK * DINNER], g_xcl[NTOK * DINNER];
// fp16 single-plane activations
__device__ __half g_y16  [NTOK * DINNER];
__device__ __half g_hln16[NTOK * DIMC];
__device__ __half g_h116 [NTOK * 1024];

// weights
__device__ __nv_bfloat16 w_inh[1024 * 256], w_inl[1024 * 256];
__device__ __nv_bfloat16 w_xph[48 * 512],   w_xpl[48 * 512];
__device__ __half w_op16[256 * 512];
__device__ __half w_m116[1024 * 256];
__device__ __half w_m216[256 * 1024];

// ---------------------------------------------------------------------------
// fused weight split
// ---------------------------------------------------------------------------
#define WS0 262144            // in_proj (bf16 hi/lo)
#define WS1 (WS0 + 24576)     // x_proj (bf16 hi/lo)
#define WS2 (WS1 + 131072)    // out_proj (fp16)
#define WS3 (WS2 + 262144)    // mlp_w1 (fp16)
#define WS4 (WS3 + 262144)    // mlp_w2 (fp16)
__global__ void wconv_all(const float* __restrict__ w_in, const float* __restrict__ w_xp,
                          const float* __restrict__ w_op, const float* __restrict__ w_m1,
                          const float* __restrict__ w_m2) {
    int i = blockIdx.x * 256 + threadIdx.x;
    if (i < WS1) {
        const float* src; __nv_bfloat16 *dh, *dl; int off;
        if (i < WS0) { src = w_in; dh = w_inh; dl = w_inl; off = i; }
        else         { src = w_xp; dh = w_xph; dl = w_xpl; off = i - WS0; }
        float f = src[off];
        __nv_bfloat16 h = __float2bfloat16(f);
        dh[off] = h;
        dl[off] = __float2bfloat16(f - __bfloat162float(h));
    } else if (i < WS4) {
        const float* src; __half* dh; int off;
        if      (i < WS2) { src = w_op; dh = w_op16; off = i - WS1; }
        else if (i < WS3) { src = w_m1; dh = w_m116; off = i - WS2; }
        else              { src = w_m2; dh = w_m216; off = i - WS3; }
        dh[off] = __float2half_rn(src[off]);
    }
}

// ---------------------------------------------------------------------------
// LN1: coalesced smem-transpose
// ---------------------------------------------------------------------------
__global__ void ln1_kernel(const float* __restrict__ x,
                           const float* __restrict__ g,
                           const float* __restrict__ bta) {
    __shared__ float xs[32][257];
    int tid = threadIdx.x, lane = tid & 31, w = tid >> 5;
    int b = blockIdx.x >> 5, tb = blockIdx.x & 31;
    #pragma unroll 8
    for (int j = 0; j < 32; j++) {
        int c = w * 32 + j;
        xs[lane][c] = x[(((size_t)b * DIMC + c) << 10) + tb * 32 + lane];
    }
    __syncthreads();
    for (int q = 0; q < 4; q++) {
        int tt = w * 4 + q;
        float v[8], s = 0.f, sq = 0.f;
        #pragma unroll
        for (int k = 0; k < 8; k++) {
            v[k] = xs[tt][lane + k * 32];
            s += v[k]; sq += v[k] * v[k];
        }
        #pragma unroll
        for (int o = 16; o; o >>= 1) {
            s  += __shfl_xor_sync(~0u, s, o);
            sq += __shfl_xor_sync(~0u, sq, o);
        }
        float mean = s * (1.f / 256.f);
        float var  = sq * (1.f / 256.f) - mean * mean;
        float rs = rsqrtf(var + 1e-5f);
        size_t base = (size_t)(b * 1024 + tb * 32 + tt) * DIMC;
        #pragma unroll
        for (int k = 0; k < 8; k++) {
            int c = lane + k * 32;
            g_xf[base + c] = v[k];
            float xn = (v[k] - mean) * rs * g[c] + bta[c];
            __nv_bfloat16 h = __float2bfloat16(xn);
            g_xnh[base + c] = h;
            g_xnl[base + c] = __float2bfloat16(xn - __bfloat162float(h));
        }
    }
}

// ---------------------------------------------------------------------------
// LN2: fp32 in, fp16 out
// ---------------------------------------------------------------------------
__global__ void ln2_kernel(const float* __restrict__ g,
                           const float* __restrict__ bta) {
    int token = (blockIdx.x * blockDim.x + threadIdx.x) >> 5;
    int lane = threadIdx.x & 31;
    const float* row = g_xf2 + (size_t)token * DIMC;
    float4 a = *(const float4*)(row + lane * 4);
    float4 c4 = *(const float4*)(row + 128 + lane * 4);
    float s = a.x + a.y + a.z + a.w + c4.x + c4.y + c4.z + c4.w;
    float q = a.x*a.x + a.y*a.y + a.z*a.z + a.w*a.w
            + c4.x*c4.x + c4.y*c4.y + c4.z*c4.z + c4.w*c4.w;
    #pragma unroll
    for (int o = 16; o; o >>= 1) {
        s += __shfl_xor_sync(~0u, s, o);
        q += __shfl_xor_sync(~0u, q, o);
    }
    float mean = s * (1.f / 256.f);
    float var  = q * (1.f / 256.f) - mean * mean;
    float rs = rsqrtf(var + 1e-5f);
    float va[8] = { a.x, a.y, a.z, a.w, c4.x, c4.y, c4.z, c4.w };
    size_t base = (size_t)token * DIMC;
    #pragma unroll
    for (int h = 0; h < 2; h++) {
        #pragma unroll
        for (int i = 0; i < 4; i++) {
            int c = h * 128 + lane * 4 + i;
            float u = (va[h * 4 + i] - mean) * rs * g[c] + bta[c];
            g_hln16[base + c] = __float2half_rn(u);
        }
    }
}

// ---------------------------------------------------------------------------
// conv + silu + gate (tiled)
// ---------------------------------------------------------------------------
__global__ void conv_silu_kernel(const float* __restrict__ cw,
                                 const float* __restrict__ cb) {
    __shared__ float xs[35][64];
    __shared__ float zs[32][64];
    __shared__ float us[32][65];
    __shared__ float gs[32][65];
    int b = blockIdx.z, d0 = blockIdx.y * 64, t0 = blockIdx.x * 32;
    int tid = threadIdx.x;

    for (int i = tid; i < 35 * 64; i += 256) {
        int tt = i >> 6, dd = i & 63;
        int t = t0 - 3 + tt;
        xs[tt][dd] = (t >= 0) ? g_xz[((size_t)(b * 1024 + t) << 10) + d0 + dd] : 0.f;
    }
    for (int i = tid; i < 32 * 64; i += 256) {
        int tt = i >> 6, dd = i & 63;
        zs[tt][dd] = g_xz[((size_t)(b * 1024 + t0 + tt) << 10) + 512 + d0 + dd];
    }
    __syncthreads();

    for (int i = tid; i < 32 * 64; i += 256) {
        int tt = i >> 6, dd = i & 63;
        int d = d0 + dd;
        float acc = cb[d];
        #pragma unroll
        for (int j = 0; j < 4; j++)
            acc += xs[tt + j][dd] * cw[d * 4 + j];
        us[tt][dd] = acc / (1.f + __expf(-acc));
        float z = zs[tt][dd];
        gs[tt][dd] = z / (1.f + __expf(-z));
    }
    __syncthreads();

    {
        int tt = tid & 31, dgrp = tid >> 5;
        #pragma unroll
        for (int k = 0; k < 8; k++) {
            int dd = dgrp * 8 + k;
            size_t o = ((size_t)(b * DINNER + d0 + dd) << 10) + t0 + tt;
            g_uT[o] = us[tt][dd];
            g_gT[o] = gs[tt][dd];
        }
    }
    {
        int dd = tid & 63, tq = tid >> 6;
        #pragma unroll
        for (int k = 0; k < 8; k++) {
            int tt = k * 4 + tq;
            float u = us[tt][dd];
            __nv_bfloat16 h = __float2bfloat16(u);
            size_t o = (size_t)(b * 1024 + t0 + tt) * DINNER + d0 + dd;
            g_xch[o] = h;
            g_xcl[o] = __float2bfloat16(u - __bfloat162float(h));
        }
    }
}

// ---------------------------------------------------------------------------
// dt projection + softplus -> g_dtT [b][d][t]
// ---------------------------------------------------------------------------
__global__ void dt_kernel(const float* __restrict__ dtw,
                          const float* __restrict__ dtb) {
    __shared__ float swT[16][512];
    __shared__ float db[32][17];
    int tid = threadIdx.x, lane = tid & 31, w = tid >> 5;
    int b = blockIdx.x >> 5, t0 = (blockIdx.x & 31) * 32;
    for (int i = tid; i < 16 * 512; i += 256) {
        int dd = i >> 4, r = i & 15;
        swT[r][dd] = dtw[i];
    }
    for (int i = tid; i < 512; i += 256) {
        int tt = i >> 4, r = i & 15;
        db[tt][r] = g_dbl[(size_t)(b * 1024 + t0 + tt) * 48 + r];
    }
    __syncthreads();
    float drow[16];
    #pragma unroll
    for (int r = 0; r < 16; r++) drow[r] = db[lane][r];
    for (int dd = 0; dd < 64; dd++) {
        int d = w * 64 + dd;
        float acc = dtb[d];
        #pragma unroll
        for (int r = 0; r < 16; r++)
            acc += drow[r] * swT[r][d];
        float sp = (acc > 20.f) ? acc : log1pf(__expf(acc));
        g_dtT[((size_t)(b * DINNER + d) << 10) + t0 + lane] = sp;
    }
}

// ---------------------------------------------------------------------------
// selective scan + gating -> fp16 y
// ---------------------------------------------------------------------------
__global__ void scan_kernel(const float* __restrict__ A_log,
                            const float* __restrict__ Dp) {
    int tid = threadIdx.x;
    int b  = blockIdx.x >> 4;
    int d  = ((blockIdx.x & 15) << 5) + (tid >> 2);
    int sq = tid & 3;

    float Al[4], h[4];
    #pragma unroll
    for (int j = 0; j < 4; j++) {
        Al[j] = -__expf(A_log[d * 16 + sq * 4 + j]) * 1.44269504f;
        h[j] = 0.f;
    }
    float dpv = Dp[d];

    const float* dtp  = g_dtT + ((size_t)(b * DINNER + d) << 10);
    const float* up   = g_uT  + ((size_t)(b * DINNER + d) << 10);
    const float* gp   = g_gT  + ((size_t)(b * DINNER + d) << 10);
    const float* dblp = g_dbl + (size_t)b * LSEQ * 48;
    size_t ybase = (size_t)b * LSEQ * DINNER + d;

    float  dt_n = dtp[0];
    float  u_n  = up[0];
    float4 Bv_n = *(const float4*)(dblp + 16 + sq * 4);
    float4 Cv_n = *(const float4*)(dblp + 32 + sq * 4);
    float  g_n  = (sq == 0) ? gp[0] : 0.f;

    for (int t = 0; t < LSEQ; t++) {
        float  dt = dt_n;
        float  u  = u_n;
        float4 Bv = Bv_n;
        float4 Cv = Cv_n;
        float  gate = g_n;
        if (t + 1 < LSEQ) {
            dt_n = dtp[t + 1];
            u_n  = up[t + 1];
            Bv_n = *(const float4*)(dblp + (size_t)(t + 1) * 48 + 16 + sq * 4);
            Cv_n = *(const float4*)(dblp + (size_t)(t + 1) * 48 + 32 + sq * 4);
            if (sq == 0) g_n = gp[t + 1];
        }
        float dtu = dt * u;
        float y = 0.f;
        h[0] = exp2f(dt * Al[0]) * h[0] + dtu * Bv.x; y += h[0] * Cv.x;
        h[1] = exp2f(dt * Al[1]) * h[1] + dtu * Bv.y; y += h[1] * Cv.y;
        h[2] = exp2f(dt * Al[2]) * h[2] + dtu * Bv.z; y += h[2] * Cv.z;
        h[3] = exp2f(dt * Al[3]) * h[3] + dtu * Bv.w; y += h[3] * Cv.w;
        y += __shfl_xor_sync(~0u, y, 1);
        y += __shfl_xor_sync(~0u, y, 2);
        if (sq == 0) {
            float v = (y + u * dpv) * gate;
            g_y16[ybase + (size_t)t * DINNER] = __float2half_rn(v);
        }
    }
}

// ---------------------------------------------------------------------------
// GEMM helpers
// ---------------------------------------------------------------------------
__device__ __forceinline__ uint32_t pack_bf16x2(float e, float o) {
    uint32_t d;
    asm("cvt.rn.bf16x2.f32 %0, %1, %2;" : "=r"(d) : "f"(o), "f"(e));
    return d;
}
__device__ __forceinline__ uint32_t pack_f16x2(float e, float o) {
    uint32_t d;
    asm("cvt.rn.f16x2.f32 %0, %1, %2;" : "=r"(d) : "f"(o), "f"(e));
    return d;
}

__device__ __forceinline__ void ldsm4(uint32_t r[4], uint32_t addr) {
    asm volatile("ldmatrix.sync.aligned.m8n8.x4.shared.b16 {%0,%1,%2,%3}, [%4];"
                 : "=r"(r[0]), "=r"(r[1]), "=r"(r[2]), "=r"(r[3]) : "r"(addr));
}

__device__ __forceinline__ void mma_bf16(float* c, const uint32_t* a, const uint32_t* b) {
    asm volatile(
        "mma.sync.aligned.m16n8k16.row.col.f32.bf16.bf16.f32 "
        "{%0,%1,%2,%3}, {%4,%5,%6,%7}, {%8,%9}, {%0,%1,%2,%3};\n"
        : "+f"(c[0]), "+f"(c[1]), "+f"(c[2]), "+f"(c[3])
        : "r"(a[0]), "r"(a[1]), "r"(a[2]), "r"(a[3]), "r"(b[0]), "r"(b[1]));
}
__device__ __forceinline__ void mma_f16(float* c, const uint32_t* a, const uint32_t* b) {
    asm volatile(
        "mma.sync.aligned.m16n8k16.row.col.f32.f16.f16.f32 "
        "{%0,%1,%2,%3}, {%4,%5,%6,%7}, {%8,%9}, {%0,%1,%2,%3};\n"
        : "+f"(c[0]), "+f"(c[1]), "+f"(c[2]), "+f"(c[3])
        : "r"(a[0]), "r"(a[1]), "r"(a[2]), "r"(a[3]), "r"(b[0]), "r"(b[1]));
}

__device__ __forceinline__ void cp16(uint32_t dst, const void* src, bool ok) {
    int sz = ok ? 16 : 0;
    asm volatile("cp.async.cg.shared.global [%0], [%1], 16, %2;\n"
                 :: "r"(dst), "l"(src), "r"(sz));
}
#define CP_COMMIT() asm volatile("cp.async.commit_group;\n" ::: "memory")

// ---------------------------------------------------------------------------
// GEMM (NT), cp.async 2-stage, BM=128 BN=64 BK=64, 256 thr, 8 warps 4x2.
// KIND 0: bf16 hi/lo 3-pass (planar). KIND 1: fp16 single-pass.
// EPI: 0 fp32 | 1 +res | 2 gelu+bias -> fp16 | 3 res+bias, smem-transposed
// ---------------------------------------------------------------------------
template <int EPI, int KIND>
__global__ void __launch_bounds__(256, 2)
gemm_mix(const uint16_t* __restrict__ Ah, const uint16_t* __restrict__ Al,
         const uint16_t* __restrict__ Bh, const uint16_t* __restrict__ Bl,
         float* __restrict__ C, int M, int N, int K,
         const float* __restrict__ bias, const float* __restrict__ res,
         uint16_t* __restrict__ outO) {
    const int APL = 128 * 128;                       // bytes per A plane
    const int BPL = 64 * 128;                        // bytes per B plane
    const int NPLANE = (KIND == 0) ? 2 : 1;
    const int STG = NPLANE * (APL + BPL);            // bytes per stage
    extern __shared__ __align__(1024) unsigned char smem[];

    int tid = threadIdx.x;
    int lane = tid & 31, wid = tid >> 5;
    int wm = wid & 3, wn = wid >> 2;
    int m0 = blockIdx.y * 128, n0 = blockIdx.x * 64;

    uint32_t smem_u;
    asm("{ .reg .u64 t; cvta.to.shared.u64 t, %1; cvt.u32.u64 %0, t; }"
        : "=r"(smem_u) : "l"(smem));

    int lh = lane >> 4;
    uint32_t aOff[2], bOff[2];
    #pragma unroll
    for (int mt = 0; mt < 2; mt++) {
        int r = wm * 32 + mt * 16 + (lane & 15);
        aOff[mt] = r * 128 + ((lh ^ (r & 7)) << 4);
    }
    #pragma unroll
    for (int np = 0; np < 2; np++) {
        int r = wn * 32 + np * 16 + (lane & 15);
        bOff[np] = NPLANE * APL + r * 128 + ((lh ^ (r & 7)) << 4);
    }

    float acc[2][4][4];
    #pragma unroll
    for (int i = 0; i < 2; i++)
        #pragma unroll
        for (int j = 0; j < 4; j++)
            #pragma unroll
            for (int k = 0; k < 4; k++) acc[i][j][k] = 0.f;

    int nk = K / 64;

    auto stage_copy = [&](int st, int kt) {
        uint32_t sb = smem_u + st * STG;
        #pragma unroll
        for (int i = 0; i < 4; i++) {
            int chunk = tid + i * 256;
            int row = chunk >> 3, c = chunk & 7;
            size_t goff = (size_t)(m0 + row) * K + kt + c * 8;
            uint32_t d = sb + row * 128 + ((c ^ (row & 7)) << 4);
            cp16(d, Ah + goff, true);
            if (KIND == 0) cp16(d + APL, Al + goff, true);
        }
        #pragma unroll
        for (int i = 0; i < 2; i++) {
            int chunk = tid + i * 256;
            int row = chunk >> 3, c = chunk & 7;
            bool ok = (n0 + row) < N;
            size_t goff = (size_t)(ok ? (n0 + row) : 0) * K + kt + c * 8;
            uint32_t d = sb + NPLANE * APL + row * 128 + ((c ^ (row & 7)) << 4);
            cp16(d, Bh + goff, ok);
            if (KIND == 0) cp16(d + BPL, Bl + goff, ok);
        }
    };

    stage_copy(0, 0);
    CP_COMMIT();

    for (int it = 0; it < nk; it++) {
        bool more = (it + 1) < nk;
        if (more) {
            stage_copy((it + 1) & 1, (it + 1) * 64);
            CP_COMMIT();
            asm volatile("cp.async.wait_group 1;\n" ::: "memory");
        } else {
            asm volatile("cp.async.wait_group 0;\n" ::: "memory");
        }
        __syncthreads();

        uint32_t sb = smem_u + (it & 1) * STG;
        #pragma unroll
        for (int s = 0; s < 4; s++) {
            uint32_t sx = s << 5;
            if (KIND == 0) {
                uint32_t ah[2][4], al[2][4];
                ldsm4(ah[0], (sb + aOff[0]) ^ sx);
                ldsm4(ah[1], (sb + aOff[1]) ^ sx);
                ldsm4(al[0], (sb + aOff[0] + APL) ^ sx);
                ldsm4(al[1], (sb + aOff[1] + APL) ^ sx);
                uint32_t t0[4], t1[4], u0[4], u1[4];
                ldsm4(t0, (sb + bOff[0]) ^ sx);
                ldsm4(t1, (sb + bOff[1]) ^ sx);
                ldsm4(u0, (sb + bOff[0] + BPL) ^ sx);
                ldsm4(u1, (sb + bOff[1] + BPL) ^ sx);
                uint32_t bh2[4][2] = {{t0[0], t0[2]}, {t0[1], t0[3]}, {t1[0], t1[2]}, {t1[1], t1[3]}};
                uint32_t bl2[4][2] = {{u0[0], u0[2]}, {u0[1], u0[3]}, {u1[0], u1[2]}, {u1[1], u1[3]}};
                #pragma unroll
                for (int mt = 0; mt < 2; mt++)
                    #pragma unroll
                    for (int nt = 0; nt < 4; nt++) {
                        mma_bf16(acc[mt][nt], ah[mt], bh2[nt]);
                        mma_bf16(acc[mt][nt], ah[mt], bl2[nt]);
                        mma_bf16(acc[mt][nt], al[mt], bh2[nt]);
                    }
            } else {
                uint32_t ah[2][4];
                ldsm4(ah[0], (sb + aOff[0]) ^ sx);
                ldsm4(ah[1], (sb + aOff[1]) ^ sx);
                uint32_t t0[4], t1[4];
                ldsm4(t0, (sb + bOff[0]) ^ sx);
                ldsm4(t1, (sb + bOff[1]) ^ sx);
                uint32_t bh2[4][2] = {{t0[0], t0[2]}, {t0[1], t0[3]}, {t1[0], t1[2]}, {t1[1], t1[3]}};
                #pragma unroll
                for (int mt = 0; mt < 2; mt++)
                    #pragma unroll
                    for (int nt = 0; nt < 4; nt++)
                        mma_f16(acc[mt][nt], ah[mt], bh2[nt]);
            }
        }
        __syncthreads();
    }

    if (EPI == 3) {
        float* sf = (float*)smem;
        #pragma unroll
        for (int mt = 0; mt < 2; mt++) {
            #pragma unroll
            for (int nt = 0; nt < 4; nt++) {
                int mlb = wm * 32 + mt * 16 + (lane >> 2);
                int nlb = wn * 32 + nt * 8 + (lane & 3) * 2;
                #pragma unroll
                for (int e = 0; e < 4; e++) {
                    int ml = mlb + (e >> 1) * 8;
                    int nl = nlb + (e & 1);
                    float v = res[(size_t)(m0 + ml) * N + (n0 + nl)]
                            + acc[mt][nt][e] + bias[n0 + nl];
                    sf[nl * 132 + ml] = v;
                }
            }
        }
        __syncthreads();
        int b = m0 >> 10, tb = m0 & 1023;
        for (int i = tid; i < 64 * 128; i += 256) {
            int nl = i >> 7, ml = i & 127;
            C[(((size_t)b * DIMC + n0 + nl) << 10) + tb + ml] = sf[nl * 132 + ml];
        }
        return;
    }

    #pragma unroll
    for (int mt = 0; mt < 2; mt++) {
        #pragma unroll
        for (int nt = 0; nt < 4; nt++) {
            int rbase = m0 + wm * 32 + mt * 16 + (lane >> 2);
            int cbase = n0 + wn * 32 + nt * 8 + (lane & 3) * 2;
            if (EPI == 2) {
                #pragma unroll
                for (int ep = 0; ep < 2; ep++) {
                    int m = rbase + ep * 8;
                    int n = cbase;
                    float u0 = acc[mt][nt][ep * 2 + 0] + bias[n];
                    float u1 = acc[mt][nt][ep * 2 + 1] + bias[n + 1];
                    float g0 = 0.5f * u0 * (1.f + erff(u0 * 0.70710678118f));
                    float g1 = 0.5f * u1 * (1.f + erff(u1 * 0.70710678118f));
                    ((uint32_t*)outO)[((size_t)m * N + n) >> 1] = pack_f16x2(g0, g1);
                }
            } else {
                #pragma unroll
                for (int e = 0; e < 4; e++) {
                    int m = rbase + (e >> 1) * 8;
                    int n = cbase + (e & 1);
                    if (n >= N) continue;
                    float v = acc[mt][nt][e];
                    if (EPI == 0) {
                        C[(size_t)m * N + n] = v;
                    } else { // EPI 1
                        C[(size_t)m * N + n] = res[(size_t)m * N + n] + v;
                    }
                }
            }
        }
    }
}

// ---------------------------------------------------------------------------
extern "C" void kernel_launch(void* const* d_in, const int* in_sizes, int n_in,
                              void* d_out, int out_size) {
    const float* x        = (const float*)d_in[0];
    const float* ln_g     = (const float*)d_in[1];
    const float* ln_b     = (const float*)d_in[2];
    const float* in_proj  = (const float*)d_in[3];
    const float* conv_w   = (const float*)d_in[4];
    const float* conv_b   = (const float*)d_in[5];
    const float* x_proj   = (const float*)d_in[6];
    const float* dt_w     = (const float*)d_in[7];
    const float* dt_b     = (const float*)d_in[8];
    const float* A_log    = (const float*)d_in[9];
    const float* Dp       = (const float*)d_in[10];
    const float* out_proj = (const float*)d_in[11];
    const float* mlp_ln_g = (const float*)d_in[12];
    const float* mlp_ln_b = (const float*)d_in[13];
    const float* mlp_w1   = (const float*)d_in[14];
    const float* mlp_b1   = (const float*)d_in[15];
    const float* mlp_w2   = (const float*)d_in[16];
    const float* mlp_b2   = (const float*)d_in[17];
    float* out = (float*)d_out;

    float *p_dbl, *p_xf, *p_xf2, *p_xz;
    cudaGetSymbolAddress((void**)&p_dbl, g_dbl);
    cudaGetSymbolAddress((void**)&p_xf,  g_xf);
    cudaGetSymbolAddress((void**)&p_xf2, g_xf2);
    cudaGetSymbolAddress((void**)&p_xz,  g_xz);
    uint16_t *p_xnh, *p_xnl, *p_xch, *p_xcl, *p_y16, *p_hln16, *p_h116;
    cudaGetSymbolAddress((void**)&p_xnh,   g_xnh);
    cudaGetSymbolAddress((void**)&p_xnl,   g_xnl);
    cudaGetSymbolAddress((void**)&p_xch,   g_xch);
    cudaGetSymbolAddress((void**)&p_xcl,   g_xcl);
    cudaGetSymbolAddress((void**)&p_y16,   g_y16);
    cudaGetSymbolAddress((void**)&p_hln16, g_hln16);
    cudaGetSymbolAddress((void**)&p_h116,  g_h116);
    uint16_t *p_inh, *p_inl, *p_xph, *p_xpl, *p_op16, *p_m116, *p_m216;
    cudaGetSymbolAddress((void**)&p_inh,  w_inh);
    cudaGetSymbolAddress((void**)&p_inl,  w_inl);
    cudaGetSymbolAddress((void**)&p_xph,  w_xph);
    cudaGetSymbolAddress((void**)&p_xpl,  w_xpl);
    cudaGetSymbolAddress((void**)&p_op16, w_op16);
    cudaGetSymbolAddress((void**)&p_m116, w_m116);
    cudaGetSymbolAddress((void**)&p_m216, w_m216);

    const int SMEM3 = 2 * 2 * (128 * 128 + 64 * 128);   // 98304 (bf16 3-pass)
    const int SMEM1 = 2 * (128 * 128 + 64 * 128);       // 49152 (fp16 1-pass)
    cudaFuncSetAttribute(gemm_mix<0, 0>, cudaFuncAttributeMaxDynamicSharedMemorySize, SMEM3);
    cudaFuncSetAttribute(gemm_mix<1, 1>, cudaFuncAttributeMaxDynamicSharedMemorySize, SMEM1);
    cudaFuncSetAttribute(gemm_mix<2, 1>, cudaFuncAttributeMaxDynamicSharedMemorySize, SMEM1);
    cudaFuncSetAttribute(gemm_mix<3, 1>, cudaFuncAttributeMaxDynamicSharedMemorySize, SMEM1);

    // fused weight split
    wconv_all<<<(WS4 + 255) / 256, 256>>>(in_proj, x_proj, out_proj, mlp_w1, mlp_w2);

    // 1. ln1
    ln1_kernel<<<256, 256>>>(x, ln_g, ln_b);
    // 2. in_proj (8192 x 1024, K=256) bf16 3-pass
    gemm_mix<0, 0><<<dim3(16, 64), 256, SMEM3>>>(
        p_xnh, p_xnl, p_inh, p_inl, p_xz, NTOK, 1024, 256, nullptr, nullptr, nullptr);
    // 3. conv + silu + gate
    conv_silu_kernel<<<dim3(32, 8, 8), 256>>>(conv_w, conv_b);
    // 4. x_proj (8192 x 48, K=512) bf16 3-pass
    gemm_mix<0, 0><<<dim3(1, 64), 256, SMEM3>>>(
        p_xch, p_xcl, p_xph, p_xpl, p_dbl, NTOK, 48, 512, nullptr, nullptr, nullptr);
    // 5. dt projection
    dt_kernel<<<256, 256>>>(dt_w, dt_b);
    // 6. selective scan
    scan_kernel<<<128, 128>>>(A_log, Dp);
    // 7. out_proj + residual (8192 x 256, K=512) fp16 1-pass
    gemm_mix<1, 1><<<dim3(4, 64), 256, SMEM1>>>(
        p_y16, nullptr, p_op16, nullptr, p_xf2, NTOK, 256, 512, nullptr, p_xf, nullptr);
    // 8. ln2
    ln2_kernel<<<NTOK / 8, 256>>>(mlp_ln_g, mlp_ln_b);
    // 9. mlp1 + gelu -> fp16 h1 (8192 x 1024, K=256) fp16 1-pass
    gemm_mix<2, 1><<<dim3(16, 64), 256, SMEM1>>>(
        p_hln16, nullptr, p_m116, nullptr, nullptr, NTOK, 1024, 256, mlp_b1, nullptr, p_h116);
    // 10. mlp2 + residual + transposed store (8192 x 256, K=1024) fp16 1-pass
    gemm_mix<3, 1><<<dim3(4, 64), 256, SMEM1>>>(
        p_h116, nullptr, p_m216, nullptr, out, NTOK, 256, 1024, mlp_b2, p_xf2, nullptr);
}

// round 12
// speedup vs baseline: 3.5882x; 1.0523x over previous
#include <cuda_runtime.h>
#include <cuda_bf16.h>
#include <cuda_fp16.h>
#include <math.h>
#include <stdint.h>

// ---------------------------------------------------------------------------
// OptimizedMambaBlock: B=8, DIM=256, H=W=32 -> L=1024, tokens N=8192
// R12: in_proj moves to fp16 single-pass (error diluted through scan branch);
// x_proj stays bf16 hi/lo 3-pass. Rest as R11.
// ---------------------------------------------------------------------------

#define NTOK   8192
#define LSEQ   1024
#define DIMC   256
#define DINNER 512

// fp32 scratch
__device__ float g_xf [NTOK * DIMC];
__device__ float g_xz [NTOK * 1024];
__device__ float g_dbl[NTOK * 48];
__device__ float g_xf2[NTOK * DIMC];
// scan-layout operands [b][d][t]
__device__ float g_uT [8 * DINNER * LSEQ];
__device__ float g_gT [8 * DINNER * LSEQ];
__device__ float g_dtT[8 * DINNER * LSEQ];

// fp16 activations
__device__ __half g_xn16 [NTOK * DIMC];
__device__ __half g_y16  [NTOK * DINNER];
__device__ __half g_hln16[NTOK * DIMC];
__device__ __half g_h116 [NTOK * 1024];
// bf16 hi/lo activations (x_proj path)
__device__ __nv_bfloat16 g_xch[NTOK * DINNER], g_xcl[NTOK * DINNER];

// weights
__device__ __half w_in16[1024 * 256];
__device__ __nv_bfloat16 w_xph[48 * 512], w_xpl[48 * 512];
__device__ __half w_op16[256 * 512];
__device__ __half w_m116[1024 * 256];
__device__ __half w_m216[256 * 1024];

// ---------------------------------------------------------------------------
// fused weight split
// ---------------------------------------------------------------------------
#define WS0 262144            // in_proj (fp16)
#define WS1 (WS0 + 24576)     // x_proj (bf16 hi/lo)
#define WS2 (WS1 + 131072)    // out_proj (fp16)
#define WS3 (WS2 + 262144)    // mlp_w1 (fp16)
#define WS4 (WS3 + 262144)    // mlp_w2 (fp16)
__global__ void wconv_all(const float* __restrict__ w_in, const float* __restrict__ w_xp,
                          const float* __restrict__ w_op, const float* __restrict__ w_m1,
                          const float* __restrict__ w_m2) {
    int i = blockIdx.x * 256 + threadIdx.x;
    if (i < WS0) {
        w_in16[i] = __float2half_rn(w_in[i]);
    } else if (i < WS1) {
        int off = i - WS0;
        float f = w_xp[off];
        __nv_bfloat16 h = __float2bfloat16(f);
        w_xph[off] = h;
        w_xpl[off] = __float2bfloat16(f - __bfloat162float(h));
    } else if (i < WS4) {
        const float* src; __half* dh; int off;
        if      (i < WS2) { src = w_op; dh = w_op16; off = i - WS1; }
        else if (i < WS3) { src = w_m1; dh = w_m116; off = i - WS2; }
        else              { src = w_m2; dh = w_m216; off = i - WS3; }
        dh[off] = __float2half_rn(src[off]);
    }
}

// ---------------------------------------------------------------------------
// LN1: coalesced smem-transpose; fp32 residual + fp16 normed
// ---------------------------------------------------------------------------
__global__ void ln1_kernel(const float* __restrict__ x,
                           const float* __restrict__ g,
                           const float* __restrict__ bta) {
    __shared__ float xs[32][257];
    int tid = threadIdx.x, lane = tid & 31, w = tid >> 5;
    int b = blockIdx.x >> 5, tb = blockIdx.x & 31;
    #pragma unroll 8
    for (int j = 0; j < 32; j++) {
        int c = w * 32 + j;
        xs[lane][c] = x[(((size_t)b * DIMC + c) << 10) + tb * 32 + lane];
    }
    __syncthreads();
    for (int q = 0; q < 4; q++) {
        int tt = w * 4 + q;
        float v[8], s = 0.f, sq = 0.f;
        #pragma unroll
        for (int k = 0; k < 8; k++) {
            v[k] = xs[tt][lane + k * 32];
            s += v[k]; sq += v[k] * v[k];
        }
        #pragma unroll
        for (int o = 16; o; o >>= 1) {
            s  += __shfl_xor_sync(~0u, s, o);
            sq += __shfl_xor_sync(~0u, sq, o);
        }
        float mean = s * (1.f / 256.f);
        float var  = sq * (1.f / 256.f) - mean * mean;
        float rs = rsqrtf(var + 1e-5f);
        size_t base = (size_t)(b * 1024 + tb * 32 + tt) * DIMC;
        #pragma unroll
        for (int k = 0; k < 8; k++) {
            int c = lane + k * 32;
            g_xf[base + c] = v[k];
            float xn = (v[k] - mean) * rs * g[c] + bta[c];
            g_xn16[base + c] = __float2half_rn(xn);
        }
    }
}

// ---------------------------------------------------------------------------
// LN2: fp32 in, fp16 out
// ---------------------------------------------------------------------------
__global__ void ln2_kernel(const float* __restrict__ g,
                           const float* __restrict__ bta) {
    int token = (blockIdx.x * blockDim.x + threadIdx.x) >> 5;
    int lane = threadIdx.x & 31;
    const float* row = g_xf2 + (size_t)token * DIMC;
    float4 a = *(const float4*)(row + lane * 4);
    float4 c4 = *(const float4*)(row + 128 + lane * 4);
    float s = a.x + a.y + a.z + a.w + c4.x + c4.y + c4.z + c4.w;
    float q = a.x*a.x + a.y*a.y + a.z*a.z + a.w*a.w
            + c4.x*c4.x + c4.y*c4.y + c4.z*c4.z + c4.w*c4.w;
    #pragma unroll
    for (int o = 16; o; o >>= 1) {
        s += __shfl_xor_sync(~0u, s, o);
        q += __shfl_xor_sync(~0u, q, o);
    }
    float mean = s * (1.f / 256.f);
    float var  = q * (1.f / 256.f) - mean * mean;
    float rs = rsqrtf(var + 1e-5f);
    float va[8] = { a.x, a.y, a.z, a.w, c4.x, c4.y, c4.z, c4.w };
    size_t base = (size_t)token * DIMC;
    #pragma unroll
    for (int h = 0; h < 2; h++) {
        #pragma unroll
        for (int i = 0; i < 4; i++) {
            int c = h * 128 + lane * 4 + i;
            float u = (va[h * 4 + i] - mean) * rs * g[c] + bta[c];
            g_hln16[base + c] = __float2half_rn(u);
        }
    }
}

// ---------------------------------------------------------------------------
// conv + silu + gate (tiled)
// ---------------------------------------------------------------------------
__global__ void conv_silu_kernel(const float* __restrict__ cw,
                                 const float* __restrict__ cb) {
    __shared__ float xs[35][64];
    __shared__ float zs[32][64];
    __shared__ float us[32][65];
    __shared__ float gs[32][65];
    int b = blockIdx.z, d0 = blockIdx.y * 64, t0 = blockIdx.x * 32;
    int tid = threadIdx.x;

    for (int i = tid; i < 35 * 64; i += 256) {
        int tt = i >> 6, dd = i & 63;
        int t = t0 - 3 + tt;
        xs[tt][dd] = (t >= 0) ? g_xz[((size_t)(b * 1024 + t) << 10) + d0 + dd] : 0.f;
    }
    for (int i = tid; i < 32 * 64; i += 256) {
        int tt = i >> 6, dd = i & 63;
        zs[tt][dd] = g_xz[((size_t)(b * 1024 + t0 + tt) << 10) + 512 + d0 + dd];
    }
    __syncthreads();

    for (int i = tid; i < 32 * 64; i += 256) {
        int tt = i >> 6, dd = i & 63;
        int d = d0 + dd;
        float acc = cb[d];
        #pragma unroll
        for (int j = 0; j < 4; j++)
            acc += xs[tt + j][dd] * cw[d * 4 + j];
        us[tt][dd] = acc / (1.f + __expf(-acc));
        float z = zs[tt][dd];
        gs[tt][dd] = z / (1.f + __expf(-z));
    }
    __syncthreads();

    {
        int tt = tid & 31, dgrp = tid >> 5;
        #pragma unroll
        for (int k = 0; k < 8; k++) {
            int dd = dgrp * 8 + k;
            size_t o = ((size_t)(b * DINNER + d0 + dd) << 10) + t0 + tt;
            g_uT[o] = us[tt][dd];
            g_gT[o] = gs[tt][dd];
        }
    }
    {
        int dd = tid & 63, tq = tid >> 6;
        #pragma unroll
        for (int k = 0; k < 8; k++) {
            int tt = k * 4 + tq;
            float u = us[tt][dd];
            __nv_bfloat16 h = __float2bfloat16(u);
            size_t o = (size_t)(b * 1024 + t0 + tt) * DINNER + d0 + dd;
            g_xch[o] = h;
            g_xcl[o] = __float2bfloat16(u - __bfloat162float(h));
        }
    }
}

// ---------------------------------------------------------------------------
// dt projection + softplus -> g_dtT [b][d][t]
// ---------------------------------------------------------------------------
__global__ void dt_kernel(const float* __restrict__ dtw,
                          const float* __restrict__ dtb) {
    __shared__ float swT[16][512];
    __shared__ float db[32][17];
    int tid = threadIdx.x, lane = tid & 31, w = tid >> 5;
    int b = blockIdx.x >> 5, t0 = (blockIdx.x & 31) * 32;
    for (int i = tid; i < 16 * 512; i += 256) {
        int dd = i >> 4, r = i & 15;
        swT[r][dd] = dtw[i];
    }
    for (int i = tid; i < 512; i += 256) {
        int tt = i >> 4, r = i & 15;
        db[tt][r] = g_dbl[(size_t)(b * 1024 + t0 + tt) * 48 + r];
    }
    __syncthreads();
    float drow[16];
    #pragma unroll
    for (int r = 0; r < 16; r++) drow[r] = db[lane][r];
    for (int dd = 0; dd < 64; dd++) {
        int d = w * 64 + dd;
        float acc = dtb[d];
        #pragma unroll
        for (int r = 0; r < 16; r++)
            acc += drow[r] * swT[r][d];
        float sp = (acc > 20.f) ? acc : log1pf(__expf(acc));
        g_dtT[((size_t)(b * DINNER + d) << 10) + t0 + lane] = sp;
    }
}

// ---------------------------------------------------------------------------
// selective scan + gating -> fp16 y
// ---------------------------------------------------------------------------
__global__ void scan_kernel(const float* __restrict__ A_log,
                            const float* __restrict__ Dp) {
    int tid = threadIdx.x;
    int b  = blockIdx.x >> 4;
    int d  = ((blockIdx.x & 15) << 5) + (tid >> 2);
    int sq = tid & 3;

    float Al[4], h[4];
    #pragma unroll
    for (int j = 0; j < 4; j++) {
        Al[j] = -__expf(A_log[d * 16 + sq * 4 + j]) * 1.44269504f;
        h[j] = 0.f;
    }
    float dpv = Dp[d];

    const float* dtp  = g_dtT + ((size_t)(b * DINNER + d) << 10);
    const float* up   = g_uT  + ((size_t)(b * DINNER + d) << 10);
    const float* gp   = g_gT  + ((size_t)(b * DINNER + d) << 10);
    const float* dblp = g_dbl + (size_t)b * LSEQ * 48;
    size_t ybase = (size_t)b * LSEQ * DINNER + d;

    float  dt_n = dtp[0];
    float  u_n  = up[0];
    float4 Bv_n = *(const float4*)(dblp + 16 + sq * 4);
    float4 Cv_n = *(const float4*)(dblp + 32 + sq * 4);
    float  g_n  = (sq == 0) ? gp[0] : 0.f;

    for (int t = 0; t < LSEQ; t++) {
        float  dt = dt_n;
        float  u  = u_n;
        float4 Bv = Bv_n;
        float4 Cv = Cv_n;
        float  gate = g_n;
        if (t + 1 < LSEQ) {
            dt_n = dtp[t + 1];
            u_n  = up[t + 1];
            Bv_n = *(const float4*)(dblp + (size_t)(t + 1) * 48 + 16 + sq * 4);
            Cv_n = *(const float4*)(dblp + (size_t)(t + 1) * 48 + 32 + sq * 4);
            if (sq == 0) g_n = gp[t + 1];
        }
        float dtu = dt * u;
        float y = 0.f;
        h[0] = exp2f(dt * Al[0]) * h[0] + dtu * Bv.x; y += h[0] * Cv.x;
        h[1] = exp2f(dt * Al[1]) * h[1] + dtu * Bv.y; y += h[1] * Cv.y;
        h[2] = exp2f(dt * Al[2]) * h[2] + dtu * Bv.z; y += h[2] * Cv.z;
        h[3] = exp2f(dt * Al[3]) * h[3] + dtu * Bv.w; y += h[3] * Cv.w;
        y += __shfl_xor_sync(~0u, y, 1);
        y += __shfl_xor_sync(~0u, y, 2);
        if (sq == 0) {
            float v = (y + u * dpv) * gate;
            g_y16[ybase + (size_t)t * DINNER] = __float2half_rn(v);
        }
    }
}

// ---------------------------------------------------------------------------
// GEMM helpers
// ---------------------------------------------------------------------------
__device__ __forceinline__ uint32_t pack_f16x2(float e, float o) {
    uint32_t d;
    asm("cvt.rn.f16x2.f32 %0, %1, %2;" : "=r"(d) : "f"(o), "f"(e));
    return d;
}

__device__ __forceinline__ void ldsm4(uint32_t r[4], uint32_t addr) {
    asm volatile("ldmatrix.sync.aligned.m8n8.x4.shared.b16 {%0,%1,%2,%3}, [%4];"
                 : "=r"(r[0]), "=r"(r[1]), "=r"(r[2]), "=r"(r[3]) : "r"(addr));
}

__device__ __forceinline__ void mma_bf16(float* c, const uint32_t* a, const uint32_t* b) {
    asm volatile(
        "mma.sync.aligned.m16n8k16.row.col.f32.bf16.bf16.f32 "
        "{%0,%1,%2,%3}, {%4,%5,%6,%7}, {%8,%9}, {%0,%1,%2,%3};\n"
        : "+f"(c[0]), "+f"(c[1]), "+f"(c[2]), "+f"(c[3])
        : "r"(a[0]), "r"(a[1]), "r"(a[2]), "r"(a[3]), "r"(b[0]), "r"(b[1]));
}
__device__ __forceinline__ void mma_f16(float* c, const uint32_t* a, const uint32_t* b) {
    asm volatile(
        "mma.sync.aligned.m16n8k16.row.col.f32.f16.f16.f32 "
        "{%0,%1,%2,%3}, {%4,%5,%6,%7}, {%8,%9}, {%0,%1,%2,%3};\n"
        : "+f"(c[0]), "+f"(c[1]), "+f"(c[2]), "+f"(c[3])
        : "r"(a[0]), "r"(a[1]), "r"(a[2]), "r"(a[3]), "r"(b[0]), "r"(b[1]));
}

__device__ __forceinline__ void cp16(uint32_t dst, const void* src, bool ok) {
    int sz = ok ? 16 : 0;
    asm volatile("cp.async.cg.shared.global [%0], [%1], 16, %2;\n"
                 :: "r"(dst), "l"(src), "r"(sz));
}
#define CP_COMMIT() asm volatile("cp.async.commit_group;\n" ::: "memory")

// ---------------------------------------------------------------------------
// GEMM (NT), cp.async 2-stage, BM=128 BN=64 BK=64, 256 thr, 8 warps 4x2.
// KIND 0: bf16 hi/lo 3-pass. KIND 1: fp16 single-pass.
// EPI: 0 fp32 | 1 +res | 2 gelu+bias -> fp16 | 3 res+bias, smem-transposed
// ---------------------------------------------------------------------------
template <int EPI, int KIND>
__global__ void __launch_bounds__(256, 2)
gemm_mix(const uint16_t* __restrict__ Ah, const uint16_t* __restrict__ Al,
         const uint16_t* __restrict__ Bh, const uint16_t* __restrict__ Bl,
         float* __restrict__ C, int M, int N, int K,
         const float* __restrict__ bias, const float* __restrict__ res,
         uint16_t* __restrict__ outO) {
    const int APL = 128 * 128;
    const int BPL = 64 * 128;
    const int NPLANE = (KIND == 0) ? 2 : 1;
    const int STG = NPLANE * (APL + BPL);
    extern __shared__ __align__(1024) unsigned char smem[];

    int tid = threadIdx.x;
    int lane = tid & 31, wid = tid >> 5;
    int wm = wid & 3, wn = wid >> 2;
    int m0 = blockIdx.y * 128, n0 = blockIdx.x * 64;

    uint32_t smem_u;
    asm("{ .reg .u64 t; cvta.to.shared.u64 t, %1; cvt.u32.u64 %0, t; }"
        : "=r"(smem_u) : "l"(smem));

    int lh = lane >> 4;
    uint32_t aOff[2], bOff[2];
    #pragma unroll
    for (int mt = 0; mt < 2; mt++) {
        int r = wm * 32 + mt * 16 + (lane & 15);
        aOff[mt] = r * 128 + ((lh ^ (r & 7)) << 4);
    }
    #pragma unroll
    for (int np = 0; np < 2; np++) {
        int r = wn * 32 + np * 16 + (lane & 15);
        bOff[np] = NPLANE * APL + r * 128 + ((lh ^ (r & 7)) << 4);
    }

    float acc[2][4][4];
    #pragma unroll
    for (int i = 0; i < 2; i++)
        #pragma unroll
        for (int j = 0; j < 4; j++)
            #pragma unroll
            for (int k = 0; k < 4; k++) acc[i][j][k] = 0.f;

    int nk = K / 64;

    auto stage_copy = [&](int st, int kt) {
        uint32_t sb = smem_u + st * STG;
        #pragma unroll
        for (int i = 0; i < 4; i++) {
            int chunk = tid + i * 256;
            int row = chunk >> 3, c = chunk & 7;
            size_t goff = (size_t)(m0 + row) * K + kt + c * 8;
            uint32_t d = sb + row * 128 + ((c ^ (row & 7)) << 4);
            cp16(d, Ah + goff, true);
            if (KIND == 0) cp16(d + APL, Al + goff, true);
        }
        #pragma unroll
        for (int i = 0; i < 2; i++) {
            int chunk = tid + i * 256;
            int row = chunk >> 3, c = chunk & 7;
            bool ok = (n0 + row) < N;
            size_t goff = (size_t)(ok ? (n0 + row) : 0) * K + kt + c * 8;
            uint32_t d = sb + NPLANE * APL + row * 128 + ((c ^ (row & 7)) << 4);
            cp16(d, Bh + goff, ok);
            if (KIND == 0) cp16(d + BPL, Bl + goff, ok);
        }
    };

    stage_copy(0, 0);
    CP_COMMIT();

    for (int it = 0; it < nk; it++) {
        bool more = (it + 1) < nk;
        if (more) {
            stage_copy((it + 1) & 1, (it + 1) * 64);
            CP_COMMIT();
            asm volatile("cp.async.wait_group 1;\n" ::: "memory");
        } else {
            asm volatile("cp.async.wait_group 0;\n" ::: "memory");
        }
        __syncthreads();

        uint32_t sb = smem_u + (it & 1) * STG;
        #pragma unroll
        for (int s = 0; s < 4; s++) {
            uint32_t sx = s << 5;
            if (KIND == 0) {
                uint32_t ah[2][4], al[2][4];
                ldsm4(ah[0], (sb + aOff[0]) ^ sx);
                ldsm4(ah[1], (sb + aOff[1]) ^ sx);
                ldsm4(al[0], (sb + aOff[0] + APL) ^ sx);
                ldsm4(al[1], (sb + aOff[1] + APL) ^ sx);
                uint32_t t0[4], t1[4], u0[4], u1[4];
                ldsm4(t0, (sb + bOff[0]) ^ sx);
                ldsm4(t1, (sb + bOff[1]) ^ sx);
                ldsm4(u0, (sb + bOff[0] + BPL) ^ sx);
                ldsm4(u1, (sb + bOff[1] + BPL) ^ sx);
                uint32_t bh2[4][2] = {{t0[0], t0[2]}, {t0[1], t0[3]}, {t1[0], t1[2]}, {t1[1], t1[3]}};
                uint32_t bl2[4][2] = {{u0[0], u0[2]}, {u0[1], u0[3]}, {u1[0], u1[2]}, {u1[1], u1[3]}};
                #pragma unroll
                for (int mt = 0; mt < 2; mt++)
                    #pragma unroll
                    for (int nt = 0; nt < 4; nt++) {
                        mma_bf16(acc[mt][nt], ah[mt], bh2[nt]);
                        mma_bf16(acc[mt][nt], ah[mt], bl2[nt]);
                        mma_bf16(acc[mt][nt], al[mt], bh2[nt]);
                    }
            } else {
                uint32_t ah[2][4];
                ldsm4(ah[0], (sb + aOff[0]) ^ sx);
                ldsm4(ah[1], (sb + aOff[1]) ^ sx);
                uint32_t t0[4], t1[4];
                ldsm4(t0, (sb + bOff[0]) ^ sx);
                ldsm4(t1, (sb + bOff[1]) ^ sx);
                uint32_t bh2[4][2] = {{t0[0], t0[2]}, {t0[1], t0[3]}, {t1[0], t1[2]}, {t1[1], t1[3]}};
                #pragma unroll
                for (int mt = 0; mt < 2; mt++)
                    #pragma unroll
                    for (int nt = 0; nt < 4; nt++)
                        mma_f16(acc[mt][nt], ah[mt], bh2[nt]);
            }
        }
        __syncthreads();
    }

    if (EPI == 3) {
        float* sf = (float*)smem;
        #pragma unroll
        for (int mt = 0; mt < 2; mt++) {
            #pragma unroll
            for (int nt = 0; nt < 4; nt++) {
                int mlb = wm * 32 + mt * 16 + (lane >> 2);
                int nlb = wn * 32 + nt * 8 + (lane & 3) * 2;
                #pragma unroll
                for (int e = 0; e < 4; e++) {
                    int ml = mlb + (e >> 1) * 8;
                    int nl = nlb + (e & 1);
                    float v = res[(size_t)(m0 + ml) * N + (n0 + nl)]
                            + acc[mt][nt][e] + bias[n0 + nl];
                    sf[nl * 132 + ml] = v;
                }
            }
        }
        __syncthreads();
        int b = m0 >> 10, tb = m0 & 1023;
        for (int i = tid; i < 64 * 128; i += 256) {
            int nl = i >> 7, ml = i & 127;
            C[(((size_t)b * DIMC + n0 + nl) << 10) + tb + ml] = sf[nl * 132 + ml];
        }
        return;
    }

    #pragma unroll
    for (int mt = 0; mt < 2; mt++) {
        #pragma unroll
        for (int nt = 0; nt < 4; nt++) {
            int rbase = m0 + wm * 32 + mt * 16 + (lane >> 2);
            int cbase = n0 + wn * 32 + nt * 8 + (lane & 3) * 2;
            if (EPI == 2) {
                #pragma unroll
                for (int ep = 0; ep < 2; ep++) {
                    int m = rbase + ep * 8;
                    int n = cbase;
                    float u0 = acc[mt][nt][ep * 2 + 0] + bias[n];
                    float u1 = acc[mt][nt][ep * 2 + 1] + bias[n + 1];
                    float g0 = 0.5f * u0 * (1.f + erff(u0 * 0.70710678118f));
                    float g1 = 0.5f * u1 * (1.f + erff(u1 * 0.70710678118f));
                    ((uint32_t*)outO)[((size_t)m * N + n) >> 1] = pack_f16x2(g0, g1);
                }
            } else {
                #pragma unroll
                for (int e = 0; e < 4; e++) {
                    int m = rbase + (e >> 1) * 8;
                    int n = cbase + (e & 1);
                    if (n >= N) continue;
                    float v = acc[mt][nt][e];
                    if (EPI == 0) {
                        C[(size_t)m * N + n] = v;
                    } else { // EPI 1
                        C[(size_t)m * N + n] = res[(size_t)m * N + n] + v;
                    }
                }
            }
        }
    }
}

// ---------------------------------------------------------------------------
extern "C" void kernel_launch(void* const* d_in, const int* in_sizes, int n_in,
                              void* d_out, int out_size) {
    const float* x        = (const float*)d_in[0];
    const float* ln_g     = (const float*)d_in[1];
    const float* ln_b     = (const float*)d_in[2];
    const float* in_proj  = (const float*)d_in[3];
    const float* conv_w   = (const float*)d_in[4];
    const float* conv_b   = (const float*)d_in[5];
    const float* x_proj   = (const float*)d_in[6];
    const float* dt_w     = (const float*)d_in[7];
    const float* dt_b     = (const float*)d_in[8];
    const float* A_log    = (const float*)d_in[9];
    const float* Dp       = (const float*)d_in[10];
    const float* out_proj = (const float*)d_in[11];
    const float* mlp_ln_g = (const float*)d_in[12];
    const float* mlp_ln_b = (const float*)d_in[13];
    const float* mlp_w1   = (const float*)d_in[14];
    const float* mlp_b1   = (const float*)d_in[15];
    const float* mlp_w2   = (const float*)d_in[16];
    const float* mlp_b2   = (const float*)d_in[17];
    float* out = (float*)d_out;

    float *p_dbl, *p_xf, *p_xf2, *p_xz;
    cudaGetSymbolAddress((void**)&p_dbl, g_dbl);
    cudaGetSymbolAddress((void**)&p_xf,  g_xf);
    cudaGetSymbolAddress((void**)&p_xf2, g_xf2);
    cudaGetSymbolAddress((void**)&p_xz,  g_xz);
    uint16_t *p_xn16, *p_xch, *p_xcl, *p_y16, *p_hln16, *p_h116;
    cudaGetSymbolAddress((void**)&p_xn16,  g_xn16);
    cudaGetSymbolAddress((void**)&p_xch,   g_xch);
    cudaGetSymbolAddress((void**)&p_xcl,   g_xcl);
    cudaGetSymbolAddress((void**)&p_y16,   g_y16);
    cudaGetSymbolAddress((void**)&p_hln16, g_hln16);
    cudaGetSymbolAddress((void**)&p_h116,  g_h116);
    uint16_t *p_in16, *p_xph, *p_xpl, *p_op16, *p_m116, *p_m216;
    cudaGetSymbolAddress((void**)&p_in16, w_in16);
    cudaGetSymbolAddress((void**)&p_xph,  w_xph);
    cudaGetSymbolAddress((void**)&p_xpl,  w_xpl);
    cudaGetSymbolAddress((void**)&p_op16, w_op16);
    cudaGetSymbolAddress((void**)&p_m116, w_m116);
    cudaGetSymbolAddress((void**)&p_m216, w_m216);

    const int SMEM3 = 2 * 2 * (128 * 128 + 64 * 128);   // 98304 (bf16 3-pass)
    const int SMEM1 = 2 * (128 * 128 + 64 * 128);       // 49152 (fp16 1-pass)
    cudaFuncSetAttribute(gemm_mix<0, 1>, cudaFuncAttributeMaxDynamicSharedMemorySize, SMEM1);
    cudaFuncSetAttribute(gemm_mix<0, 0>, cudaFuncAttributeMaxDynamicSharedMemorySize, SMEM3);
    cudaFuncSetAttribute(gemm_mix<1, 1>, cudaFuncAttributeMaxDynamicSharedMemorySize, SMEM1);
    cudaFuncSetAttribute(gemm_mix<2, 1>, cudaFuncAttributeMaxDynamicSharedMemorySize, SMEM1);
    cudaFuncSetAttribute(gemm_mix<3, 1>, cudaFuncAttributeMaxDynamicSharedMemorySize, SMEM1);

    // fused weight split
    wconv_all<<<(WS4 + 255) / 256, 256>>>(in_proj, x_proj, out_proj, mlp_w1, mlp_w2);

    // 1. ln1
    ln1_kernel<<<256, 256>>>(x, ln_g, ln_b);
    // 2. in_proj (8192 x 1024, K=256) fp16 1-pass
    gemm_mix<0, 1><<<dim3(16, 64), 256, SMEM1>>>(
        p_xn16, nullptr, p_in16, nullptr, p_xz, NTOK, 1024, 256, nullptr, nullptr, nullptr);
    // 3. conv + silu + gate
    conv_silu_kernel<<<dim3(32, 8, 8), 256>>>(conv_w, conv_b);
    // 4. x_proj (8192 x 48, K=512) bf16 3-pass
    gemm_mix<0, 0><<<dim3(1, 64), 256, SMEM3>>>(
        p_xch, p_xcl, p_xph, p_xpl, p_dbl, NTOK, 48, 512, nullptr, nullptr, nullptr);
    // 5. dt projection
    dt_kernel<<<256, 256>>>(dt_w, dt_b);
    // 6. selective scan
    scan_kernel<<<128, 128>>>(A_log, Dp);
    // 7. out_proj + residual (8192 x 256, K=512) fp16 1-pass
    gemm_mix<1, 1><<<dim3(4, 64), 256, SMEM1>>>(
        p_y16, nullptr, p_op16, nullptr, p_xf2, NTOK, 256, 512, nullptr, p_xf, nullptr);
    // 8. ln2
    ln2_kernel<<<NTOK / 8, 256>>>(mlp_ln_g, mlp_ln_b);
    // 9. mlp1 + gelu -> fp16 h1 (8192 x 1024, K=256) fp16 1-pass
    gemm_mix<2, 1><<<dim3(16, 64), 256, SMEM1>>>(
        p_hln16, nullptr, p_m116, nullptr, nullptr, NTOK, 1024, 256, mlp_b1, nullptr, p_h116);
    // 10. mlp2 + residual + transposed store (8192 x 256, K=1024) fp16 1-pass
    gemm_mix<3, 1><<<dim3(4, 64), 256, SMEM1>>>(
        p_h116, nullptr, p_m216, nullptr, out, NTOK, 256, 1024, mlp_b2, p_xf2, nullptr);
}

// round 13
// speedup vs baseline: 3.7105x; 1.0341x over previous
#include <cuda_runtime.h>
#include <cuda_bf16.h>
#include <cuda_fp16.h>
#include <math.h>
#include <stdint.h>

// ---------------------------------------------------------------------------
// OptimizedMambaBlock: B=8, DIM=256, H=W=32 -> L=1024, tokens N=8192
// R13: all GEMMs fp16 single-pass; g_xz fp16; conv emits single fp16 plane.
// ---------------------------------------------------------------------------

#define NTOK   8192
#define LSEQ   1024
#define DIMC   256
#define DINNER 512

// fp32 scratch
__device__ float g_xf [NTOK * DIMC];
__device__ float g_dbl[NTOK * 48];
__device__ float g_xf2[NTOK * DIMC];
// scan-layout operands [b][d][t]
__device__ float g_uT [8 * DINNER * LSEQ];
__device__ float g_gT [8 * DINNER * LSEQ];
__device__ float g_dtT[8 * DINNER * LSEQ];

// fp16 activations
__device__ __half g_xn16 [NTOK * DIMC];
__device__ __half g_xz16 [NTOK * 1024];
__device__ __half g_xc16 [NTOK * DINNER];
__device__ __half g_y16  [NTOK * DINNER];
__device__ __half g_hln16[NTOK * DIMC];
__device__ __half g_h116 [NTOK * 1024];

// fp16 weights
__device__ __half w_in16[1024 * 256];
__device__ __half w_xp16[48 * 512];
__device__ __half w_op16[256 * 512];
__device__ __half w_m116[1024 * 256];
__device__ __half w_m216[256 * 1024];

// ---------------------------------------------------------------------------
// fused weight split (all fp16)
// ---------------------------------------------------------------------------
#define WS0 262144
#define WS1 (WS0 + 24576)
#define WS2 (WS1 + 131072)
#define WS3 (WS2 + 262144)
#define WS4 (WS3 + 262144)
__global__ void wconv_all(const float* __restrict__ w_in, const float* __restrict__ w_xp,
                          const float* __restrict__ w_op, const float* __restrict__ w_m1,
                          const float* __restrict__ w_m2) {
    int i = blockIdx.x * 256 + threadIdx.x;
    const float* src; __half* dh; int off;
    if      (i < WS0) { src = w_in; dh = w_in16; off = i; }
    else if (i < WS1) { src = w_xp; dh = w_xp16; off = i - WS0; }
    else if (i < WS2) { src = w_op; dh = w_op16; off = i - WS1; }
    else if (i < WS3) { src = w_m1; dh = w_m116; off = i - WS2; }
    else if (i < WS4) { src = w_m2; dh = w_m216; off = i - WS3; }
    else return;
    dh[off] = __float2half_rn(src[off]);
}

// ---------------------------------------------------------------------------
// LN1: coalesced smem-transpose; fp32 residual + fp16 normed
// ---------------------------------------------------------------------------
__global__ void ln1_kernel(const float* __restrict__ x,
                           const float* __restrict__ g,
                           const float* __restrict__ bta) {
    __shared__ float xs[32][257];
    int tid = threadIdx.x, lane = tid & 31, w = tid >> 5;
    int b = blockIdx.x >> 5, tb = blockIdx.x & 31;
    #pragma unroll 8
    for (int j = 0; j < 32; j++) {
        int c = w * 32 + j;
        xs[lane][c] = x[(((size_t)b * DIMC + c) << 10) + tb * 32 + lane];
    }
    __syncthreads();
    for (int q = 0; q < 4; q++) {
        int tt = w * 4 + q;
        float v[8], s = 0.f, sq = 0.f;
        #pragma unroll
        for (int k = 0; k < 8; k++) {
            v[k] = xs[tt][lane + k * 32];
            s += v[k]; sq += v[k] * v[k];
        }
        #pragma unroll
        for (int o = 16; o; o >>= 1) {
            s  += __shfl_xor_sync(~0u, s, o);
            sq += __shfl_xor_sync(~0u, sq, o);
        }
        float mean = s * (1.f / 256.f);
        float var  = sq * (1.f / 256.f) - mean * mean;
        float rs = rsqrtf(var + 1e-5f);
        size_t base = (size_t)(b * 1024 + tb * 32 + tt) * DIMC;
        #pragma unroll
        for (int k = 0; k < 8; k++) {
            int c = lane + k * 32;
            g_xf[base + c] = v[k];
            float xn = (v[k] - mean) * rs * g[c] + bta[c];
            g_xn16[base + c] = __float2half_rn(xn);
        }
    }
}

// ---------------------------------------------------------------------------
// LN2: fp32 in, fp16 out
// ---------------------------------------------------------------------------
__global__ void ln2_kernel(const float* __restrict__ g,
                           const float* __restrict__ bta) {
    int token = (blockIdx.x * blockDim.x + threadIdx.x) >> 5;
    int lane = threadIdx.x & 31;
    const float* row = g_xf2 + (size_t)token * DIMC;
    float4 a = *(const float4*)(row + lane * 4);
    float4 c4 = *(const float4*)(row + 128 + lane * 4);
    float s = a.x + a.y + a.z + a.w + c4.x + c4.y + c4.z + c4.w;
    float q = a.x*a.x + a.y*a.y + a.z*a.z + a.w*a.w
            + c4.x*c4.x + c4.y*c4.y + c4.z*c4.z + c4.w*c4.w;
    #pragma unroll
    for (int o = 16; o; o >>= 1) {
        s += __shfl_xor_sync(~0u, s, o);
        q += __shfl_xor_sync(~0u, q, o);
    }
    float mean = s * (1.f / 256.f);
    float var  = q * (1.f / 256.f) - mean * mean;
    float rs = rsqrtf(var + 1e-5f);
    float va[8] = { a.x, a.y, a.z, a.w, c4.x, c4.y, c4.z, c4.w };
    size_t base = (size_t)token * DIMC;
    #pragma unroll
    for (int h = 0; h < 2; h++) {
        #pragma unroll
        for (int i = 0; i < 4; i++) {
            int c = h * 128 + lane * 4 + i;
            float u = (va[h * 4 + i] - mean) * rs * g[c] + bta[c];
            g_hln16[base + c] = __float2half_rn(u);
        }
    }
}

// ---------------------------------------------------------------------------
// conv + silu + gate (tiled); fp16 in (xz), fp32 scan outputs + fp16 GEMM out
// ---------------------------------------------------------------------------
__global__ void conv_silu_kernel(const float* __restrict__ cw,
                                 const float* __restrict__ cb) {
    __shared__ float xs[35][64];
    __shared__ float zs[32][64];
    __shared__ float us[32][65];
    __shared__ float gs[32][65];
    int b = blockIdx.z, d0 = blockIdx.y * 64, t0 = blockIdx.x * 32;
    int tid = threadIdx.x;

    for (int i = tid; i < 35 * 64; i += 256) {
        int tt = i >> 6, dd = i & 63;
        int t = t0 - 3 + tt;
        xs[tt][dd] = (t >= 0)
            ? __half2float(g_xz16[((size_t)(b * 1024 + t) << 10) + d0 + dd]) : 0.f;
    }
    for (int i = tid; i < 32 * 64; i += 256) {
        int tt = i >> 6, dd = i & 63;
        zs[tt][dd] = __half2float(g_xz16[((size_t)(b * 1024 + t0 + tt) << 10) + 512 + d0 + dd]);
    }
    __syncthreads();

    for (int i = tid; i < 32 * 64; i += 256) {
        int tt = i >> 6, dd = i & 63;
        int d = d0 + dd;
        float acc = cb[d];
        #pragma unroll
        for (int j = 0; j < 4; j++)
            acc += xs[tt + j][dd] * cw[d * 4 + j];
        us[tt][dd] = acc / (1.f + __expf(-acc));
        float z = zs[tt][dd];
        gs[tt][dd] = z / (1.f + __expf(-z));
    }
    __syncthreads();

    {
        int tt = tid & 31, dgrp = tid >> 5;
        #pragma unroll
        for (int k = 0; k < 8; k++) {
            int dd = dgrp * 8 + k;
            size_t o = ((size_t)(b * DINNER + d0 + dd) << 10) + t0 + tt;
            g_uT[o] = us[tt][dd];
            g_gT[o] = gs[tt][dd];
        }
    }
    {
        int dd = tid & 63, tq = tid >> 6;
        #pragma unroll
        for (int k = 0; k < 8; k++) {
            int tt = k * 4 + tq;
            size_t o = (size_t)(b * 1024 + t0 + tt) * DINNER + d0 + dd;
            g_xc16[o] = __float2half_rn(us[tt][dd]);
        }
    }
}

// ---------------------------------------------------------------------------
// dt projection + softplus -> g_dtT [b][d][t]
// ---------------------------------------------------------------------------
__global__ void dt_kernel(const float* __restrict__ dtw,
                          const float* __restrict__ dtb) {
    __shared__ float swT[16][512];
    __shared__ float db[32][17];
    int tid = threadIdx.x, lane = tid & 31, w = tid >> 5;
    int b = blockIdx.x >> 5, t0 = (blockIdx.x & 31) * 32;
    for (int i = tid; i < 16 * 512; i += 256) {
        int dd = i >> 4, r = i & 15;
        swT[r][dd] = dtw[i];
    }
    for (int i = tid; i < 512; i += 256) {
        int tt = i >> 4, r = i & 15;
        db[tt][r] = g_dbl[(size_t)(b * 1024 + t0 + tt) * 48 + r];
    }
    __syncthreads();
    float drow[16];
    #pragma unroll
    for (int r = 0; r < 16; r++) drow[r] = db[lane][r];
    for (int dd = 0; dd < 64; dd++) {
        int d = w * 64 + dd;
        float acc = dtb[d];
        #pragma unroll
        for (int r = 0; r < 16; r++)
            acc += drow[r] * swT[r][d];
        float sp = (acc > 20.f) ? acc : log1pf(__expf(acc));
        g_dtT[((size_t)(b * DINNER + d) << 10) + t0 + lane] = sp;
    }
}

// ---------------------------------------------------------------------------
// selective scan + gating -> fp16 y
// ---------------------------------------------------------------------------
__global__ void scan_kernel(const float* __restrict__ A_log,
                            const float* __restrict__ Dp) {
    int tid = threadIdx.x;
    int b  = blockIdx.x >> 4;
    int d  = ((blockIdx.x & 15) << 5) + (tid >> 2);
    int sq = tid & 3;

    float Al[4], h[4];
    #pragma unroll
    for (int j = 0; j < 4; j++) {
        Al[j] = -__expf(A_log[d * 16 + sq * 4 + j]) * 1.44269504f;
        h[j] = 0.f;
    }
    float dpv = Dp[d];

    const float* dtp  = g_dtT + ((size_t)(b * DINNER + d) << 10);
    const float* up   = g_uT  + ((size_t)(b * DINNER + d) << 10);
    const float* gp   = g_gT  + ((size_t)(b * DINNER + d) << 10);
    const float* dblp = g_dbl + (size_t)b * LSEQ * 48;
    size_t ybase = (size_t)b * LSEQ * DINNER + d;

    float  dt_n = dtp[0];
    float  u_n  = up[0];
    float4 Bv_n = *(const float4*)(dblp + 16 + sq * 4);
    float4 Cv_n = *(const float4*)(dblp + 32 + sq * 4);
    float  g_n  = (sq == 0) ? gp[0] : 0.f;

    for (int t = 0; t < LSEQ; t++) {
        float  dt = dt_n;
        float  u  = u_n;
        float4 Bv = Bv_n;
        float4 Cv = Cv_n;
        float  gate = g_n;
        if (t + 1 < LSEQ) {
            dt_n = dtp[t + 1];
            u_n  = up[t + 1];
            Bv_n = *(const float4*)(dblp + (size_t)(t + 1) * 48 + 16 + sq * 4);
            Cv_n = *(const float4*)(dblp + (size_t)(t + 1) * 48 + 32 + sq * 4);
            if (sq == 0) g_n = gp[t + 1];
        }
        float dtu = dt * u;
        float y = 0.f;
        h[0] = exp2f(dt * Al[0]) * h[0] + dtu * Bv.x; y += h[0] * Cv.x;
        h[1] = exp2f(dt * Al[1]) * h[1] + dtu * Bv.y; y += h[1] * Cv.y;
        h[2] = exp2f(dt * Al[2]) * h[2] + dtu * Bv.z; y += h[2] * Cv.z;
        h[3] = exp2f(dt * Al[3]) * h[3] + dtu * Bv.w; y += h[3] * Cv.w;
        y += __shfl_xor_sync(~0u, y, 1);
        y += __shfl_xor_sync(~0u, y, 2);
        if (sq == 0) {
            float v = (y + u * dpv) * gate;
            g_y16[ybase + (size_t)t * DINNER] = __float2half_rn(v);
        }
    }
}

// ---------------------------------------------------------------------------
// GEMM helpers
// ---------------------------------------------------------------------------
__device__ __forceinline__ uint32_t pack_f16x2(float e, float o) {
    uint32_t d;
    asm("cvt.rn.f16x2.f32 %0, %1, %2;" : "=r"(d) : "f"(o), "f"(e));
    return d;
}

__device__ __forceinline__ void ldsm4(uint32_t r[4], uint32_t addr) {
    asm volatile("ldmatrix.sync.aligned.m8n8.x4.shared.b16 {%0,%1,%2,%3}, [%4];"
                 : "=r"(r[0]), "=r"(r[1]), "=r"(r[2]), "=r"(r[3]) : "r"(addr));
}

__device__ __forceinline__ void mma_f16(float* c, const uint32_t* a, const uint32_t* b) {
    asm volatile(
        "mma.sync.aligned.m16n8k16.row.col.f32.f16.f16.f32 "
        "{%0,%1,%2,%3}, {%4,%5,%6,%7}, {%8,%9}, {%0,%1,%2,%3};\n"
        : "+f"(c[0]), "+f"(c[1]), "+f"(c[2]), "+f"(c[3])
        : "r"(a[0]), "r"(a[1]), "r"(a[2]), "r"(a[3]), "r"(b[0]), "r"(b[1]));
}

__device__ __forceinline__ void cp16(uint32_t dst, const void* src, bool ok) {
    int sz = ok ? 16 : 0;
    asm volatile("cp.async.cg.shared.global [%0], [%1], 16, %2;\n"
                 :: "r"(dst), "l"(src), "r"(sz));
}
#define CP_COMMIT() asm volatile("cp.async.commit_group;\n" ::: "memory")

// ---------------------------------------------------------------------------
// fp16 GEMM (NT), cp.async 2-stage, BM=128 BN=64 BK=64, 256 thr, 8 warps 4x2.
// EPI: 0 fp32 | 1 +res | 2 gelu+bias -> fp16 | 3 res+bias transp | 4 fp16 out
// ---------------------------------------------------------------------------
template <int EPI>
__global__ void __launch_bounds__(256, 2)
gemm_f16(const uint16_t* __restrict__ A, const uint16_t* __restrict__ B,
         float* __restrict__ C, int M, int N, int K,
         const float* __restrict__ bias, const float* __restrict__ res,
         uint16_t* __restrict__ outO) {
    const int APL = 128 * 128;
    const int BPL = 64 * 128;
    const int STG = APL + BPL;
    extern __shared__ __align__(1024) unsigned char smem[];

    int tid = threadIdx.x;
    int lane = tid & 31, wid = tid >> 5;
    int wm = wid & 3, wn = wid >> 2;
    int m0 = blockIdx.y * 128, n0 = blockIdx.x * 64;

    uint32_t smem_u;
    asm("{ .reg .u64 t; cvta.to.shared.u64 t, %1; cvt.u32.u64 %0, t; }"
        : "=r"(smem_u) : "l"(smem));

    int lh = lane >> 4;
    uint32_t aOff[2], bOff[2];
    #pragma unroll
    for (int mt = 0; mt < 2; mt++) {
        int r = wm * 32 + mt * 16 + (lane & 15);
        aOff[mt] = r * 128 + ((lh ^ (r & 7)) << 4);
    }
    #pragma unroll
    for (int np = 0; np < 2; np++) {
        int r = wn * 32 + np * 16 + (lane & 15);
        bOff[np] = APL + r * 128 + ((lh ^ (r & 7)) << 4);
    }

    float acc[2][4][4];
    #pragma unroll
    for (int i = 0; i < 2; i++)
        #pragma unroll
        for (int j = 0; j < 4; j++)
            #pragma unroll
            for (int k = 0; k < 4; k++) acc[i][j][k] = 0.f;

    int nk = K / 64;

    auto stage_copy = [&](int st, int kt) {
        uint32_t sb = smem_u + st * STG;
        #pragma unroll
        for (int i = 0; i < 4; i++) {
            int chunk = tid + i * 256;
            int row = chunk >> 3, c = chunk & 7;
            size_t goff = (size_t)(m0 + row) * K + kt + c * 8;
            uint32_t d = sb + row * 128 + ((c ^ (row & 7)) << 4);
            cp16(d, A + goff, true);
        }
        #pragma unroll
        for (int i = 0; i < 2; i++) {
            int chunk = tid + i * 256;
            int row = chunk >> 3, c = chunk & 7;
            bool ok = (n0 + row) < N;
            size_t goff = (size_t)(ok ? (n0 + row) : 0) * K + kt + c * 8;
            uint32_t d = sb + APL + row * 128 + ((c ^ (row & 7)) << 4);
            cp16(d, B + goff, ok);
        }
    };

    stage_copy(0, 0);
    CP_COMMIT();

    for (int it = 0; it < nk; it++) {
        bool more = (it + 1) < nk;
        if (more) {
            stage_copy((it + 1) & 1, (it + 1) * 64);
            CP_COMMIT();
            asm volatile("cp.async.wait_group 1;\n" ::: "memory");
        } else {
            asm volatile("cp.async.wait_group 0;\n" ::: "memory");
        }
        __syncthreads();

        uint32_t sb = smem_u + (it & 1) * STG;
        #pragma unroll
        for (int s = 0; s < 4; s++) {
            uint32_t sx = s << 5;
            uint32_t ah[2][4];
            ldsm4(ah[0], (sb + aOff[0]) ^ sx);
            ldsm4(ah[1], (sb + aOff[1]) ^ sx);
            uint32_t t0[4], t1[4];
            ldsm4(t0, (sb + bOff[0]) ^ sx);
            ldsm4(t1, (sb + bOff[1]) ^ sx);
            uint32_t bh2[4][2] = {{t0[0], t0[2]}, {t0[1], t0[3]}, {t1[0], t1[2]}, {t1[1], t1[3]}};
            #pragma unroll
            for (int mt = 0; mt < 2; mt++)
                #pragma unroll
                for (int nt = 0; nt < 4; nt++)
                    mma_f16(acc[mt][nt], ah[mt], bh2[nt]);
        }
        __syncthreads();
    }

    if (EPI == 3) {
        float* sf = (float*)smem;
        #pragma unroll
        for (int mt = 0; mt < 2; mt++) {
            #pragma unroll
            for (int nt = 0; nt < 4; nt++) {
                int mlb = wm * 32 + mt * 16 + (lane >> 2);
                int nlb = wn * 32 + nt * 8 + (lane & 3) * 2;
                #pragma unroll
                for (int e = 0; e < 4; e++) {
                    int ml = mlb + (e >> 1) * 8;
                    int nl = nlb + (e & 1);
                    float v = res[(size_t)(m0 + ml) * N + (n0 + nl)]
                            + acc[mt][nt][e] + bias[n0 + nl];
                    sf[nl * 132 + ml] = v;
                }
            }
        }
        __syncthreads();
        int b = m0 >> 10, tb = m0 & 1023;
        for (int i = tid; i < 64 * 128; i += 256) {
            int nl = i >> 7, ml = i & 127;
            C[(((size_t)b * DIMC + n0 + nl) << 10) + tb + ml] = sf[nl * 132 + ml];
        }
        return;
    }

    #pragma unroll
    for (int mt = 0; mt < 2; mt++) {
        #pragma unroll
        for (int nt = 0; nt < 4; nt++) {
            int rbase = m0 + wm * 32 + mt * 16 + (lane >> 2);
            int cbase = n0 + wn * 32 + nt * 8 + (lane & 3) * 2;
            if (EPI == 2 || EPI == 4) {
                #pragma unroll
                for (int ep = 0; ep < 2; ep++) {
                    int m = rbase + ep * 8;
                    int n = cbase;
                    float u0 = acc[mt][nt][ep * 2 + 0];
                    float u1 = acc[mt][nt][ep * 2 + 1];
                    if (EPI == 2) {
                        u0 += bias[n];
                        u1 += bias[n + 1];
                        u0 = 0.5f * u0 * (1.f + erff(u0 * 0.70710678118f));
                        u1 = 0.5f * u1 * (1.f + erff(u1 * 0.70710678118f));
                    }
                    ((uint32_t*)outO)[((size_t)m * N + n) >> 1] = pack_f16x2(u0, u1);
                }
            } else {
                #pragma unroll
                for (int e = 0; e < 4; e++) {
                    int m = rbase + (e >> 1) * 8;
                    int n = cbase + (e & 1);
                    if (n >= N) continue;
                    float v = acc[mt][nt][e];
                    if (EPI == 0) {
                        C[(size_t)m * N + n] = v;
                    } else { // EPI 1
                        C[(size_t)m * N + n] = res[(size_t)m * N + n] + v;
                    }
                }
            }
        }
    }
}

// ---------------------------------------------------------------------------
extern "C" void kernel_launch(void* const* d_in, const int* in_sizes, int n_in,
                              void* d_out, int out_size) {
    const float* x        = (const float*)d_in[0];
    const float* ln_g     = (const float*)d_in[1];
    const float* ln_b     = (const float*)d_in[2];
    const float* in_proj  = (const float*)d_in[3];
    const float* conv_w   = (const float*)d_in[4];
    const float* conv_b   = (const float*)d_in[5];
    const float* x_proj   = (const float*)d_in[6];
    const float* dt_w     = (const float*)d_in[7];
    const float* dt_b     = (const float*)d_in[8];
    const float* A_log    = (const float*)d_in[9];
    const float* Dp       = (const float*)d_in[10];
    const float* out_proj = (const float*)d_in[11];
    const float* mlp_ln_g = (const float*)d_in[12];
    const float* mlp_ln_b = (const float*)d_in[13];
    const float* mlp_w1   = (const float*)d_in[14];
    const float* mlp_b1   = (const float*)d_in[15];
    const float* mlp_w2   = (const float*)d_in[16];
    const float* mlp_b2   = (const float*)d_in[17];
    float* out = (float*)d_out;

    float *p_dbl, *p_xf, *p_xf2;
    cudaGetSymbolAddress((void**)&p_dbl, g_dbl);
    cudaGetSymbolAddress((void**)&p_xf,  g_xf);
    cudaGetSymbolAddress((void**)&p_xf2, g_xf2);
    uint16_t *p_xn16, *p_xz16, *p_xc16, *p_y16, *p_hln16, *p_h116;
    cudaGetSymbolAddress((void**)&p_xn16,  g_xn16);
    cudaGetSymbolAddress((void**)&p_xz16,  g_xz16);
    cudaGetSymbolAddress((void**)&p_xc16,  g_xc16);
    cudaGetSymbolAddress((void**)&p_y16,   g_y16);
    cudaGetSymbolAddress((void**)&p_hln16, g_hln16);
    cudaGetSymbolAddress((void**)&p_h116,  g_h116);
    uint16_t *p_in16, *p_xp16, *p_op16, *p_m116, *p_m216;
    cudaGetSymbolAddress((void**)&p_in16, w_in16);
    cudaGetSymbolAddress((void**)&p_xp16, w_xp16);
    cudaGetSymbolAddress((void**)&p_op16, w_op16);
    cudaGetSymbolAddress((void**)&p_m116, w_m116);
    cudaGetSymbolAddress((void**)&p_m216, w_m216);

    const int SMEM = 2 * (128 * 128 + 64 * 128);   // 49152
    cudaFuncSetAttribute(gemm_f16<0>, cudaFuncAttributeMaxDynamicSharedMemorySize, SMEM);
    cudaFuncSetAttribute(gemm_f16<1>, cudaFuncAttributeMaxDynamicSharedMemorySize, SMEM);
    cudaFuncSetAttribute(gemm_f16<2>, cudaFuncAttributeMaxDynamicSharedMemorySize, SMEM);
    cudaFuncSetAttribute(gemm_f16<3>, cudaFuncAttributeMaxDynamicSharedMemorySize, SMEM);
    cudaFuncSetAttribute(gemm_f16<4>, cudaFuncAttributeMaxDynamicSharedMemorySize, SMEM);

    // fused weight split
    wconv_all<<<(WS4 + 255) / 256, 256>>>(in_proj, x_proj, out_proj, mlp_w1, mlp_w2);

    // 1. ln1
    ln1_kernel<<<256, 256>>>(x, ln_g, ln_b);
    // 2. in_proj (8192 x 1024, K=256) -> fp16 xz
    gemm_f16<4><<<dim3(16, 64), 256, SMEM>>>(
        p_xn16, p_in16, nullptr, NTOK, 1024, 256, nullptr, nullptr, p_xz16);
    // 3. conv + silu + gate
    conv_silu_kernel<<<dim3(32, 8, 8), 256>>>(conv_w, conv_b);
    // 4. x_proj (8192 x 48, K=512) -> fp32 dbl
    gemm_f16<0><<<dim3(1, 64), 256, SMEM>>>(
        p_xc16, p_xp16, p_dbl, NTOK, 48, 512, nullptr, nullptr, nullptr);
    // 5. dt projection
    dt_kernel<<<256, 256>>>(dt_w, dt_b);
    // 6. selective scan
    scan_kernel<<<128, 128>>>(A_log, Dp);
    // 7. out_proj + residual (8192 x 256, K=512)
    gemm_f16<1><<<dim3(4, 64), 256, SMEM>>>(
        p_y16, p_op16, p_xf2, NTOK, 256, 512, nullptr, p_xf, nullptr);
    // 8. ln2
    ln2_kernel<<<NTOK / 8, 256>>>(mlp_ln_g, mlp_ln_b);
    // 9. mlp1 + gelu -> fp16 h1 (8192 x 1024, K=256)
    gemm_f16<2><<<dim3(16, 64), 256, SMEM>>>(
        p_hln16, p_m116, nullptr, NTOK, 1024, 256, mlp_b1, nullptr, p_h116);
    // 10. mlp2 + residual + transposed store (8192 x 256, K=1024)
    gemm_f16<3><<<dim3(4, 64), 256, SMEM>>>(
        p_h116, p_m216, out, NTOK, 256, 1024, mlp_b2, p_xf2, nullptr);
}

// round 14
// speedup vs baseline: 3.7911x; 1.0217x over previous
#include <cuda_runtime.h>
#include <cuda_bf16.h>
#include <cuda_fp16.h>
#include <math.h>
#include <stdint.h>

// ---------------------------------------------------------------------------
// OptimizedMambaBlock: B=8, DIM=256, H=W=32 -> L=1024, tokens N=8192
// R14: 3-stage cp.async GEMM pipeline; half2 conv loads; MUFU softplus.
// ---------------------------------------------------------------------------

#define NTOK   8192
#define LSEQ   1024
#define DIMC   256
#define DINNER 512

// fp32 scratch
__device__ float g_xf [NTOK * DIMC];
__device__ float g_dbl[NTOK * 48];
__device__ float g_xf2[NTOK * DIMC];
// scan-layout operands [b][d][t]
__device__ float g_uT [8 * DINNER * LSEQ];
__device__ float g_gT [8 * DINNER * LSEQ];
__device__ float g_dtT[8 * DINNER * LSEQ];

// fp16 activations
__device__ __half g_xn16 [NTOK * DIMC];
__device__ __half g_xz16 [NTOK * 1024];
__device__ __half g_xc16 [NTOK * DINNER];
__device__ __half g_y16  [NTOK * DINNER];
__device__ __half g_hln16[NTOK * DIMC];
__device__ __half g_h116 [NTOK * 1024];

// fp16 weights
__device__ __half w_in16[1024 * 256];
__device__ __half w_xp16[48 * 512];
__device__ __half w_op16[256 * 512];
__device__ __half w_m116[1024 * 256];
__device__ __half w_m216[256 * 1024];

// ---------------------------------------------------------------------------
// fused weight split (all fp16)
// ---------------------------------------------------------------------------
#define WS0 262144
#define WS1 (WS0 + 24576)
#define WS2 (WS1 + 131072)
#define WS3 (WS2 + 262144)
#define WS4 (WS3 + 262144)
__global__ void wconv_all(const float* __restrict__ w_in, const float* __restrict__ w_xp,
                          const float* __restrict__ w_op, const float* __restrict__ w_m1,
                          const float* __restrict__ w_m2) {
    int i = blockIdx.x * 256 + threadIdx.x;
    const float* src; __half* dh; int off;
    if      (i < WS0) { src = w_in; dh = w_in16; off = i; }
    else if (i < WS1) { src = w_xp; dh = w_xp16; off = i - WS0; }
    else if (i < WS2) { src = w_op; dh = w_op16; off = i - WS1; }
    else if (i < WS3) { src = w_m1; dh = w_m116; off = i - WS2; }
    else if (i < WS4) { src = w_m2; dh = w_m216; off = i - WS3; }
    else return;
    dh[off] = __float2half_rn(src[off]);
}

// ---------------------------------------------------------------------------
// LN1: coalesced smem-transpose; fp32 residual + fp16 normed
// ---------------------------------------------------------------------------
__global__ void ln1_kernel(const float* __restrict__ x,
                           const float* __restrict__ g,
                           const float* __restrict__ bta) {
    __shared__ float xs[32][257];
    int tid = threadIdx.x, lane = tid & 31, w = tid >> 5;
    int b = blockIdx.x >> 5, tb = blockIdx.x & 31;
    #pragma unroll 8
    for (int j = 0; j < 32; j++) {
        int c = w * 32 + j;
        xs[lane][c] = x[(((size_t)b * DIMC + c) << 10) + tb * 32 + lane];
    }
    __syncthreads();
    for (int q = 0; q < 4; q++) {
        int tt = w * 4 + q;
        float v[8], s = 0.f, sq = 0.f;
        #pragma unroll
        for (int k = 0; k < 8; k++) {
            v[k] = xs[tt][lane + k * 32];
            s += v[k]; sq += v[k] * v[k];
        }
        #pragma unroll
        for (int o = 16; o; o >>= 1) {
            s  += __shfl_xor_sync(~0u, s, o);
            sq += __shfl_xor_sync(~0u, sq, o);
        }
        float mean = s * (1.f / 256.f);
        float var  = sq * (1.f / 256.f) - mean * mean;
        float rs = rsqrtf(var + 1e-5f);
        size_t base = (size_t)(b * 1024 + tb * 32 + tt) * DIMC;
        #pragma unroll
        for (int k = 0; k < 8; k++) {
            int c = lane + k * 32;
            g_xf[base + c] = v[k];
            float xn = (v[k] - mean) * rs * g[c] + bta[c];
            g_xn16[base + c] = __float2half_rn(xn);
        }
    }
}

// ---------------------------------------------------------------------------
// LN2: fp32 in, fp16 out
// ---------------------------------------------------------------------------
__global__ void ln2_kernel(const float* __restrict__ g,
                           const float* __restrict__ bta) {
    int token = (blockIdx.x * blockDim.x + threadIdx.x) >> 5;
    int lane = threadIdx.x & 31;
    const float* row = g_xf2 + (size_t)token * DIMC;
    float4 a = *(const float4*)(row + lane * 4);
    float4 c4 = *(const float4*)(row + 128 + lane * 4);
    float s = a.x + a.y + a.z + a.w + c4.x + c4.y + c4.z + c4.w;
    float q = a.x*a.x + a.y*a.y + a.z*a.z + a.w*a.w
            + c4.x*c4.x + c4.y*c4.y + c4.z*c4.z + c4.w*c4.w;
    #pragma unroll
    for (int o = 16; o; o >>= 1) {
        s += __shfl_xor_sync(~0u, s, o);
        q += __shfl_xor_sync(~0u, q, o);
    }
    float mean = s * (1.f / 256.f);
    float var  = q * (1.f / 256.f) - mean * mean;
    float rs = rsqrtf(var + 1e-5f);
    float va[8] = { a.x, a.y, a.z, a.w, c4.x, c4.y, c4.z, c4.w };
    size_t base = (size_t)token * DIMC;
    #pragma unroll
    for (int h = 0; h < 2; h++) {
        #pragma unroll
        for (int i = 0; i < 4; i++) {
            int c = h * 128 + lane * 4 + i;
            float u = (va[h * 4 + i] - mean) * rs * g[c] + bta[c];
            g_hln16[base + c] = __float2half_rn(u);
        }
    }
}

// ---------------------------------------------------------------------------
// conv + silu + gate (tiled), half2-vectorized loads
// ---------------------------------------------------------------------------
__global__ void conv_silu_kernel(const float* __restrict__ cw,
                                 const float* __restrict__ cb) {
    __shared__ float xs[35][64];
    __shared__ float zs[32][64];
    __shared__ float us[32][65];
    __shared__ float gs[32][65];
    int b = blockIdx.z, d0 = blockIdx.y * 64, t0 = blockIdx.x * 32;
    int tid = threadIdx.x;

    for (int i = tid; i < 35 * 32; i += 256) {
        int tt = i >> 5, dp = i & 31;
        int t = t0 - 3 + tt;
        float2 f = make_float2(0.f, 0.f);
        if (t >= 0) {
            __half2 v = *(const __half2*)(g_xz16 + ((size_t)(b * 1024 + t) << 10) + d0 + dp * 2);
            f = __half22float2(v);
        }
        xs[tt][dp * 2] = f.x;
        xs[tt][dp * 2 + 1] = f.y;
    }
    for (int i = tid; i < 32 * 32; i += 256) {
        int tt = i >> 5, dp = i & 31;
        __half2 v = *(const __half2*)(g_xz16 + ((size_t)(b * 1024 + t0 + tt) << 10) + 512 + d0 + dp * 2);
        float2 f = __half22float2(v);
        zs[tt][dp * 2] = f.x;
        zs[tt][dp * 2 + 1] = f.y;
    }
    __syncthreads();

    for (int i = tid; i < 32 * 64; i += 256) {
        int tt = i >> 6, dd = i & 63;
        int d = d0 + dd;
        float acc = cb[d];
        #pragma unroll
        for (int j = 0; j < 4; j++)
            acc += xs[tt + j][dd] * cw[d * 4 + j];
        us[tt][dd] = acc / (1.f + __expf(-acc));
        float z = zs[tt][dd];
        gs[tt][dd] = z / (1.f + __expf(-z));
    }
    __syncthreads();

    {
        int tt = tid & 31, dgrp = tid >> 5;
        #pragma unroll
        for (int k = 0; k < 8; k++) {
            int dd = dgrp * 8 + k;
            size_t o = ((size_t)(b * DINNER + d0 + dd) << 10) + t0 + tt;
            g_uT[o] = us[tt][dd];
            g_gT[o] = gs[tt][dd];
        }
    }
    {
        int dd = tid & 63, tq = tid >> 6;
        #pragma unroll
        for (int k = 0; k < 8; k++) {
            int tt = k * 4 + tq;
            size_t o = (size_t)(b * 1024 + t0 + tt) * DINNER + d0 + dd;
            g_xc16[o] = __float2half_rn(us[tt][dd]);
        }
    }
}

// ---------------------------------------------------------------------------
// dt projection + MUFU softplus -> g_dtT [b][d][t]
// ---------------------------------------------------------------------------
__global__ void dt_kernel(const float* __restrict__ dtw,
                          const float* __restrict__ dtb) {
    __shared__ float swT[16][512];
    __shared__ float db[32][17];
    int tid = threadIdx.x, lane = tid & 31, w = tid >> 5;
    int b = blockIdx.x >> 5, t0 = (blockIdx.x & 31) * 32;
    for (int i = tid; i < 16 * 512; i += 256) {
        int dd = i >> 4, r = i & 15;
        swT[r][dd] = dtw[i];
    }
    for (int i = tid; i < 512; i += 256) {
        int tt = i >> 4, r = i & 15;
        db[tt][r] = g_dbl[(size_t)(b * 1024 + t0 + tt) * 48 + r];
    }
    __syncthreads();
    float drow[16];
    #pragma unroll
    for (int r = 0; r < 16; r++) drow[r] = db[lane][r];
    for (int dd = 0; dd < 64; dd++) {
        int d = w * 64 + dd;
        float acc = dtb[d];
        #pragma unroll
        for (int r = 0; r < 16; r++)
            acc += drow[r] * swT[r][d];
        float sp = (acc > 20.f) ? acc
                 : 0.69314718056f * __log2f(1.f + exp2f(acc * 1.44269504f));
        g_dtT[((size_t)(b * DINNER + d) << 10) + t0 + lane] = sp;
    }
}

// ---------------------------------------------------------------------------
// selective scan + gating -> fp16 y
// ---------------------------------------------------------------------------
__global__ void scan_kernel(const float* __restrict__ A_log,
                            const float* __restrict__ Dp) {
    int tid = threadIdx.x;
    int b  = blockIdx.x >> 4;
    int d  = ((blockIdx.x & 15) << 5) + (tid >> 2);
    int sq = tid & 3;

    float Al[4], h[4];
    #pragma unroll
    for (int j = 0; j < 4; j++) {
        Al[j] = -__expf(A_log[d * 16 + sq * 4 + j]) * 1.44269504f;
        h[j] = 0.f;
    }
    float dpv = Dp[d];

    const float* dtp  = g_dtT + ((size_t)(b * DINNER + d) << 10);
    const float* up   = g_uT  + ((size_t)(b * DINNER + d) << 10);
    const float* gp   = g_gT  + ((size_t)(b * DINNER + d) << 10);
    const float* dblp = g_dbl + (size_t)b * LSEQ * 48;
    size_t ybase = (size_t)b * LSEQ * DINNER + d;

    float  dt_n = dtp[0];
    float  u_n  = up[0];
    float4 Bv_n = *(const float4*)(dblp + 16 + sq * 4);
    float4 Cv_n = *(const float4*)(dblp + 32 + sq * 4);
    float  g_n  = (sq == 0) ? gp[0] : 0.f;

    for (int t = 0; t < LSEQ; t++) {
        float  dt = dt_n;
        float  u  = u_n;
        float4 Bv = Bv_n;
        float4 Cv = Cv_n;
        float  gate = g_n;
        if (t + 1 < LSEQ) {
            dt_n = dtp[t + 1];
            u_n  = up[t + 1];
            Bv_n = *(const float4*)(dblp + (size_t)(t + 1) * 48 + 16 + sq * 4);
            Cv_n = *(const float4*)(dblp + (size_t)(t + 1) * 48 + 32 + sq * 4);
            if (sq == 0) g_n = gp[t + 1];
        }
        float dtu = dt * u;
        float y = 0.f;
        h[0] = exp2f(dt * Al[0]) * h[0] + dtu * Bv.x; y += h[0] * Cv.x;
        h[1] = exp2f(dt * Al[1]) * h[1] + dtu * Bv.y; y += h[1] * Cv.y;
        h[2] = exp2f(dt * Al[2]) * h[2] + dtu * Bv.z; y += h[2] * Cv.z;
        h[3] = exp2f(dt * Al[3]) * h[3] + dtu * Bv.w; y += h[3] * Cv.w;
        y += __shfl_xor_sync(~0u, y, 1);
        y += __shfl_xor_sync(~0u, y, 2);
        if (sq == 0) {
            float v = (y + u * dpv) * gate;
            g_y16[ybase + (size_t)t * DINNER] = __float2half_rn(v);
        }
    }
}

// ---------------------------------------------------------------------------
// GEMM helpers
// ---------------------------------------------------------------------------
__device__ __forceinline__ uint32_t pack_f16x2(float e, float o) {
    uint32_t d;
    asm("cvt.rn.f16x2.f32 %0, %1, %2;" : "=r"(d) : "f"(o), "f"(e));
    return d;
}

__device__ __forceinline__ void ldsm4(uint32_t r[4], uint32_t addr) {
    asm volatile("ldmatrix.sync.aligned.m8n8.x4.shared.b16 {%0,%1,%2,%3}, [%4];"
                 : "=r"(r[0]), "=r"(r[1]), "=r"(r[2]), "=r"(r[3]) : "r"(addr));
}

__device__ __forceinline__ void mma_f16(float* c, const uint32_t* a, const uint32_t* b) {
    asm volatile(
        "mma.sync.aligned.m16n8k16.row.col.f32.f16.f16.f32 "
        "{%0,%1,%2,%3}, {%4,%5,%6,%7}, {%8,%9}, {%0,%1,%2,%3};\n"
        : "+f"(c[0]), "+f"(c[1]), "+f"(c[2]), "+f"(c[3])
        : "r"(a[0]), "r"(a[1]), "r"(a[2]), "r"(a[3]), "r"(b[0]), "r"(b[1]));
}

__device__ __forceinline__ void cp16(uint32_t dst, const void* src, bool ok) {
    int sz = ok ? 16 : 0;
    asm volatile("cp.async.cg.shared.global [%0], [%1], 16, %2;\n"
                 :: "r"(dst), "l"(src), "r"(sz));
}
#define CP_COMMIT() asm volatile("cp.async.commit_group;\n" ::: "memory")

// ---------------------------------------------------------------------------
// fp16 GEMM (NT), cp.async 3-stage, BM=128 BN=64 BK=64, 256 thr, 8 warps 4x2.
// EPI: 0 fp32 | 1 +res | 2 gelu+bias -> fp16 | 3 res+bias transp | 4 fp16 out
// ---------------------------------------------------------------------------
template <int EPI>
__global__ void __launch_bounds__(256, 2)
gemm_f16(const uint16_t* __restrict__ A, const uint16_t* __restrict__ B,
         float* __restrict__ C, int M, int N, int K,
         const float* __restrict__ bias, const float* __restrict__ res,
         uint16_t* __restrict__ outO) {
    const int APL = 128 * 128;
    const int BPL = 64 * 128;
    const int STG = APL + BPL;                 // 24576 bytes per stage
    extern __shared__ __align__(1024) unsigned char smem[];

    int tid = threadIdx.x;
    int lane = tid & 31, wid = tid >> 5;
    int wm = wid & 3, wn = wid >> 2;
    int m0 = blockIdx.y * 128, n0 = blockIdx.x * 64;

    uint32_t smem_u;
    asm("{ .reg .u64 t; cvta.to.shared.u64 t, %1; cvt.u32.u64 %0, t; }"
        : "=r"(smem_u) : "l"(smem));

    int lh = lane >> 4;
    uint32_t aOff[2], bOff[2];
    #pragma unroll
    for (int mt = 0; mt < 2; mt++) {
        int r = wm * 32 + mt * 16 + (lane & 15);
        aOff[mt] = r * 128 + ((lh ^ (r & 7)) << 4);
    }
    #pragma unroll
    for (int np = 0; np < 2; np++) {
        int r = wn * 32 + np * 16 + (lane & 15);
        bOff[np] = APL + r * 128 + ((lh ^ (r & 7)) << 4);
    }

    float acc[2][4][4];
    #pragma unroll
    for (int i = 0; i < 2; i++)
        #pragma unroll
        for (int j = 0; j < 4; j++)
            #pragma unroll
            for (int k = 0; k < 4; k++) acc[i][j][k] = 0.f;

    int nk = K / 64;

    auto stage_copy = [&](int st, int kt) {
        uint32_t sb = smem_u + st * STG;
        #pragma unroll
        for (int i = 0; i < 4; i++) {
            int chunk = tid + i * 256;
            int row = chunk >> 3, c = chunk & 7;
            size_t goff = (size_t)(m0 + row) * K + kt + c * 8;
            uint32_t d = sb + row * 128 + ((c ^ (row & 7)) << 4);
            cp16(d, A + goff, true);
        }
        #pragma unroll
        for (int i = 0; i < 2; i++) {
            int chunk = tid + i * 256;
            int row = chunk >> 3, c = chunk & 7;
            bool ok = (n0 + row) < N;
            size_t goff = (size_t)(ok ? (n0 + row) : 0) * K + kt + c * 8;
            uint32_t d = sb + APL + row * 128 + ((c ^ (row & 7)) << 4);
            cp16(d, B + goff, ok);
        }
    };

    // prologue: stage tiles 0 and 1
    stage_copy(0, 0);
    CP_COMMIT();
    if (nk > 1) {
        stage_copy(1, 64);
        CP_COMMIT();
    }

    for (int it = 0; it < nk; it++) {
        if (it + 2 < nk) {
            int st = it + 2;
            stage_copy(st % 3, st * 64);
            CP_COMMIT();
            asm volatile("cp.async.wait_group 2;\n" ::: "memory");
        } else if (it + 1 < nk) {
            asm volatile("cp.async.wait_group 1;\n" ::: "memory");
        } else {
            asm volatile("cp.async.wait_group 0;\n" ::: "memory");
        }
        __syncthreads();

        uint32_t sb = smem_u + (it % 3) * STG;
        #pragma unroll
        for (int s = 0; s < 4; s++) {
            uint32_t sx = s << 5;
            uint32_t ah[2][4];
            ldsm4(ah[0], (sb + aOff[0]) ^ sx);
            ldsm4(ah[1], (sb + aOff[1]) ^ sx);
            uint32_t t0[4], t1[4];
            ldsm4(t0, (sb + bOff[0]) ^ sx);
            ldsm4(t1, (sb + bOff[1]) ^ sx);
            uint32_t bh2[4][2] = {{t0[0], t0[2]}, {t0[1], t0[3]}, {t1[0], t1[2]}, {t1[1], t1[3]}};
            #pragma unroll
            for (int mt = 0; mt < 2; mt++)
                #pragma unroll
                for (int nt = 0; nt < 4; nt++)
                    mma_f16(acc[mt][nt], ah[mt], bh2[nt]);
        }
        __syncthreads();
    }

    if (EPI == 3) {
        float* sf = (float*)smem;
        #pragma unroll
        for (int mt = 0; mt < 2; mt++) {
            #pragma unroll
            for (int nt = 0; nt < 4; nt++) {
                int mlb = wm * 32 + mt * 16 + (lane >> 2);
                int nlb = wn * 32 + nt * 8 + (lane & 3) * 2;
                #pragma unroll
                for (int e = 0; e < 4; e++) {
                    int ml = mlb + (e >> 1) * 8;
                    int nl = nlb + (e & 1);
                    float v = res[(size_t)(m0 + ml) * N + (n0 + nl)]
                            + acc[mt][nt][e] + bias[n0 + nl];
                    sf[nl * 132 + ml] = v;
                }
            }
        }
        __syncthreads();
        int b = m0 >> 10, tb = m0 & 1023;
        for (int i = tid; i < 64 * 128; i += 256) {
            int nl = i >> 7, ml = i & 127;
            C[(((size_t)b * DIMC + n0 + nl) << 10) + tb + ml] = sf[nl * 132 + ml];
        }
        return;
    }

    #pragma unroll
    for (int mt = 0; mt < 2; mt++) {
        #pragma unroll
        for (int nt = 0; nt < 4; nt++) {
            int rbase = m0 + wm * 32 + mt * 16 + (lane >> 2);
            int cbase = n0 + wn * 32 + nt * 8 + (lane & 3) * 2;
            if (EPI == 2 || EPI == 4) {
                #pragma unroll
                for (int ep = 0; ep < 2; ep++) {
                    int m = rbase + ep * 8;
                    int n = cbase;
                    float u0 = acc[mt][nt][ep * 2 + 0];
                    float u1 = acc[mt][nt][ep * 2 + 1];
                    if (EPI == 2) {
                        u0 += bias[n];
                        u1 += bias[n + 1];
                        u0 = 0.5f * u0 * (1.f + erff(u0 * 0.70710678118f));
                        u1 = 0.5f * u1 * (1.f + erff(u1 * 0.70710678118f));
                    }
                    ((uint32_t*)outO)[((size_t)m * N + n) >> 1] = pack_f16x2(u0, u1);
                }
            } else {
                #pragma unroll
                for (int e = 0; e < 4; e++) {
                    int m = rbase + (e >> 1) * 8;
                    int n = cbase + (e & 1);
                    if (n >= N) continue;
                    float v = acc[mt][nt][e];
                    if (EPI == 0) {
                        C[(size_t)m * N + n] = v;
                    } else { // EPI 1
                        C[(size_t)m * N + n] = res[(size_t)m * N + n] + v;
                    }
                }
            }
        }
    }
}

// ---------------------------------------------------------------------------
extern "C" void kernel_launch(void* const* d_in, const int* in_sizes, int n_in,
                              void* d_out, int out_size) {
    const float* x        = (const float*)d_in[0];
    const float* ln_g     = (const float*)d_in[1];
    const float* ln_b     = (const float*)d_in[2];
    const float* in_proj  = (const float*)d_in[3];
    const float* conv_w   = (const float*)d_in[4];
    const float* conv_b   = (const float*)d_in[5];
    const float* x_proj   = (const float*)d_in[6];
    const float* dt_w     = (const float*)d_in[7];
    const float* dt_b     = (const float*)d_in[8];
    const float* A_log    = (const float*)d_in[9];
    const float* Dp       = (const float*)d_in[10];
    const float* out_proj = (const float*)d_in[11];
    const float* mlp_ln_g = (const float*)d_in[12];
    const float* mlp_ln_b = (const float*)d_in[13];
    const float* mlp_w1   = (const float*)d_in[14];
    const float* mlp_b1   = (const float*)d_in[15];
    const float* mlp_w2   = (const float*)d_in[16];
    const float* mlp_b2   = (const float*)d_in[17];
    float* out = (float*)d_out;

    float *p_dbl, *p_xf, *p_xf2;
    cudaGetSymbolAddress((void**)&p_dbl, g_dbl);
    cudaGetSymbolAddress((void**)&p_xf,  g_xf);
    cudaGetSymbolAddress((void**)&p_xf2, g_xf2);
    uint16_t *p_xn16, *p_xz16, *p_xc16, *p_y16, *p_hln16, *p_h116;
    cudaGetSymbolAddress((void**)&p_xn16,  g_xn16);
    cudaGetSymbolAddress((void**)&p_xz16,  g_xz16);
    cudaGetSymbolAddress((void**)&p_xc16,  g_xc16);
    cudaGetSymbolAddress((void**)&p_y16,   g_y16);
    cudaGetSymbolAddress((void**)&p_hln16, g_hln16);
    cudaGetSymbolAddress((void**)&p_h116,  g_h116);
    uint16_t *p_in16, *p_xp16, *p_op16, *p_m116, *p_m216;
    cudaGetSymbolAddress((void**)&p_in16, w_in16);
    cudaGetSymbolAddress((void**)&p_xp16, w_xp16);
    cudaGetSymbolAddress((void**)&p_op16, w_op16);
    cudaGetSymbolAddress((void**)&p_m116, w_m116);
    cudaGetSymbolAddress((void**)&p_m216, w_m216);

    const int SMEM = 3 * (128 * 128 + 64 * 128);   // 73728
    cudaFuncSetAttribute(gemm_f16<0>, cudaFuncAttributeMaxDynamicSharedMemorySize, SMEM);
    cudaFuncSetAttribute(gemm_f16<1>, cudaFuncAttributeMaxDynamicSharedMemorySize, SMEM);
    cudaFuncSetAttribute(gemm_f16<2>, cudaFuncAttributeMaxDynamicSharedMemorySize, SMEM);
    cudaFuncSetAttribute(gemm_f16<3>, cudaFuncAttributeMaxDynamicSharedMemorySize, SMEM);
    cudaFuncSetAttribute(gemm_f16<4>, cudaFuncAttributeMaxDynamicSharedMemorySize, SMEM);

    // fused weight split
    wconv_all<<<(WS4 + 255) / 256, 256>>>(in_proj, x_proj, out_proj, mlp_w1, mlp_w2);

    // 1. ln1
    ln1_kernel<<<256, 256>>>(x, ln_g, ln_b);
    // 2. in_proj (8192 x 1024, K=256) -> fp16 xz
    gemm_f16<4><<<dim3(16, 64), 256, SMEM>>>(
        p_xn16, p_in16, nullptr, NTOK, 1024, 256, nullptr, nullptr, p_xz16);
    // 3. conv + silu + gate
    conv_silu_kernel<<<dim3(32, 8, 8), 256>>>(conv_w, conv_b);
    // 4. x_proj (8192 x 48, K=512) -> fp32 dbl
    gemm_f16<0><<<dim3(1, 64), 256, SMEM>>>(
        p_xc16, p_xp16, p_dbl, NTOK, 48, 512, nullptr, nullptr, nullptr);
    // 5. dt projection
    dt_kernel<<<256, 256>>>(dt_w, dt_b);
    // 6. selective scan
    scan_kernel<<<128, 128>>>(A_log, Dp);
    // 7. out_proj + residual (8192 x 256, K=512)
    gemm_f16<1><<<dim3(4, 64), 256, SMEM>>>(
        p_y16, p_op16, p_xf2, NTOK, 256, 512, nullptr, p_xf, nullptr);
    // 8. ln2
    ln2_kernel<<<NTOK / 8, 256>>>(mlp_ln_g, mlp_ln_b);
    // 9. mlp1 + gelu -> fp16 h1 (8192 x 1024, K=256)
    gemm_f16<2><<<dim3(16, 64), 256, SMEM>>>(
        p_hln16, p_m116, nullptr, NTOK, 1024, 256, mlp_b1, nullptr, p_h116);
    // 10. mlp2 + residual + transposed store (8192 x 256, K=1024)
    gemm_f16<3><<<dim3(4, 64), 256, SMEM>>>(
        p_h116, p_m216, out, NTOK, 256, 1024, mlp_b2, p_xf2, nullptr);
}